// round 1
// baseline (speedup 1.0000x reference)
#include <cuda_runtime.h>

// ---------------------------------------------------------------------------
// MHA block: x[2,2048,1024] -> qkv -> attention (16 heads, Dh=64, scale=C^-0.5)
//            -> out proj + bias. All fp32 SIMT baseline.
// ---------------------------------------------------------------------------

#define B_   2
#define L_   2048
#define C_   1024
#define H_   16
#define DH_  64
#define SCALE_ 0.03125f   // 1024^-0.5

// Scratch (allocation-free rule: __device__ globals)
__device__ float g_q[B_ * H_ * L_ * DH_];      // [b][h][l][d]
__device__ float g_k[B_ * H_ * L_ * DH_];
__device__ float g_v[B_ * H_ * L_ * DH_];
__device__ float g_att[B_ * L_ * C_];          // [b][l][h*64+d]

// ---------------------------------------------------------------------------
// Kernel 1: QKV GEMM.  Y[m][o] = sum_k X[m][k] * Wqkv[o][k]
// M=4096, N=3072, K=1024.  64x64 tiles, 16x16 threads, 4x4 per thread
// (strided register mapping: rows ty+16i, cols tx+16j).
// Results scattered directly into g_q/g_k/g_v in [b][h][l][d] layout.
// ---------------------------------------------------------------------------
__global__ __launch_bounds__(256) void qkv_gemm(const float* __restrict__ X,
                                                const float* __restrict__ W) {
    __shared__ float As[64][17];
    __shared__ float Bs[64][17];
    const int tx = threadIdx.x, ty = threadIdx.y;
    const int tid = ty * 16 + tx;
    const int m0 = blockIdx.y * 64, n0 = blockIdx.x * 64;

    float acc[4][4] = {};

    for (int k0 = 0; k0 < C_; k0 += 16) {
        #pragma unroll
        for (int t = 0; t < 4; t++) {
            int idx = tid + t * 256;
            int r = idx >> 4, c = idx & 15;
            As[r][c] = X[(m0 + r) * C_ + k0 + c];
            Bs[r][c] = W[(n0 + r) * C_ + k0 + c];
        }
        __syncthreads();
        #pragma unroll
        for (int kk = 0; kk < 16; kk++) {
            float a[4], b[4];
            #pragma unroll
            for (int i = 0; i < 4; i++) a[i] = As[ty + 16 * i][kk];
            #pragma unroll
            for (int j = 0; j < 4; j++) b[j] = Bs[tx + 16 * j][kk];
            #pragma unroll
            for (int i = 0; i < 4; i++)
                #pragma unroll
                for (int j = 0; j < 4; j++)
                    acc[i][j] = fmaf(a[i], b[j], acc[i][j]);
        }
        __syncthreads();
    }

    #pragma unroll
    for (int i = 0; i < 4; i++) {
        int m = m0 + ty + 16 * i;          // m = b*L + l
        int b = m >> 11, l = m & (L_ - 1);
        #pragma unroll
        for (int j = 0; j < 4; j++) {
            int o = n0 + tx + 16 * j;      // o in [0, 3C)
            int part = o >> 10;
            int c = o & (C_ - 1);
            int h = c >> 6, d = c & 63;
            float* dst = (part == 0) ? g_q : (part == 1) ? g_k : g_v;
            dst[(((b << 4) + h) * L_ + l) * DH_ + d] = acc[i][j];
        }
    }
}

// ---------------------------------------------------------------------------
// Kernel 2: flash attention.  One block per (q-tile of 64 rows, head, batch).
// BM=64, BN=32, Dh=64.  Online softmax with running (m, l).
// Static smem = 16K(Q) + 8.3K(K) + 8.3K(V) + 8.4K(P) = 41.5 KB (< 48 KB).
// ---------------------------------------------------------------------------
__global__ __launch_bounds__(256) void attn_kernel() {
    __shared__ float Qs[64][64];   // broadcast reads only -> no pad needed
    __shared__ float Ks[32][65];
    __shared__ float Vs[32][65];
    __shared__ float Ps[64][33];

    const int tx = threadIdx.x, ty = threadIdx.y;
    const int tid = ty * 16 + tx;
    const int qt = blockIdx.x, h = blockIdx.y, b = blockIdx.z;

    const float* Q = g_q + ((b * H_ + h) * L_ + qt * 64) * DH_;
    const float* K = g_k + (b * H_ + h) * L_ * DH_;
    const float* V = g_v + (b * H_ + h) * L_ * DH_;

    // load Q tile, pre-scaled
    #pragma unroll
    for (int t = 0; t < 16; t++) {
        int idx = tid + t * 256;
        int r = idx >> 6, c = idx & 63;
        Qs[r][c] = Q[r * DH_ + c] * SCALE_;
    }

    float mI[4], lI[4], acc[4][4];
    #pragma unroll
    for (int i = 0; i < 4; i++) {
        mI[i] = -1e30f;
        lI[i] = 0.f;
        #pragma unroll
        for (int j = 0; j < 4; j++) acc[i][j] = 0.f;
    }
    __syncthreads();

    for (int kt = 0; kt < L_ / 32; kt++) {
        #pragma unroll
        for (int t = 0; t < 8; t++) {
            int idx = tid + t * 256;
            int r = idx >> 6, c = idx & 63;
            Ks[r][c] = K[(kt * 32 + r) * DH_ + c];
            Vs[r][c] = V[(kt * 32 + r) * DH_ + c];
        }
        __syncthreads();

        // S = Q K^T  (64x32 tile; thread owns rows ty+16i, cols tx, tx+16)
        float s[4][2] = {};
        #pragma unroll
        for (int d = 0; d < 64; d++) {
            float a[4];
            #pragma unroll
            for (int i = 0; i < 4; i++) a[i] = Qs[ty + 16 * i][d];
            float b0 = Ks[tx][d];
            float b1 = Ks[tx + 16][d];
            #pragma unroll
            for (int i = 0; i < 4; i++) {
                s[i][0] = fmaf(a[i], b0, s[i][0]);
                s[i][1] = fmaf(a[i], b1, s[i][1]);
            }
        }

        // online softmax per row (16 lanes own each row)
        #pragma unroll
        for (int i = 0; i < 4; i++) {
            float rm = fmaxf(s[i][0], s[i][1]);
            #pragma unroll
            for (int off = 8; off; off >>= 1)
                rm = fmaxf(rm, __shfl_xor_sync(0xffffffffu, rm, off));
            float mnew  = fmaxf(mI[i], rm);
            float alpha = __expf(mI[i] - mnew);
            float p0 = __expf(s[i][0] - mnew);
            float p1 = __expf(s[i][1] - mnew);
            float rs = p0 + p1;
            #pragma unroll
            for (int off = 8; off; off >>= 1)
                rs += __shfl_xor_sync(0xffffffffu, rs, off);
            lI[i] = lI[i] * alpha + rs;
            mI[i] = mnew;
            #pragma unroll
            for (int j = 0; j < 4; j++) acc[i][j] *= alpha;
            Ps[ty + 16 * i][tx]      = p0;
            Ps[ty + 16 * i][tx + 16] = p1;
        }
        __syncthreads();

        // acc += P @ V  (P: 64x32, V: 32x64)
        #pragma unroll
        for (int k = 0; k < 32; k++) {
            float v0 = Vs[k][tx];
            float v1 = Vs[k][tx + 16];
            float v2 = Vs[k][tx + 32];
            float v3 = Vs[k][tx + 48];
            #pragma unroll
            for (int i = 0; i < 4; i++) {
                float p = Ps[ty + 16 * i][k];
                acc[i][0] = fmaf(p, v0, acc[i][0]);
                acc[i][1] = fmaf(p, v1, acc[i][1]);
                acc[i][2] = fmaf(p, v2, acc[i][2]);
                acc[i][3] = fmaf(p, v3, acc[i][3]);
            }
        }
        __syncthreads();
    }

    // epilogue: divide by l, write [b][l][h*64+d]
    #pragma unroll
    for (int i = 0; i < 4; i++) {
        float inv = 1.0f / lI[i];
        int l = qt * 64 + ty + 16 * i;
        float* dst = g_att + (b * L_ + l) * C_ + h * DH_;
        #pragma unroll
        for (int j = 0; j < 4; j++)
            dst[tx + 16 * j] = acc[i][j] * inv;
    }
}

// ---------------------------------------------------------------------------
// Kernel 3: out projection + bias.  out[m][o] = sum_k att[m][k]*Wout[o][k] + b[o]
// M=4096, N=1024, K=1024.
// ---------------------------------------------------------------------------
__global__ __launch_bounds__(256) void proj_gemm(const float* __restrict__ Wout,
                                                 const float* __restrict__ bias,
                                                 float* __restrict__ out) {
    __shared__ float As[64][17];
    __shared__ float Bs[64][17];
    const int tx = threadIdx.x, ty = threadIdx.y;
    const int tid = ty * 16 + tx;
    const int m0 = blockIdx.y * 64, n0 = blockIdx.x * 64;

    float acc[4][4] = {};

    for (int k0 = 0; k0 < C_; k0 += 16) {
        #pragma unroll
        for (int t = 0; t < 4; t++) {
            int idx = tid + t * 256;
            int r = idx >> 4, c = idx & 15;
            As[r][c] = g_att[(m0 + r) * C_ + k0 + c];
            Bs[r][c] = Wout[(n0 + r) * C_ + k0 + c];
        }
        __syncthreads();
        #pragma unroll
        for (int kk = 0; kk < 16; kk++) {
            float a[4], b[4];
            #pragma unroll
            for (int i = 0; i < 4; i++) a[i] = As[ty + 16 * i][kk];
            #pragma unroll
            for (int j = 0; j < 4; j++) b[j] = Bs[tx + 16 * j][kk];
            #pragma unroll
            for (int i = 0; i < 4; i++)
                #pragma unroll
                for (int j = 0; j < 4; j++)
                    acc[i][j] = fmaf(a[i], b[j], acc[i][j]);
        }
        __syncthreads();
    }

    #pragma unroll
    for (int i = 0; i < 4; i++) {
        int m = m0 + ty + 16 * i;
        #pragma unroll
        for (int j = 0; j < 4; j++) {
            int o = n0 + tx + 16 * j;
            out[m * C_ + o] = acc[i][j] + bias[o];
        }
    }
}

// ---------------------------------------------------------------------------
extern "C" void kernel_launch(void* const* d_in, const int* in_sizes, int n_in,
                              void* d_out, int out_size) {
    const float* x     = (const float*)d_in[0];   // [2,2048,1024]
    const float* w_qkv = (const float*)d_in[1];   // [3072,1024]
    const float* w_out = (const float*)d_in[2];   // [1024,1024]
    const float* b_out = (const float*)d_in[3];   // [1024]
    float* out = (float*)d_out;                   // [2,2048,1024]

    dim3 thr(16, 16);

    // QKV GEMM: N tiles = 3072/64 = 48, M tiles = 4096/64 = 64
    qkv_gemm<<<dim3(48, 64), thr>>>(x, w_qkv);

    // Attention: q-tiles x heads x batch
    attn_kernel<<<dim3(L_ / 64, H_, B_), thr>>>();

    // Out proj: N tiles = 1024/64 = 16, M tiles = 64
    proj_gemm<<<dim3(16, 64), thr>>>(w_out, b_out, out);
}

// round 3
// speedup vs baseline: 1.0356x; 1.0356x over previous
#include <cuda_runtime.h>
#include <cuda_bf16.h>
#include <cstdint>

// ---------------------------------------------------------------------------
// MHA block. Round 3: GEMMs on mma.sync bf16x3 (HMMA, sm_103-base-safe),
// flash attention still SIMT fp32.
// ---------------------------------------------------------------------------

#define B_   2
#define L_   2048
#define C_   1024
#define H_   16
#define DH_  64
#define SCALE_ 0.03125f   // 1024^-0.5

// ---------------- scratch (__device__ globals; no allocs allowed) ----------
__device__ float g_q[B_ * H_ * L_ * DH_];
__device__ float g_k[B_ * H_ * L_ * DH_];
__device__ float g_v[B_ * H_ * L_ * DH_];
__device__ float g_att[B_ * L_ * C_];

__device__ __nv_bfloat16 g_xh[4096 * 1024], g_xl[4096 * 1024];
__device__ __nv_bfloat16 g_wqh[3072 * 1024], g_wql[3072 * 1024];
__device__ __nv_bfloat16 g_woh[1024 * 1024], g_wol[1024 * 1024];
__device__ __nv_bfloat16 g_ath[4096 * 1024], g_atl[4096 * 1024];

// ---------------- helpers ---------------------------------------------------
static __device__ __forceinline__ uint32_t smem_u32(const void* p) {
    uint32_t a;
    asm("{ .reg .u64 t; cvta.to.shared.u64 t, %1; cvt.u32.u64 %0, t; }"
        : "=r"(a) : "l"(p));
    return a;
}
#define SWZ(o) ((o) ^ (((o) >> 3) & 0x70))

static __device__ __forceinline__ void cp16(uint32_t saddr, const void* gaddr) {
    asm volatile("cp.async.cg.shared.global [%0], [%1], 16;"
                 :: "r"(saddr), "l"(gaddr) : "memory");
}
static __device__ __forceinline__ void ldmx4(uint32_t* r, uint32_t addr) {
    asm volatile("ldmatrix.sync.aligned.m8n8.x4.shared.b16 {%0,%1,%2,%3}, [%4];"
                 : "=r"(r[0]), "=r"(r[1]), "=r"(r[2]), "=r"(r[3]) : "r"(addr));
}
static __device__ __forceinline__ void mma16816(float* c, const uint32_t* a,
                                                const uint32_t* b) {
    asm volatile(
        "mma.sync.aligned.m16n8k16.row.col.f32.bf16.bf16.f32 "
        "{%0,%1,%2,%3}, {%4,%5,%6,%7}, {%8,%9}, {%0,%1,%2,%3};"
        : "+f"(c[0]), "+f"(c[1]), "+f"(c[2]), "+f"(c[3])
        : "r"(a[0]), "r"(a[1]), "r"(a[2]), "r"(a[3]), "r"(b[0]), "r"(b[1]));
}

// ---------------------------------------------------------------------------
// fp32 -> bf16 hi/lo split.  SEL: 0=x, 1=w_qkv, 2=w_out, 3=g_att
// ---------------------------------------------------------------------------
template <int SEL>
__global__ __launch_bounds__(256) void split_bf16(const float* __restrict__ src, int n) {
    __nv_bfloat16 *h, *l;
    if (SEL == 0)      { h = g_xh;  l = g_xl;  }
    else if (SEL == 1) { h = g_wqh; l = g_wql; }
    else if (SEL == 2) { h = g_woh; l = g_wol; }
    else               { h = g_ath; l = g_atl; src = g_att; }

    int i = blockIdx.x * 256 + threadIdx.x;
    if (i * 4 < n) {
        float4 v = reinterpret_cast<const float4*>(src)[i];
        float vv[4] = {v.x, v.y, v.z, v.w};
        __nv_bfloat16 hh[4], ll[4];
        #pragma unroll
        for (int j = 0; j < 4; j++) {
            hh[j] = __float2bfloat16(vv[j]);
            ll[j] = __float2bfloat16(vv[j] - __bfloat162float(hh[j]));
        }
        *reinterpret_cast<uint2*>(h + i * 4) = *reinterpret_cast<uint2*>(hh);
        *reinterpret_cast<uint2*>(l + i * 4) = *reinterpret_cast<uint2*>(ll);
    }
}

// ---------------------------------------------------------------------------
// HMMA GEMM: D[M,N] = A[M,K] * B[N,K]^T, bf16x3 split, fp32 accum.
// 128x128 block, 8 warps (64x32 warp tiles), K-chunk 64, 2-stage cp.async.
// Stage layout (64KB): Ah 16K | Al 16K | Bh 16K | Bl 16K, SW128 swizzle.
// ---------------------------------------------------------------------------
static constexpr int GSMEM = 131072;

template <int OUTK>
__global__ __launch_bounds__(256) void hmma_gemm(const float* __restrict__ bias,
                                                 float* __restrict__ outp) {
    extern __shared__ char smem[];
    const uint32_t sb = smem_u32(smem);
    const int tid = threadIdx.x;
    const int lane = tid & 31, wid = tid >> 5;
    const int wm = wid & 1, wn = wid >> 1;     // warp tile: rows wm*64, cols wn*32

    const __nv_bfloat16* Ah = (OUTK == 0) ? g_xh  : g_ath;
    const __nv_bfloat16* Al = (OUTK == 0) ? g_xl  : g_atl;
    const __nv_bfloat16* Bh = (OUTK == 0) ? g_wqh : g_woh;
    const __nv_bfloat16* Bl = (OUTK == 0) ? g_wql : g_wol;

    const int n0 = blockIdx.x * 128;
    const int m0 = blockIdx.y * 128;

    float c[4][4][4];
    #pragma unroll
    for (int i = 0; i < 4; i++)
        #pragma unroll
        for (int j = 0; j < 4; j++)
            #pragma unroll
            for (int e = 0; e < 4; e++) c[i][j][e] = 0.f;

    // prefetch one chunk (ch) into stage s
    auto prefetch = [&](int ch, int s) {
        const int k0 = ch * 64;
        #pragma unroll
        for (int p = 0; p < 4; p++) {
            const __nv_bfloat16* src = (p == 0) ? Ah : (p == 1) ? Al : (p == 2) ? Bh : Bl;
            const int base = (p < 2) ? m0 : n0;
            #pragma unroll
            for (int t = 0; t < 4; t++) {
                int idx = tid + t * 256;
                int r = idx >> 3, j = idx & 7;
                uint32_t sa = sb + s * 65536 + p * 16384 + SWZ(r * 128 + j * 16);
                cp16(sa, src + (size_t)(base + r) * 1024 + k0 + j * 8);
            }
        }
        asm volatile("cp.async.commit_group;" ::: "memory");
    };

    prefetch(0, 0);

    for (int ch = 0; ch < 16; ch++) {
        if (ch + 1 < 16) {
            prefetch(ch + 1, (ch + 1) & 1);
            asm volatile("cp.async.wait_group 1;" ::: "memory");
        } else {
            asm volatile("cp.async.wait_group 0;" ::: "memory");
        }
        __syncthreads();

        const uint32_t stg = sb + (ch & 1) * 65536;
        const uint32_t aH = stg, aL = stg + 16384, bH = stg + 32768, bL = stg + 49152;

        // per-lane ldmatrix row/col components
        const int a_row = wm * 64 + (lane & 15);
        const int a_cb  = (lane >> 4) << 4;                      // 0 or 16
        const int b_row = wn * 32 + ((lane >> 4) << 3) + (lane & 7);
        const int b_cb  = ((lane >> 3) & 1) << 4;                // 0 or 16

        #pragma unroll
        for (int ks = 0; ks < 4; ks++) {
            const int kb = ks * 32;                              // byte offset of k16 step
            uint32_t ahf[4][4], alf[4][4];
            #pragma unroll
            for (int mi = 0; mi < 4; mi++) {
                uint32_t off = SWZ((a_row + mi * 16) * 128 + kb + a_cb);
                ldmx4(ahf[mi], aH + off);
                ldmx4(alf[mi], aL + off);
            }
            uint32_t bhf[4][2], blf[4][2];
            #pragma unroll
            for (int nj = 0; nj < 2; nj++) {
                uint32_t off = SWZ((b_row + nj * 16) * 128 + kb + b_cb);
                uint32_t r[4];
                ldmx4(r, bH + off);
                bhf[nj * 2][0] = r[0]; bhf[nj * 2][1] = r[1];
                bhf[nj * 2 + 1][0] = r[2]; bhf[nj * 2 + 1][1] = r[3];
                ldmx4(r, bL + off);
                blf[nj * 2][0] = r[0]; blf[nj * 2][1] = r[1];
                blf[nj * 2 + 1][0] = r[2]; blf[nj * 2 + 1][1] = r[3];
            }
            #pragma unroll
            for (int mi = 0; mi < 4; mi++)
                #pragma unroll
                for (int nj = 0; nj < 4; nj++) {
                    mma16816(c[mi][nj], ahf[mi], bhf[nj]);
                    mma16816(c[mi][nj], ahf[mi], blf[nj]);
                    mma16816(c[mi][nj], alf[mi], bhf[nj]);
                }
        }
        __syncthreads();
    }

    // ---------------- epilogue: direct float2 stores ------------------------
    const int row_in = lane >> 2;
    const int col_in = (lane & 3) * 2;
    #pragma unroll
    for (int mi = 0; mi < 4; mi++) {
        #pragma unroll
        for (int nj = 0; nj < 4; nj++) {
            int o = n0 + wn * 32 + nj * 8 + col_in;
            #pragma unroll
            for (int half = 0; half < 2; half++) {
                int m = m0 + wm * 64 + mi * 16 + row_in + half * 8;
                float v0 = c[mi][nj][half * 2 + 0];
                float v1 = c[mi][nj][half * 2 + 1];
                if (OUTK == 0) {
                    int b = m >> 11, l = m & (L_ - 1);
                    int part = o >> 10;
                    int cc = o & (C_ - 1);
                    int h = cc >> 6, d = cc & 63;
                    float* dst = (part == 0) ? g_q : (part == 1) ? g_k : g_v;
                    float2* pd = reinterpret_cast<float2*>(
                        dst + (((size_t)(b << 4) + h) * L_ + l) * DH_ + d);
                    *pd = make_float2(v0, v1);
                } else {
                    float2* pd = reinterpret_cast<float2*>(outp + (size_t)m * C_ + o);
                    *pd = make_float2(v0 + bias[o], v1 + bias[o + 1]);
                }
            }
        }
    }
}

// ---------------------------------------------------------------------------
// Flash attention (SIMT fp32) — unchanged from round 1 (passing).
// ---------------------------------------------------------------------------
__global__ __launch_bounds__(256) void attn_kernel() {
    __shared__ float Qs[64][64];
    __shared__ float Ks[32][65];
    __shared__ float Vs[32][65];
    __shared__ float Ps[64][33];

    const int tx = threadIdx.x, ty = threadIdx.y;
    const int tid = ty * 16 + tx;
    const int qt = blockIdx.x, h = blockIdx.y, b = blockIdx.z;

    const float* Q = g_q + ((b * H_ + h) * L_ + qt * 64) * DH_;
    const float* K = g_k + (b * H_ + h) * L_ * DH_;
    const float* V = g_v + (b * H_ + h) * L_ * DH_;

    #pragma unroll
    for (int t = 0; t < 16; t++) {
        int idx = tid + t * 256;
        int r = idx >> 6, c = idx & 63;
        Qs[r][c] = Q[r * DH_ + c] * SCALE_;
    }

    float mI[4], lI[4], acc[4][4];
    #pragma unroll
    for (int i = 0; i < 4; i++) {
        mI[i] = -1e30f;
        lI[i] = 0.f;
        #pragma unroll
        for (int j = 0; j < 4; j++) acc[i][j] = 0.f;
    }
    __syncthreads();

    for (int kt = 0; kt < L_ / 32; kt++) {
        #pragma unroll
        for (int t = 0; t < 8; t++) {
            int idx = tid + t * 256;
            int r = idx >> 6, c = idx & 63;
            Ks[r][c] = K[(kt * 32 + r) * DH_ + c];
            Vs[r][c] = V[(kt * 32 + r) * DH_ + c];
        }
        __syncthreads();

        float s[4][2] = {};
        #pragma unroll
        for (int d = 0; d < 64; d++) {
            float a[4];
            #pragma unroll
            for (int i = 0; i < 4; i++) a[i] = Qs[ty + 16 * i][d];
            float b0 = Ks[tx][d];
            float b1 = Ks[tx + 16][d];
            #pragma unroll
            for (int i = 0; i < 4; i++) {
                s[i][0] = fmaf(a[i], b0, s[i][0]);
                s[i][1] = fmaf(a[i], b1, s[i][1]);
            }
        }

        #pragma unroll
        for (int i = 0; i < 4; i++) {
            float rm = fmaxf(s[i][0], s[i][1]);
            #pragma unroll
            for (int off = 8; off; off >>= 1)
                rm = fmaxf(rm, __shfl_xor_sync(0xffffffffu, rm, off));
            float mnew  = fmaxf(mI[i], rm);
            float alpha = __expf(mI[i] - mnew);
            float p0 = __expf(s[i][0] - mnew);
            float p1 = __expf(s[i][1] - mnew);
            float rs = p0 + p1;
            #pragma unroll
            for (int off = 8; off; off >>= 1)
                rs += __shfl_xor_sync(0xffffffffu, rs, off);
            lI[i] = lI[i] * alpha + rs;
            mI[i] = mnew;
            #pragma unroll
            for (int j = 0; j < 4; j++) acc[i][j] *= alpha;
            Ps[ty + 16 * i][tx]      = p0;
            Ps[ty + 16 * i][tx + 16] = p1;
        }
        __syncthreads();

        #pragma unroll
        for (int k = 0; k < 32; k++) {
            float v0 = Vs[k][tx];
            float v1 = Vs[k][tx + 16];
            float v2 = Vs[k][tx + 32];
            float v3 = Vs[k][tx + 48];
            #pragma unroll
            for (int i = 0; i < 4; i++) {
                float p = Ps[ty + 16 * i][k];
                acc[i][0] = fmaf(p, v0, acc[i][0]);
                acc[i][1] = fmaf(p, v1, acc[i][1]);
                acc[i][2] = fmaf(p, v2, acc[i][2]);
                acc[i][3] = fmaf(p, v3, acc[i][3]);
            }
        }
        __syncthreads();
    }

    #pragma unroll
    for (int i = 0; i < 4; i++) {
        float inv = 1.0f / lI[i];
        int l = qt * 64 + ty + 16 * i;
        float* dst = g_att + (b * L_ + l) * C_ + h * DH_;
        #pragma unroll
        for (int j = 0; j < 4; j++)
            dst[tx + 16 * j] = acc[i][j] * inv;
    }
}

// ---------------------------------------------------------------------------
extern "C" void kernel_launch(void* const* d_in, const int* in_sizes, int n_in,
                              void* d_out, int out_size) {
    const float* x     = (const float*)d_in[0];   // [2,2048,1024]
    const float* w_qkv = (const float*)d_in[1];   // [3072,1024]
    const float* w_out = (const float*)d_in[2];   // [1024,1024]
    const float* b_out = (const float*)d_in[3];   // [1024]
    float* out = (float*)d_out;

    cudaFuncSetAttribute(hmma_gemm<0>, cudaFuncAttributeMaxDynamicSharedMemorySize, GSMEM);
    cudaFuncSetAttribute(hmma_gemm<1>, cudaFuncAttributeMaxDynamicSharedMemorySize, GSMEM);

    // bf16 hi/lo splits
    split_bf16<0><<<4096 * 1024 / 1024, 256>>>(x, 4096 * 1024);
    split_bf16<1><<<3072 * 1024 / 1024, 256>>>(w_qkv, 3072 * 1024);
    split_bf16<2><<<1024 * 1024 / 1024, 256>>>(w_out, 1024 * 1024);

    // QKV GEMM: 24 n-tiles x 32 m-tiles
    hmma_gemm<0><<<dim3(24, 32), 256, GSMEM>>>(nullptr, nullptr);

    // attention
    attn_kernel<<<dim3(L_ / 64, H_, B_), dim3(16, 16)>>>();

    // split attention output, out-proj (8 n-tiles x 32 m-tiles)
    split_bf16<3><<<4096 * 1024 / 1024, 256>>>(nullptr, 4096 * 1024);
    hmma_gemm<1><<<dim3(8, 32), 256, GSMEM>>>(b_out, out);
}

// round 4
// speedup vs baseline: 3.6193x; 3.4950x over previous
#include <cuda_runtime.h>
#include <cuda_bf16.h>
#include <cstdint>

// ---------------------------------------------------------------------------
// MHA block. Round 4: everything on HMMA bf16x3 (GEMMs + flash attention).
// ---------------------------------------------------------------------------

#define B_   2
#define L_   2048
#define C_   1024
#define H_   16
#define DH_  64
#define SCALE_ 0.03125f   // 1024^-0.5

// ---------------- scratch (__device__ globals; no allocs allowed) ----------
__device__ __nv_bfloat16 g_xh[4096 * 1024], g_xl[4096 * 1024];
__device__ __nv_bfloat16 g_wqh[3072 * 1024], g_wql[3072 * 1024];
__device__ __nv_bfloat16 g_woh[1024 * 1024], g_wol[1024 * 1024];
__device__ __nv_bfloat16 g_ath[4096 * 1024], g_atl[4096 * 1024];
__device__ __nv_bfloat16 g_qh[B_*H_*L_*DH_], g_ql[B_*H_*L_*DH_];
__device__ __nv_bfloat16 g_kh[B_*H_*L_*DH_], g_kl[B_*H_*L_*DH_];
__device__ __nv_bfloat16 g_vh[B_*H_*L_*DH_], g_vl[B_*H_*L_*DH_];

// ---------------- helpers ---------------------------------------------------
static __device__ __forceinline__ uint32_t smem_u32(const void* p) {
    uint32_t a;
    asm("{ .reg .u64 t; cvta.to.shared.u64 t, %1; cvt.u32.u64 %0, t; }"
        : "=r"(a) : "l"(p));
    return a;
}
#define SWZ(o) ((o) ^ (((o) >> 3) & 0x70))

static __device__ __forceinline__ void cp16(uint32_t saddr, const void* gaddr) {
    asm volatile("cp.async.cg.shared.global [%0], [%1], 16;"
                 :: "r"(saddr), "l"(gaddr) : "memory");
}
static __device__ __forceinline__ void ldmx4(uint32_t* r, uint32_t addr) {
    asm volatile("ldmatrix.sync.aligned.m8n8.x4.shared.b16 {%0,%1,%2,%3}, [%4];"
                 : "=r"(r[0]), "=r"(r[1]), "=r"(r[2]), "=r"(r[3]) : "r"(addr));
}
static __device__ __forceinline__ void ldmx4t(uint32_t* r, uint32_t addr) {
    asm volatile("ldmatrix.sync.aligned.m8n8.x4.trans.shared.b16 {%0,%1,%2,%3}, [%4];"
                 : "=r"(r[0]), "=r"(r[1]), "=r"(r[2]), "=r"(r[3]) : "r"(addr));
}
static __device__ __forceinline__ void mma16816(float* c, const uint32_t* a,
                                                const uint32_t* b) {
    asm volatile(
        "mma.sync.aligned.m16n8k16.row.col.f32.bf16.bf16.f32 "
        "{%0,%1,%2,%3}, {%4,%5,%6,%7}, {%8,%9}, {%0,%1,%2,%3};"
        : "+f"(c[0]), "+f"(c[1]), "+f"(c[2]), "+f"(c[3])
        : "r"(a[0]), "r"(a[1]), "r"(a[2]), "r"(a[3]), "r"(b[0]), "r"(b[1]));
}
static __device__ __forceinline__ uint32_t packbf(float a, float b) {
    __nv_bfloat162 t = __floats2bfloat162_rn(a, b);
    return *reinterpret_cast<uint32_t*>(&t);
}

// ---------------------------------------------------------------------------
// fp32 -> bf16 hi/lo split.  SEL: 0=x, 1=w_qkv, 2=w_out
// ---------------------------------------------------------------------------
template <int SEL>
__global__ __launch_bounds__(256) void split_bf16(const float* __restrict__ src, int n) {
    __nv_bfloat16 *h, *l;
    if (SEL == 0)      { h = g_xh;  l = g_xl;  }
    else if (SEL == 1) { h = g_wqh; l = g_wql; }
    else               { h = g_woh; l = g_wol; }

    int i = blockIdx.x * 256 + threadIdx.x;
    if (i * 4 < n) {
        float4 v = reinterpret_cast<const float4*>(src)[i];
        float vv[4] = {v.x, v.y, v.z, v.w};
        __nv_bfloat16 hh[4], ll[4];
        #pragma unroll
        for (int j = 0; j < 4; j++) {
            hh[j] = __float2bfloat16(vv[j]);
            ll[j] = __float2bfloat16(vv[j] - __bfloat162float(hh[j]));
        }
        *reinterpret_cast<uint2*>(h + i * 4) = *reinterpret_cast<uint2*>(hh);
        *reinterpret_cast<uint2*>(l + i * 4) = *reinterpret_cast<uint2*>(ll);
    }
}

// ---------------------------------------------------------------------------
// HMMA GEMM: D[M,N] = A[M,K] * B[N,K]^T, bf16x3 split, fp32 accum.
// 128x128 block, 8 warps (64x32 warp tiles), K-chunk 64, 2-stage cp.async.
// OUTK 0: QKV — epilogue writes bf16 hi/lo q/k/v (scale folded into q).
// OUTK 1: out-proj — fp32 out + bias.
// ---------------------------------------------------------------------------
static constexpr int GSMEM = 131072;

template <int OUTK>
__global__ __launch_bounds__(256) void hmma_gemm(const float* __restrict__ bias,
                                                 float* __restrict__ outp) {
    extern __shared__ char smem[];
    const uint32_t sb = smem_u32(smem);
    const int tid = threadIdx.x;
    const int lane = tid & 31, wid = tid >> 5;
    const int wm = wid & 1, wn = wid >> 1;

    const __nv_bfloat16* Ah = (OUTK == 0) ? g_xh  : g_ath;
    const __nv_bfloat16* Al = (OUTK == 0) ? g_xl  : g_atl;
    const __nv_bfloat16* Bh = (OUTK == 0) ? g_wqh : g_woh;
    const __nv_bfloat16* Bl = (OUTK == 0) ? g_wql : g_wol;

    const int n0 = blockIdx.x * 128;
    const int m0 = blockIdx.y * 128;

    float c[4][4][4];
    #pragma unroll
    for (int i = 0; i < 4; i++)
        #pragma unroll
        for (int j = 0; j < 4; j++)
            #pragma unroll
            for (int e = 0; e < 4; e++) c[i][j][e] = 0.f;

    auto prefetch = [&](int ch, int s) {
        const int k0 = ch * 64;
        #pragma unroll
        for (int p = 0; p < 4; p++) {
            const __nv_bfloat16* src = (p == 0) ? Ah : (p == 1) ? Al : (p == 2) ? Bh : Bl;
            const int base = (p < 2) ? m0 : n0;
            #pragma unroll
            for (int t = 0; t < 4; t++) {
                int idx = tid + t * 256;
                int r = idx >> 3, j = idx & 7;
                uint32_t sa = sb + s * 65536 + p * 16384 + SWZ(r * 128 + j * 16);
                cp16(sa, src + (size_t)(base + r) * 1024 + k0 + j * 8);
            }
        }
        asm volatile("cp.async.commit_group;" ::: "memory");
    };

    prefetch(0, 0);

    for (int ch = 0; ch < 16; ch++) {
        if (ch + 1 < 16) {
            prefetch(ch + 1, (ch + 1) & 1);
            asm volatile("cp.async.wait_group 1;" ::: "memory");
        } else {
            asm volatile("cp.async.wait_group 0;" ::: "memory");
        }
        __syncthreads();

        const uint32_t stg = sb + (ch & 1) * 65536;
        const uint32_t aH = stg, aL = stg + 16384, bH = stg + 32768, bL = stg + 49152;

        const int a_row = wm * 64 + (lane & 15);
        const int a_cb  = (lane >> 4) << 4;
        const int b_row = wn * 32 + ((lane >> 4) << 3) + (lane & 7);
        const int b_cb  = ((lane >> 3) & 1) << 4;

        #pragma unroll
        for (int ks = 0; ks < 4; ks++) {
            const int kb = ks * 32;
            uint32_t ahf[4][4], alf[4][4];
            #pragma unroll
            for (int mi = 0; mi < 4; mi++) {
                uint32_t off = SWZ((a_row + mi * 16) * 128 + kb + a_cb);
                ldmx4(ahf[mi], aH + off);
                ldmx4(alf[mi], aL + off);
            }
            uint32_t bhf[4][2], blf[4][2];
            #pragma unroll
            for (int nj = 0; nj < 2; nj++) {
                uint32_t off = SWZ((b_row + nj * 16) * 128 + kb + b_cb);
                uint32_t r[4];
                ldmx4(r, bH + off);
                bhf[nj * 2][0] = r[0]; bhf[nj * 2][1] = r[1];
                bhf[nj * 2 + 1][0] = r[2]; bhf[nj * 2 + 1][1] = r[3];
                ldmx4(r, bL + off);
                blf[nj * 2][0] = r[0]; blf[nj * 2][1] = r[1];
                blf[nj * 2 + 1][0] = r[2]; blf[nj * 2 + 1][1] = r[3];
            }
            #pragma unroll
            for (int mi = 0; mi < 4; mi++)
                #pragma unroll
                for (int nj = 0; nj < 4; nj++) {
                    mma16816(c[mi][nj], ahf[mi], bhf[nj]);
                    mma16816(c[mi][nj], ahf[mi], blf[nj]);
                    mma16816(c[mi][nj], alf[mi], bhf[nj]);
                }
        }
        __syncthreads();
    }

    const int row_in = lane >> 2;
    const int col_in = (lane & 3) * 2;
    #pragma unroll
    for (int mi = 0; mi < 4; mi++) {
        #pragma unroll
        for (int nj = 0; nj < 4; nj++) {
            int o = n0 + wn * 32 + nj * 8 + col_in;
            #pragma unroll
            for (int half = 0; half < 2; half++) {
                int m = m0 + wm * 64 + mi * 16 + row_in + half * 8;
                float v0 = c[mi][nj][half * 2 + 0];
                float v1 = c[mi][nj][half * 2 + 1];
                if (OUTK == 0) {
                    int b = m >> 11, l = m & (L_ - 1);
                    int part = o >> 10;
                    int cc = o & (C_ - 1);
                    int hh = cc >> 6, d = cc & 63;
                    __nv_bfloat16 *dh, *dl;
                    if (part == 0)      { dh = g_qh; dl = g_ql; v0 *= SCALE_; v1 *= SCALE_; }
                    else if (part == 1) { dh = g_kh; dl = g_kl; }
                    else                { dh = g_vh; dl = g_vl; }
                    __nv_bfloat16 h0 = __float2bfloat16(v0);
                    __nv_bfloat16 h1 = __float2bfloat16(v1);
                    float l0 = v0 - __bfloat162float(h0);
                    float l1 = v1 - __bfloat162float(h1);
                    size_t base = (((size_t)(b << 4) + hh) * L_ + l) * DH_ + d;
                    *reinterpret_cast<uint32_t*>(dh + base) =
                        ((uint32_t)*reinterpret_cast<uint16_t*>(&h1) << 16) |
                        *reinterpret_cast<uint16_t*>(&h0);
                    *reinterpret_cast<uint32_t*>(dl + base) = packbf(l0, l1);
                } else {
                    float2* pd = reinterpret_cast<float2*>(outp + (size_t)m * C_ + o);
                    *pd = make_float2(v0 + bias[o], v1 + bias[o + 1]);
                }
            }
        }
    }
}

// ---------------------------------------------------------------------------
// Flash attention on HMMA. CTA = (q-tile 128, head, batch). 8 warps: 4(m) x 2(n).
// K/V chunks of 64, cp.async double-buffered. bf16x3 for both QK^T and PV.
// smem: Qh/Ql 32K | KV 2 stages x 32K | Ph/Pl 32K | rowstats 2K  = 133120 B.
// ---------------------------------------------------------------------------
static constexpr int ATT_QH   = 0;
static constexpr int ATT_QL   = 16384;
static constexpr int ATT_KV   = 32768;     // + stage*32768 ; KH 0 KL 8192 VH 16384 VL 24576
static constexpr int ATT_PH   = 98304;
static constexpr int ATT_PL   = 114688;
static constexpr int ATT_RMAX = 131072;    // float[2][128]
static constexpr int ATT_RSUM = 132096;    // float[2][128]
static constexpr int ATT_SMEM = 133120;

__global__ __launch_bounds__(256) void attn_mma() {
    extern __shared__ char smem[];
    const uint32_t sb = smem_u32(smem);
    const int tid = threadIdx.x, lane = tid & 31, wid = tid >> 5;
    const int wm = wid & 3, wn = wid >> 2;
    const int qt = blockIdx.x, h = blockIdx.y, b = blockIdx.z;
    const size_t bh = (size_t)(b * H_ + h) * L_;

    // lane-derived constants
    const int r0   = lane >> 2;
    const int cb   = (lane & 3) * 2;
    const int a_lr = lane & 15;
    const int a_cb = (lane >> 4) << 4;
    const int b_lr = ((lane >> 4) << 3) + (lane & 7);
    const int b_cb = ((lane >> 3) & 1) << 4;
    const int v_lr = (lane & 7) + (((lane >> 3) & 1) << 3);
    const int v_cB = ((lane >> 4) << 3) * 2;   // byte col offset

    // ---- load Q tile (128x64 hi/lo), once ----
    #pragma unroll
    for (int t = 0; t < 8; t++) {
        int idx = tid + t * 256;
        int p = idx >> 10, r = (idx >> 3) & 127, j = idx & 7;
        const __nv_bfloat16* src = (p ? g_ql : g_qh) + (bh + qt * 128 + r) * DH_ + j * 8;
        cp16(sb + ATT_QH + p * 16384 + SWZ(r * 128 + j * 16), src);
    }
    asm volatile("cp.async.commit_group;" ::: "memory");

    auto prefetch = [&](int kt) {
        const uint32_t stg = sb + ATT_KV + (kt & 1) * 32768;
        #pragma unroll
        for (int t = 0; t < 8; t++) {
            int idx = tid + t * 256;
            int p = idx >> 9, r = (idx >> 3) & 63, j = idx & 7;
            const __nv_bfloat16* src =
                ((p == 0) ? g_kh : (p == 1) ? g_kl : (p == 2) ? g_vh : g_vl)
                + (bh + kt * 64 + r) * DH_ + j * 8;
            cp16(stg + p * 8192 + SWZ(r * 128 + j * 16), src);
        }
        asm volatile("cp.async.commit_group;" ::: "memory");
    };
    prefetch(0);

    float* rmax = reinterpret_cast<float*>(smem + ATT_RMAX);
    float* rsum = reinterpret_cast<float*>(smem + ATT_RSUM);

    float c_o[2][4][4];
    float m_st[2][2], l_st[2][2];
    #pragma unroll
    for (int mi = 0; mi < 2; mi++) {
        m_st[mi][0] = m_st[mi][1] = -1e30f;
        l_st[mi][0] = l_st[mi][1] = 0.f;
        #pragma unroll
        for (int nj = 0; nj < 4; nj++)
            #pragma unroll
            for (int e = 0; e < 4; e++) c_o[mi][nj][e] = 0.f;
    }

    for (int kt = 0; kt < L_ / 64; kt++) {
        if (kt + 1 < L_ / 64) {
            prefetch(kt + 1);
            asm volatile("cp.async.wait_group 1;" ::: "memory");
        } else {
            asm volatile("cp.async.wait_group 0;" ::: "memory");
        }
        __syncthreads();

        const uint32_t stg = sb + ATT_KV + (kt & 1) * 32768;
        const uint32_t kH = stg, kL = stg + 8192, vH = stg + 16384, vL = stg + 24576;
        const uint32_t qH = sb + ATT_QH, qL = sb + ATT_QL;
        const uint32_t pH = sb + ATT_PH, pL = sb + ATT_PL;

        // ---- S = Q K^T (128x64 per CTA; warp 32x32) ----
        float c_s[2][4][4];
        #pragma unroll
        for (int mi = 0; mi < 2; mi++)
            #pragma unroll
            for (int nj = 0; nj < 4; nj++)
                #pragma unroll
                for (int e = 0; e < 4; e++) c_s[mi][nj][e] = 0.f;

        #pragma unroll
        for (int ks = 0; ks < 4; ks++) {
            const int kb = ks * 32;
            uint32_t qa_h[2][4], qa_l[2][4];
            #pragma unroll
            for (int mi = 0; mi < 2; mi++) {
                uint32_t off = SWZ((wm * 32 + mi * 16 + a_lr) * 128 + kb + a_cb);
                ldmx4(qa_h[mi], qH + off);
                ldmx4(qa_l[mi], qL + off);
            }
            uint32_t kb_h[4][2], kb_l[4][2];
            #pragma unroll
            for (int half = 0; half < 2; half++) {
                uint32_t off = SWZ((wn * 32 + half * 16 + b_lr) * 128 + kb + b_cb);
                uint32_t r[4];
                ldmx4(r, kH + off);
                kb_h[half * 2][0] = r[0]; kb_h[half * 2][1] = r[1];
                kb_h[half * 2 + 1][0] = r[2]; kb_h[half * 2 + 1][1] = r[3];
                ldmx4(r, kL + off);
                kb_l[half * 2][0] = r[0]; kb_l[half * 2][1] = r[1];
                kb_l[half * 2 + 1][0] = r[2]; kb_l[half * 2 + 1][1] = r[3];
            }
            #pragma unroll
            for (int mi = 0; mi < 2; mi++)
                #pragma unroll
                for (int nj = 0; nj < 4; nj++) {
                    mma16816(c_s[mi][nj], qa_h[mi], kb_h[nj]);
                    mma16816(c_s[mi][nj], qa_h[mi], kb_l[nj]);
                    mma16816(c_s[mi][nj], qa_l[mi], kb_h[nj]);
                }
        }

        // ---- online softmax on fragments ----
        #pragma unroll
        for (int mi = 0; mi < 2; mi++)
            #pragma unroll
            for (int rh = 0; rh < 2; rh++) {
                float mx = -1e30f;
                #pragma unroll
                for (int nj = 0; nj < 4; nj++)
                    mx = fmaxf(mx, fmaxf(c_s[mi][nj][rh * 2], c_s[mi][nj][rh * 2 + 1]));
                mx = fmaxf(mx, __shfl_xor_sync(0xffffffffu, mx, 1));
                mx = fmaxf(mx, __shfl_xor_sync(0xffffffffu, mx, 2));
                if ((lane & 3) == 0)
                    rmax[wn * 128 + wm * 32 + mi * 16 + r0 + rh * 8] = mx;
            }
        __syncthreads();

        float alpha[2][2];
        #pragma unroll
        for (int mi = 0; mi < 2; mi++)
            #pragma unroll
            for (int rh = 0; rh < 2; rh++) {
                int row = wm * 32 + mi * 16 + r0 + rh * 8;
                float rm = fmaxf(rmax[row], rmax[128 + row]);
                float mnew = fmaxf(m_st[mi][rh], rm);
                alpha[mi][rh] = __expf(m_st[mi][rh] - mnew);
                m_st[mi][rh] = mnew;
            }

        #pragma unroll
        for (int mi = 0; mi < 2; mi++)
            #pragma unroll
            for (int rh = 0; rh < 2; rh++) {
                int row = wm * 32 + mi * 16 + r0 + rh * 8;
                float ssum = 0.f;
                #pragma unroll
                for (int nj = 0; nj < 4; nj++) {
                    float p0 = __expf(c_s[mi][nj][rh * 2]     - m_st[mi][rh]);
                    float p1 = __expf(c_s[mi][nj][rh * 2 + 1] - m_st[mi][rh]);
                    ssum += p0 + p1;
                    __nv_bfloat16 h0 = __float2bfloat16(p0);
                    __nv_bfloat16 h1 = __float2bfloat16(p1);
                    float l0 = p0 - __bfloat162float(h0);
                    float l1 = p1 - __bfloat162float(h1);
                    int col = wn * 32 + nj * 8 + cb;
                    uint32_t off = SWZ(row * 128 + col * 2);
                    *reinterpret_cast<uint32_t*>(smem + ATT_PH + off) =
                        ((uint32_t)*reinterpret_cast<uint16_t*>(&h1) << 16) |
                        *reinterpret_cast<uint16_t*>(&h0);
                    *reinterpret_cast<uint32_t*>(smem + ATT_PL + off) = packbf(l0, l1);
                }
                ssum += __shfl_xor_sync(0xffffffffu, ssum, 1);
                ssum += __shfl_xor_sync(0xffffffffu, ssum, 2);
                if ((lane & 3) == 0) rsum[wn * 128 + row] = ssum;
            }
        __syncthreads();

        #pragma unroll
        for (int mi = 0; mi < 2; mi++)
            #pragma unroll
            for (int rh = 0; rh < 2; rh++) {
                int row = wm * 32 + mi * 16 + r0 + rh * 8;
                float rs = rsum[row] + rsum[128 + row];
                l_st[mi][rh] = l_st[mi][rh] * alpha[mi][rh] + rs;
                #pragma unroll
                for (int nj = 0; nj < 4; nj++) {
                    c_o[mi][nj][rh * 2]     *= alpha[mi][rh];
                    c_o[mi][nj][rh * 2 + 1] *= alpha[mi][rh];
                }
            }

        // ---- O += P V  (P:128x64, V:64x64; warp 32x32) ----
        #pragma unroll
        for (int ks = 0; ks < 4; ks++) {
            uint32_t pa_h[2][4], pa_l[2][4];
            #pragma unroll
            for (int mi = 0; mi < 2; mi++) {
                uint32_t off = SWZ((wm * 32 + mi * 16 + a_lr) * 128 + ks * 32 + a_cb);
                ldmx4(pa_h[mi], pH + off);
                ldmx4(pa_l[mi], pL + off);
            }
            uint32_t vb_h[4][2], vb_l[4][2];
            #pragma unroll
            for (int half = 0; half < 2; half++) {
                uint32_t off = SWZ((ks * 16 + v_lr) * 128 + (wn * 32 + half * 16) * 2 + v_cB);
                uint32_t r[4];
                ldmx4t(r, vH + off);
                vb_h[half * 2][0] = r[0]; vb_h[half * 2][1] = r[1];
                vb_h[half * 2 + 1][0] = r[2]; vb_h[half * 2 + 1][1] = r[3];
                ldmx4t(r, vL + off);
                vb_l[half * 2][0] = r[0]; vb_l[half * 2][1] = r[1];
                vb_l[half * 2 + 1][0] = r[2]; vb_l[half * 2 + 1][1] = r[3];
            }
            #pragma unroll
            for (int mi = 0; mi < 2; mi++)
                #pragma unroll
                for (int nj = 0; nj < 4; nj++) {
                    mma16816(c_o[mi][nj], pa_h[mi], vb_h[nj]);
                    mma16816(c_o[mi][nj], pa_h[mi], vb_l[nj]);
                    mma16816(c_o[mi][nj], pa_l[mi], vb_h[nj]);
                }
        }
        __syncthreads();
    }

    // ---- epilogue: O/l -> g_ath/g_atl at [b*L + l][h*64 + d] ----
    #pragma unroll
    for (int mi = 0; mi < 2; mi++)
        #pragma unroll
        for (int rh = 0; rh < 2; rh++) {
            int row = wm * 32 + mi * 16 + r0 + rh * 8;
            float inv = 1.0f / l_st[mi][rh];
            size_t grow = ((size_t)b * L_ + qt * 128 + row) * C_ + h * DH_;
            #pragma unroll
            for (int nj = 0; nj < 4; nj++) {
                int col = wn * 32 + nj * 8 + cb;
                float o0 = c_o[mi][nj][rh * 2]     * inv;
                float o1 = c_o[mi][nj][rh * 2 + 1] * inv;
                __nv_bfloat16 h0 = __float2bfloat16(o0);
                __nv_bfloat16 h1 = __float2bfloat16(o1);
                float l0 = o0 - __bfloat162float(h0);
                float l1 = o1 - __bfloat162float(h1);
                *reinterpret_cast<uint32_t*>(g_ath + grow + col) =
                    ((uint32_t)*reinterpret_cast<uint16_t*>(&h1) << 16) |
                    *reinterpret_cast<uint16_t*>(&h0);
                *reinterpret_cast<uint32_t*>(g_atl + grow + col) = packbf(l0, l1);
            }
        }
}

// ---------------------------------------------------------------------------
extern "C" void kernel_launch(void* const* d_in, const int* in_sizes, int n_in,
                              void* d_out, int out_size) {
    const float* x     = (const float*)d_in[0];
    const float* w_qkv = (const float*)d_in[1];
    const float* w_out = (const float*)d_in[2];
    const float* b_out = (const float*)d_in[3];
    float* out = (float*)d_out;

    cudaFuncSetAttribute(hmma_gemm<0>, cudaFuncAttributeMaxDynamicSharedMemorySize, GSMEM);
    cudaFuncSetAttribute(hmma_gemm<1>, cudaFuncAttributeMaxDynamicSharedMemorySize, GSMEM);
    cudaFuncSetAttribute(attn_mma, cudaFuncAttributeMaxDynamicSharedMemorySize, ATT_SMEM);

    split_bf16<0><<<4096 * 1024 / 1024, 256>>>(x, 4096 * 1024);
    split_bf16<1><<<3072 * 1024 / 1024, 256>>>(w_qkv, 3072 * 1024);
    split_bf16<2><<<1024 * 1024 / 1024, 256>>>(w_out, 1024 * 1024);

    hmma_gemm<0><<<dim3(24, 32), 256, GSMEM>>>(nullptr, nullptr);

    attn_mma<<<dim3(L_ / 128, H_, B_), 256, ATT_SMEM>>>();

    hmma_gemm<1><<<dim3(8, 32), 256, GSMEM>>>(b_out, out);
}

// round 5
// speedup vs baseline: 4.1332x; 1.1420x over previous
#include <cuda_runtime.h>
#include <cuda_bf16.h>
#include <cstdint>

// ---------------------------------------------------------------------------
// MHA block. Round 5: HMMA everywhere; attention with warp-local softmax and
// register-resident P (no P smem round-trip), 2 CTAs/SM.
// ---------------------------------------------------------------------------

#define B_   2
#define L_   2048
#define C_   1024
#define H_   16
#define DH_  64
#define SCALE_ 0.03125f   // 1024^-0.5

// ---------------- scratch ----------------------------------------------------
__device__ __nv_bfloat16 g_xh[4096 * 1024], g_xl[4096 * 1024];
__device__ __nv_bfloat16 g_wqh[3072 * 1024], g_wql[3072 * 1024];
__device__ __nv_bfloat16 g_woh[1024 * 1024], g_wol[1024 * 1024];
__device__ __nv_bfloat16 g_ath[4096 * 1024], g_atl[4096 * 1024];
__device__ __nv_bfloat16 g_qh[B_*H_*L_*DH_], g_ql[B_*H_*L_*DH_];
__device__ __nv_bfloat16 g_kh[B_*H_*L_*DH_], g_kl[B_*H_*L_*DH_];
__device__ __nv_bfloat16 g_vh[B_*H_*L_*DH_], g_vl[B_*H_*L_*DH_];

// ---------------- helpers ----------------------------------------------------
static __device__ __forceinline__ uint32_t smem_u32(const void* p) {
    uint32_t a;
    asm("{ .reg .u64 t; cvta.to.shared.u64 t, %1; cvt.u32.u64 %0, t; }"
        : "=r"(a) : "l"(p));
    return a;
}
#define SWZ(o) ((o) ^ (((o) >> 3) & 0x70))

static __device__ __forceinline__ void cp16(uint32_t saddr, const void* gaddr) {
    asm volatile("cp.async.cg.shared.global [%0], [%1], 16;"
                 :: "r"(saddr), "l"(gaddr) : "memory");
}
static __device__ __forceinline__ void ldmx4(uint32_t* r, uint32_t addr) {
    asm volatile("ldmatrix.sync.aligned.m8n8.x4.shared.b16 {%0,%1,%2,%3}, [%4];"
                 : "=r"(r[0]), "=r"(r[1]), "=r"(r[2]), "=r"(r[3]) : "r"(addr));
}
static __device__ __forceinline__ void ldmx4t(uint32_t* r, uint32_t addr) {
    asm volatile("ldmatrix.sync.aligned.m8n8.x4.trans.shared.b16 {%0,%1,%2,%3}, [%4];"
                 : "=r"(r[0]), "=r"(r[1]), "=r"(r[2]), "=r"(r[3]) : "r"(addr));
}
static __device__ __forceinline__ void mma16816(float* c, const uint32_t* a,
                                                const uint32_t* b) {
    asm volatile(
        "mma.sync.aligned.m16n8k16.row.col.f32.bf16.bf16.f32 "
        "{%0,%1,%2,%3}, {%4,%5,%6,%7}, {%8,%9}, {%0,%1,%2,%3};"
        : "+f"(c[0]), "+f"(c[1]), "+f"(c[2]), "+f"(c[3])
        : "r"(a[0]), "r"(a[1]), "r"(a[2]), "r"(a[3]), "r"(b[0]), "r"(b[1]));
}
static __device__ __forceinline__ uint32_t packbf(float a, float b) {
    __nv_bfloat162 t = __floats2bfloat162_rn(a, b);
    return *reinterpret_cast<uint32_t*>(&t);
}
// hi/lo split of two floats into packed bf16x2 words
static __device__ __forceinline__ void split2(float a, float b,
                                              uint32_t& hi, uint32_t& lo) {
    __nv_bfloat16 ha = __float2bfloat16(a), hb = __float2bfloat16(b);
    hi = ((uint32_t)*reinterpret_cast<uint16_t*>(&hb) << 16) |
         *reinterpret_cast<uint16_t*>(&ha);
    lo = packbf(a - __bfloat162float(ha), b - __bfloat162float(hb));
}

// ---------------------------------------------------------------------------
// fp32 -> bf16 hi/lo split.  SEL: 0=x, 1=w_qkv, 2=w_out
// ---------------------------------------------------------------------------
template <int SEL>
__global__ __launch_bounds__(256) void split_bf16(const float* __restrict__ src, int n) {
    __nv_bfloat16 *h, *l;
    if (SEL == 0)      { h = g_xh;  l = g_xl;  }
    else if (SEL == 1) { h = g_wqh; l = g_wql; }
    else               { h = g_woh; l = g_wol; }

    int i = blockIdx.x * 256 + threadIdx.x;
    if (i * 4 < n) {
        float4 v = reinterpret_cast<const float4*>(src)[i];
        float vv[4] = {v.x, v.y, v.z, v.w};
        __nv_bfloat16 hh[4], ll[4];
        #pragma unroll
        for (int j = 0; j < 4; j++) {
            hh[j] = __float2bfloat16(vv[j]);
            ll[j] = __float2bfloat16(vv[j] - __bfloat162float(hh[j]));
        }
        *reinterpret_cast<uint2*>(h + i * 4) = *reinterpret_cast<uint2*>(hh);
        *reinterpret_cast<uint2*>(l + i * 4) = *reinterpret_cast<uint2*>(ll);
    }
}

// ---------------------------------------------------------------------------
// HMMA GEMM (unchanged from round 4, passing).
// ---------------------------------------------------------------------------
static constexpr int GSMEM = 131072;

template <int OUTK>
__global__ __launch_bounds__(256) void hmma_gemm(const float* __restrict__ bias,
                                                 float* __restrict__ outp) {
    extern __shared__ char smem[];
    const uint32_t sb = smem_u32(smem);
    const int tid = threadIdx.x;
    const int lane = tid & 31, wid = tid >> 5;
    const int wm = wid & 1, wn = wid >> 1;

    const __nv_bfloat16* Ah = (OUTK == 0) ? g_xh  : g_ath;
    const __nv_bfloat16* Al = (OUTK == 0) ? g_xl  : g_atl;
    const __nv_bfloat16* Bh = (OUTK == 0) ? g_wqh : g_woh;
    const __nv_bfloat16* Bl = (OUTK == 0) ? g_wql : g_wol;

    const int n0 = blockIdx.x * 128;
    const int m0 = blockIdx.y * 128;

    float c[4][4][4];
    #pragma unroll
    for (int i = 0; i < 4; i++)
        #pragma unroll
        for (int j = 0; j < 4; j++)
            #pragma unroll
            for (int e = 0; e < 4; e++) c[i][j][e] = 0.f;

    auto prefetch = [&](int ch, int s) {
        const int k0 = ch * 64;
        #pragma unroll
        for (int p = 0; p < 4; p++) {
            const __nv_bfloat16* src = (p == 0) ? Ah : (p == 1) ? Al : (p == 2) ? Bh : Bl;
            const int base = (p < 2) ? m0 : n0;
            #pragma unroll
            for (int t = 0; t < 4; t++) {
                int idx = tid + t * 256;
                int r = idx >> 3, j = idx & 7;
                uint32_t sa = sb + s * 65536 + p * 16384 + SWZ(r * 128 + j * 16);
                cp16(sa, src + (size_t)(base + r) * 1024 + k0 + j * 8);
            }
        }
        asm volatile("cp.async.commit_group;" ::: "memory");
    };

    prefetch(0, 0);

    for (int ch = 0; ch < 16; ch++) {
        if (ch + 1 < 16) {
            prefetch(ch + 1, (ch + 1) & 1);
            asm volatile("cp.async.wait_group 1;" ::: "memory");
        } else {
            asm volatile("cp.async.wait_group 0;" ::: "memory");
        }
        __syncthreads();

        const uint32_t stg = sb + (ch & 1) * 65536;
        const uint32_t aH = stg, aL = stg + 16384, bH = stg + 32768, bL = stg + 49152;

        const int a_row = wm * 64 + (lane & 15);
        const int a_cb  = (lane >> 4) << 4;
        const int b_row = wn * 32 + ((lane >> 4) << 3) + (lane & 7);
        const int b_cb  = ((lane >> 3) & 1) << 4;

        #pragma unroll
        for (int ks = 0; ks < 4; ks++) {
            const int kb = ks * 32;
            uint32_t ahf[4][4], alf[4][4];
            #pragma unroll
            for (int mi = 0; mi < 4; mi++) {
                uint32_t off = SWZ((a_row + mi * 16) * 128 + kb + a_cb);
                ldmx4(ahf[mi], aH + off);
                ldmx4(alf[mi], aL + off);
            }
            uint32_t bhf[4][2], blf[4][2];
            #pragma unroll
            for (int nj = 0; nj < 2; nj++) {
                uint32_t off = SWZ((b_row + nj * 16) * 128 + kb + b_cb);
                uint32_t r[4];
                ldmx4(r, bH + off);
                bhf[nj * 2][0] = r[0]; bhf[nj * 2][1] = r[1];
                bhf[nj * 2 + 1][0] = r[2]; bhf[nj * 2 + 1][1] = r[3];
                ldmx4(r, bL + off);
                blf[nj * 2][0] = r[0]; blf[nj * 2][1] = r[1];
                blf[nj * 2 + 1][0] = r[2]; blf[nj * 2 + 1][1] = r[3];
            }
            #pragma unroll
            for (int mi = 0; mi < 4; mi++)
                #pragma unroll
                for (int nj = 0; nj < 4; nj++) {
                    mma16816(c[mi][nj], ahf[mi], bhf[nj]);
                    mma16816(c[mi][nj], ahf[mi], blf[nj]);
                    mma16816(c[mi][nj], alf[mi], bhf[nj]);
                }
        }
        __syncthreads();
    }

    const int row_in = lane >> 2;
    const int col_in = (lane & 3) * 2;
    #pragma unroll
    for (int mi = 0; mi < 4; mi++) {
        #pragma unroll
        for (int nj = 0; nj < 4; nj++) {
            int o = n0 + wn * 32 + nj * 8 + col_in;
            #pragma unroll
            for (int half = 0; half < 2; half++) {
                int m = m0 + wm * 64 + mi * 16 + row_in + half * 8;
                float v0 = c[mi][nj][half * 2 + 0];
                float v1 = c[mi][nj][half * 2 + 1];
                if (OUTK == 0) {
                    int b = m >> 11, l = m & (L_ - 1);
                    int part = o >> 10;
                    int cc = o & (C_ - 1);
                    int hh = cc >> 6, d = cc & 63;
                    __nv_bfloat16 *dh, *dl;
                    if (part == 0)      { dh = g_qh; dl = g_ql; v0 *= SCALE_; v1 *= SCALE_; }
                    else if (part == 1) { dh = g_kh; dl = g_kl; }
                    else                { dh = g_vh; dl = g_vl; }
                    uint32_t hi, lo;
                    split2(v0, v1, hi, lo);
                    size_t base = (((size_t)(b << 4) + hh) * L_ + l) * DH_ + d;
                    *reinterpret_cast<uint32_t*>(dh + base) = hi;
                    *reinterpret_cast<uint32_t*>(dl + base) = lo;
                } else {
                    float2* pd = reinterpret_cast<float2*>(outp + (size_t)m * C_ + o);
                    *pd = make_float2(v0 + bias[o], v1 + bias[o + 1]);
                }
            }
        }
    }
}

// ---------------------------------------------------------------------------
// Flash attention, warp-local rows + register P.
// CTA = (q-tile 128, head, batch). 8 warps; warp w owns rows [w*16, w*16+16).
// KV chunks of 64, cp.async double-buffered.
// smem: Qh/Ql 32K | KV 2 x 32K = 96 KB -> 2 CTAs/SM (regs capped at 128).
// ---------------------------------------------------------------------------
static constexpr int ATT_QL   = 16384;
static constexpr int ATT_KV   = 32768;   // + stage*32768; KH 0 KL 8192 VH 16384 VL 24576
static constexpr int ATT_SMEM = 98304;

__global__ __launch_bounds__(256, 2) void attn_mma() {
    extern __shared__ char smem[];
    const uint32_t sb = smem_u32(smem);
    const int tid = threadIdx.x, lane = tid & 31, w = tid >> 5;
    const int qt = blockIdx.x, h = blockIdx.y, b = blockIdx.z;
    const size_t bh = (size_t)(b * H_ + h) * L_;

    const int r0   = lane >> 2;
    const int cb   = (lane & 3) * 2;
    const int a_lr = lane & 15;
    const int a_cb = (lane >> 4) << 4;
    const int b_lr = ((lane >> 4) << 3) + (lane & 7);
    const int b_cb = ((lane >> 3) & 1) << 4;
    const int v_lr = (lane & 7) + (((lane >> 3) & 1) << 3);
    const int v_cB = ((lane >> 4) << 3) * 2;

    // ---- load Q tile (128x64 hi/lo), once ----
    #pragma unroll
    for (int t = 0; t < 8; t++) {
        int idx = tid + t * 256;
        int p = idx >> 10, r = (idx >> 3) & 127, j = idx & 7;
        const __nv_bfloat16* src = (p ? g_ql : g_qh) + (bh + qt * 128 + r) * DH_ + j * 8;
        cp16(sb + p * 16384 + SWZ(r * 128 + j * 16), src);
    }
    asm volatile("cp.async.commit_group;" ::: "memory");

    auto prefetch = [&](int kt) {
        const uint32_t stg = sb + ATT_KV + (kt & 1) * 32768;
        #pragma unroll
        for (int t = 0; t < 8; t++) {
            int idx = tid + t * 256;
            int p = idx >> 9, r = (idx >> 3) & 63, j = idx & 7;
            const __nv_bfloat16* src =
                ((p == 0) ? g_kh : (p == 1) ? g_kl : (p == 2) ? g_vh : g_vl)
                + (bh + kt * 64 + r) * DH_ + j * 8;
            cp16(stg + p * 8192 + SWZ(r * 128 + j * 16), src);
        }
        asm volatile("cp.async.commit_group;" ::: "memory");
    };
    prefetch(0);

    float c_o[8][4];
    #pragma unroll
    for (int nj = 0; nj < 8; nj++)
        #pragma unroll
        for (int e = 0; e < 4; e++) c_o[nj][e] = 0.f;
    float m2[2] = {-1e30f, -1e30f}, l2[2] = {0.f, 0.f};

    const uint32_t qH = sb, qL = sb + ATT_QL;

    for (int kt = 0; kt < L_ / 64; kt++) {
        if (kt + 1 < L_ / 64) {
            prefetch(kt + 1);
            asm volatile("cp.async.wait_group 1;" ::: "memory");
        } else {
            asm volatile("cp.async.wait_group 0;" ::: "memory");
        }
        __syncthreads();

        const uint32_t stg = sb + ATT_KV + (kt & 1) * 32768;
        const uint32_t kH = stg, kL = stg + 8192, vH = stg + 16384, vL = stg + 24576;

        // ---- S = Q K^T : warp computes 16x64 stripe ----
        float c_s[8][4];
        #pragma unroll
        for (int nj = 0; nj < 8; nj++)
            #pragma unroll
            for (int e = 0; e < 4; e++) c_s[nj][e] = 0.f;

        #pragma unroll
        for (int ks = 0; ks < 4; ks++) {
            const int kb = ks * 32;
            uint32_t qa_h[4], qa_l[4];
            {
                uint32_t off = SWZ((w * 16 + a_lr) * 128 + kb + a_cb);
                ldmx4(qa_h, qH + off);
                ldmx4(qa_l, qL + off);
            }
            uint32_t kb_h[8][2], kb_l[8][2];
            #pragma unroll
            for (int grp = 0; grp < 4; grp++) {
                uint32_t off = SWZ((grp * 16 + b_lr) * 128 + kb + b_cb);
                uint32_t r[4];
                ldmx4(r, kH + off);
                kb_h[grp * 2][0] = r[0]; kb_h[grp * 2][1] = r[1];
                kb_h[grp * 2 + 1][0] = r[2]; kb_h[grp * 2 + 1][1] = r[3];
                ldmx4(r, kL + off);
                kb_l[grp * 2][0] = r[0]; kb_l[grp * 2][1] = r[1];
                kb_l[grp * 2 + 1][0] = r[2]; kb_l[grp * 2 + 1][1] = r[3];
            }
            #pragma unroll
            for (int nj = 0; nj < 8; nj++) {
                mma16816(c_s[nj], qa_h, kb_h[nj]);
                mma16816(c_s[nj], qa_h, kb_l[nj]);
                mma16816(c_s[nj], qa_l, kb_h[nj]);
            }
        }

        // ---- warp-local online softmax ----
        float alpha[2];
        #pragma unroll
        for (int rh = 0; rh < 2; rh++) {
            float mx = -1e30f;
            #pragma unroll
            for (int nj = 0; nj < 8; nj++)
                mx = fmaxf(mx, fmaxf(c_s[nj][rh * 2], c_s[nj][rh * 2 + 1]));
            mx = fmaxf(mx, __shfl_xor_sync(0xffffffffu, mx, 1));
            mx = fmaxf(mx, __shfl_xor_sync(0xffffffffu, mx, 2));
            float mnew = fmaxf(m2[rh], mx);
            alpha[rh] = __expf(m2[rh] - mnew);
            m2[rh] = mnew;
        }

        // exp, row sums, pack P fragments (hi/lo) in registers
        uint32_t ph[4][4], pl[4][4];
        float rs0 = 0.f, rs1 = 0.f;
        #pragma unroll
        for (int nj = 0; nj < 8; nj++) {
            float p0 = __expf(c_s[nj][0] - m2[0]);
            float p1 = __expf(c_s[nj][1] - m2[0]);
            float p2 = __expf(c_s[nj][2] - m2[1]);
            float p3 = __expf(c_s[nj][3] - m2[1]);
            rs0 += p0 + p1;
            rs1 += p2 + p3;
            split2(p0, p1, ph[nj >> 1][(nj & 1) * 2 + 0], pl[nj >> 1][(nj & 1) * 2 + 0]);
            split2(p2, p3, ph[nj >> 1][(nj & 1) * 2 + 1], pl[nj >> 1][(nj & 1) * 2 + 1]);
        }
        rs0 += __shfl_xor_sync(0xffffffffu, rs0, 1);
        rs0 += __shfl_xor_sync(0xffffffffu, rs0, 2);
        rs1 += __shfl_xor_sync(0xffffffffu, rs1, 1);
        rs1 += __shfl_xor_sync(0xffffffffu, rs1, 2);
        l2[0] = l2[0] * alpha[0] + rs0;
        l2[1] = l2[1] * alpha[1] + rs1;
        #pragma unroll
        for (int nj = 0; nj < 8; nj++) {
            c_o[nj][0] *= alpha[0];
            c_o[nj][1] *= alpha[0];
            c_o[nj][2] *= alpha[1];
            c_o[nj][3] *= alpha[1];
        }

        // ---- O += P V  (register P; V via ldmatrix.trans) ----
        #pragma unroll
        for (int ks = 0; ks < 4; ks++) {
            uint32_t vb_h[8][2], vb_l[8][2];
            #pragma unroll
            for (int grp = 0; grp < 4; grp++) {
                uint32_t off = SWZ((ks * 16 + v_lr) * 128 + grp * 32 + v_cB);
                uint32_t r[4];
                ldmx4t(r, vH + off);
                vb_h[grp * 2][0] = r[0]; vb_h[grp * 2][1] = r[1];
                vb_h[grp * 2 + 1][0] = r[2]; vb_h[grp * 2 + 1][1] = r[3];
                ldmx4t(r, vL + off);
                vb_l[grp * 2][0] = r[0]; vb_l[grp * 2][1] = r[1];
                vb_l[grp * 2 + 1][0] = r[2]; vb_l[grp * 2 + 1][1] = r[3];
            }
            #pragma unroll
            for (int nj = 0; nj < 8; nj++) {
                mma16816(c_o[nj], ph[ks], vb_h[nj]);
                mma16816(c_o[nj], ph[ks], vb_l[nj]);
                mma16816(c_o[nj], pl[ks], vb_h[nj]);
            }
        }
        __syncthreads();
    }

    // ---- epilogue: O/l -> g_ath/g_atl at [b*L + l][h*64 + d] ----
    #pragma unroll
    for (int rh = 0; rh < 2; rh++) {
        int row = qt * 128 + w * 16 + r0 + rh * 8;
        float inv = 1.0f / l2[rh];
        size_t grow = ((size_t)b * L_ + row) * C_ + h * DH_;
        #pragma unroll
        for (int nj = 0; nj < 8; nj++) {
            float o0 = c_o[nj][rh * 2]     * inv;
            float o1 = c_o[nj][rh * 2 + 1] * inv;
            uint32_t hi, lo;
            split2(o0, o1, hi, lo);
            *reinterpret_cast<uint32_t*>(g_ath + grow + nj * 8 + cb) = hi;
            *reinterpret_cast<uint32_t*>(g_atl + grow + nj * 8 + cb) = lo;
        }
    }
}

// ---------------------------------------------------------------------------
extern "C" void kernel_launch(void* const* d_in, const int* in_sizes, int n_in,
                              void* d_out, int out_size) {
    const float* x     = (const float*)d_in[0];
    const float* w_qkv = (const float*)d_in[1];
    const float* w_out = (const float*)d_in[2];
    const float* b_out = (const float*)d_in[3];
    float* out = (float*)d_out;

    cudaFuncSetAttribute(hmma_gemm<0>, cudaFuncAttributeMaxDynamicSharedMemorySize, GSMEM);
    cudaFuncSetAttribute(hmma_gemm<1>, cudaFuncAttributeMaxDynamicSharedMemorySize, GSMEM);
    cudaFuncSetAttribute(attn_mma, cudaFuncAttributeMaxDynamicSharedMemorySize, ATT_SMEM);

    split_bf16<0><<<4096 * 1024 / 1024, 256>>>(x, 4096 * 1024);
    split_bf16<1><<<3072 * 1024 / 1024, 256>>>(w_qkv, 3072 * 1024);
    split_bf16<2><<<1024 * 1024 / 1024, 256>>>(w_out, 1024 * 1024);

    hmma_gemm<0><<<dim3(24, 32), 256, GSMEM>>>(nullptr, nullptr);

    attn_mma<<<dim3(L_ / 128, H_, B_), 256, ATT_SMEM>>>();

    hmma_gemm<1><<<dim3(8, 32), 256, GSMEM>>>(b_out, out);
}

// round 6
// speedup vs baseline: 4.6418x; 1.1231x over previous
#include <cuda_runtime.h>
#include <cuda_bf16.h>
#include <cstdint>

// ---------------------------------------------------------------------------
// MHA block. Round 6: S=QK^T hi-only (1 MMA), PV split (3 MMA);
// GEMMs at K-chunk 32 / 2 CTAs per SM.
// ---------------------------------------------------------------------------

#define B_   2
#define L_   2048
#define C_   1024
#define H_   16
#define DH_  64
#define SCALE_ 0.03125f   // 1024^-0.5

// ---------------- scratch ----------------------------------------------------
__device__ __nv_bfloat16 g_xh[4096 * 1024], g_xl[4096 * 1024];
__device__ __nv_bfloat16 g_wqh[3072 * 1024], g_wql[3072 * 1024];
__device__ __nv_bfloat16 g_woh[1024 * 1024], g_wol[1024 * 1024];
__device__ __nv_bfloat16 g_ath[4096 * 1024], g_atl[4096 * 1024];
__device__ __nv_bfloat16 g_qh[B_*H_*L_*DH_];
__device__ __nv_bfloat16 g_kh[B_*H_*L_*DH_];
__device__ __nv_bfloat16 g_vh[B_*H_*L_*DH_], g_vl[B_*H_*L_*DH_];

// ---------------- helpers ----------------------------------------------------
static __device__ __forceinline__ uint32_t smem_u32(const void* p) {
    uint32_t a;
    asm("{ .reg .u64 t; cvta.to.shared.u64 t, %1; cvt.u32.u64 %0, t; }"
        : "=r"(a) : "l"(p));
    return a;
}
#define SWZ(o)   ((o) ^ (((o) >> 3) & 0x70))   // 128B-row swizzle
#define SWZ64(o) ((o) ^ (((o) >> 3) & 0x30))   // 64B-row swizzle

static __device__ __forceinline__ void cp16(uint32_t saddr, const void* gaddr) {
    asm volatile("cp.async.cg.shared.global [%0], [%1], 16;"
                 :: "r"(saddr), "l"(gaddr) : "memory");
}
static __device__ __forceinline__ void ldmx4(uint32_t* r, uint32_t addr) {
    asm volatile("ldmatrix.sync.aligned.m8n8.x4.shared.b16 {%0,%1,%2,%3}, [%4];"
                 : "=r"(r[0]), "=r"(r[1]), "=r"(r[2]), "=r"(r[3]) : "r"(addr));
}
static __device__ __forceinline__ void ldmx4t(uint32_t* r, uint32_t addr) {
    asm volatile("ldmatrix.sync.aligned.m8n8.x4.trans.shared.b16 {%0,%1,%2,%3}, [%4];"
                 : "=r"(r[0]), "=r"(r[1]), "=r"(r[2]), "=r"(r[3]) : "r"(addr));
}
static __device__ __forceinline__ void mma16816(float* c, const uint32_t* a,
                                                const uint32_t* b) {
    asm volatile(
        "mma.sync.aligned.m16n8k16.row.col.f32.bf16.bf16.f32 "
        "{%0,%1,%2,%3}, {%4,%5,%6,%7}, {%8,%9}, {%0,%1,%2,%3};"
        : "+f"(c[0]), "+f"(c[1]), "+f"(c[2]), "+f"(c[3])
        : "r"(a[0]), "r"(a[1]), "r"(a[2]), "r"(a[3]), "r"(b[0]), "r"(b[1]));
}
static __device__ __forceinline__ uint32_t packbf(float a, float b) {
    __nv_bfloat162 t = __floats2bfloat162_rn(a, b);
    return *reinterpret_cast<uint32_t*>(&t);
}
static __device__ __forceinline__ void split2(float a, float b,
                                              uint32_t& hi, uint32_t& lo) {
    __nv_bfloat16 ha = __float2bfloat16(a), hb = __float2bfloat16(b);
    hi = ((uint32_t)*reinterpret_cast<uint16_t*>(&hb) << 16) |
         *reinterpret_cast<uint16_t*>(&ha);
    lo = packbf(a - __bfloat162float(ha), b - __bfloat162float(hb));
}

// ---------------------------------------------------------------------------
// fp32 -> bf16 hi/lo split.  SEL: 0=x, 1=w_qkv, 2=w_out
// ---------------------------------------------------------------------------
template <int SEL>
__global__ __launch_bounds__(256) void split_bf16(const float* __restrict__ src, int n) {
    __nv_bfloat16 *h, *l;
    if (SEL == 0)      { h = g_xh;  l = g_xl;  }
    else if (SEL == 1) { h = g_wqh; l = g_wql; }
    else               { h = g_woh; l = g_wol; }

    int i = blockIdx.x * 256 + threadIdx.x;
    if (i * 4 < n) {
        float4 v = reinterpret_cast<const float4*>(src)[i];
        float vv[4] = {v.x, v.y, v.z, v.w};
        __nv_bfloat16 hh[4], ll[4];
        #pragma unroll
        for (int j = 0; j < 4; j++) {
            hh[j] = __float2bfloat16(vv[j]);
            ll[j] = __float2bfloat16(vv[j] - __bfloat162float(hh[j]));
        }
        *reinterpret_cast<uint2*>(h + i * 4) = *reinterpret_cast<uint2*>(hh);
        *reinterpret_cast<uint2*>(l + i * 4) = *reinterpret_cast<uint2*>(ll);
    }
}

// ---------------------------------------------------------------------------
// HMMA GEMM: 128x128 tile, K-chunk 32 (SW64), 2-stage, 2 CTAs/SM.
// ---------------------------------------------------------------------------
static constexpr int GSMEM = 65536;   // 2 stages x 32KB

template <int OUTK>
__global__ __launch_bounds__(256, 2) void hmma_gemm(const float* __restrict__ bias,
                                                    float* __restrict__ outp) {
    extern __shared__ char smem[];
    const uint32_t sb = smem_u32(smem);
    const int tid = threadIdx.x;
    const int lane = tid & 31, wid = tid >> 5;
    const int wm = wid & 1, wn = wid >> 1;

    const __nv_bfloat16* Ah = (OUTK == 0) ? g_xh  : g_ath;
    const __nv_bfloat16* Al = (OUTK == 0) ? g_xl  : g_atl;
    const __nv_bfloat16* Bh = (OUTK == 0) ? g_wqh : g_woh;
    const __nv_bfloat16* Bl = (OUTK == 0) ? g_wql : g_wol;

    const int n0 = blockIdx.x * 128;
    const int m0 = blockIdx.y * 128;

    float c[4][4][4];
    #pragma unroll
    for (int i = 0; i < 4; i++)
        #pragma unroll
        for (int j = 0; j < 4; j++)
            #pragma unroll
            for (int e = 0; e < 4; e++) c[i][j][e] = 0.f;

    // stage = 32KB: Ah 8K | Al 8K | Bh 8K | Bl 8K ; rows are 64B (32 bf16)
    auto prefetch = [&](int ch, int s) {
        const int k0 = ch * 32;
        #pragma unroll
        for (int p = 0; p < 4; p++) {
            const __nv_bfloat16* src = (p == 0) ? Ah : (p == 1) ? Al : (p == 2) ? Bh : Bl;
            const int base = (p < 2) ? m0 : n0;
            #pragma unroll
            for (int t = 0; t < 2; t++) {
                int idx = tid + t * 256;
                int r = idx >> 2, j = idx & 3;
                uint32_t sa = sb + s * 32768 + p * 8192 + SWZ64(r * 64 + j * 16);
                cp16(sa, src + (size_t)(base + r) * 1024 + k0 + j * 8);
            }
        }
        asm volatile("cp.async.commit_group;" ::: "memory");
    };

    prefetch(0, 0);

    for (int ch = 0; ch < 32; ch++) {
        if (ch + 1 < 32) {
            prefetch(ch + 1, (ch + 1) & 1);
            asm volatile("cp.async.wait_group 1;" ::: "memory");
        } else {
            asm volatile("cp.async.wait_group 0;" ::: "memory");
        }
        __syncthreads();

        const uint32_t stg = sb + (ch & 1) * 32768;
        const uint32_t aH = stg, aL = stg + 8192, bH = stg + 16384, bL = stg + 24576;

        const int a_row = wm * 64 + (lane & 15);
        const int a_cb  = (lane >> 4) << 4;
        const int b_row = wn * 32 + ((lane >> 4) << 3) + (lane & 7);
        const int b_cb  = ((lane >> 3) & 1) << 4;

        #pragma unroll
        for (int ks = 0; ks < 2; ks++) {
            const int kb = ks * 32;
            uint32_t ahf[4][4], alf[4][4];
            #pragma unroll
            for (int mi = 0; mi < 4; mi++) {
                uint32_t off = SWZ64((a_row + mi * 16) * 64 + kb + a_cb);
                ldmx4(ahf[mi], aH + off);
                ldmx4(alf[mi], aL + off);
            }
            uint32_t bhf[4][2], blf[4][2];
            #pragma unroll
            for (int nj = 0; nj < 2; nj++) {
                uint32_t off = SWZ64((b_row + nj * 16) * 64 + kb + b_cb);
                uint32_t r[4];
                ldmx4(r, bH + off);
                bhf[nj * 2][0] = r[0]; bhf[nj * 2][1] = r[1];
                bhf[nj * 2 + 1][0] = r[2]; bhf[nj * 2 + 1][1] = r[3];
                ldmx4(r, bL + off);
                blf[nj * 2][0] = r[0]; blf[nj * 2][1] = r[1];
                blf[nj * 2 + 1][0] = r[2]; blf[nj * 2 + 1][1] = r[3];
            }
            #pragma unroll
            for (int mi = 0; mi < 4; mi++)
                #pragma unroll
                for (int nj = 0; nj < 4; nj++) {
                    mma16816(c[mi][nj], ahf[mi], bhf[nj]);
                    mma16816(c[mi][nj], ahf[mi], blf[nj]);
                    mma16816(c[mi][nj], alf[mi], bhf[nj]);
                }
        }
        __syncthreads();
    }

    const int row_in = lane >> 2;
    const int col_in = (lane & 3) * 2;
    #pragma unroll
    for (int mi = 0; mi < 4; mi++) {
        #pragma unroll
        for (int nj = 0; nj < 4; nj++) {
            int o = n0 + wn * 32 + nj * 8 + col_in;
            #pragma unroll
            for (int half = 0; half < 2; half++) {
                int m = m0 + wm * 64 + mi * 16 + row_in + half * 8;
                float v0 = c[mi][nj][half * 2 + 0];
                float v1 = c[mi][nj][half * 2 + 1];
                if (OUTK == 0) {
                    int b = m >> 11, l = m & (L_ - 1);
                    int part = o >> 10;
                    int cc = o & (C_ - 1);
                    int hh = cc >> 6, d = cc & 63;
                    size_t base = (((size_t)(b << 4) + hh) * L_ + l) * DH_ + d;
                    if (part == 0) {
                        v0 *= SCALE_; v1 *= SCALE_;
                        *reinterpret_cast<uint32_t*>(g_qh + base) = packbf(v0, v1);
                    } else if (part == 1) {
                        *reinterpret_cast<uint32_t*>(g_kh + base) = packbf(v0, v1);
                    } else {
                        uint32_t hi, lo;
                        split2(v0, v1, hi, lo);
                        *reinterpret_cast<uint32_t*>(g_vh + base) = hi;
                        *reinterpret_cast<uint32_t*>(g_vl + base) = lo;
                    }
                } else {
                    float2* pd = reinterpret_cast<float2*>(outp + (size_t)m * C_ + o);
                    *pd = make_float2(v0 + bias[o], v1 + bias[o + 1]);
                }
            }
        }
    }
}

// ---------------------------------------------------------------------------
// Flash attention: S hi-only (1 MMA), PV split (3 MMA), register P,
// warp-local softmax. smem: Qh 16K | 2 stages x 24K (Kh|Vh|Vl) = 64 KB.
// ---------------------------------------------------------------------------
static constexpr int ATT_KV   = 16384;
static constexpr int ATT_STG  = 24576;
static constexpr int ATT_SMEM = 65536;

__global__ __launch_bounds__(256, 2) void attn_mma() {
    extern __shared__ char smem[];
    const uint32_t sb = smem_u32(smem);
    const int tid = threadIdx.x, lane = tid & 31, w = tid >> 5;
    const int qt = blockIdx.x, h = blockIdx.y, b = blockIdx.z;
    const size_t bh = (size_t)(b * H_ + h) * L_;

    const int r0   = lane >> 2;
    const int cb   = (lane & 3) * 2;
    const int a_lr = lane & 15;
    const int a_cb = (lane >> 4) << 4;
    const int b_lr = ((lane >> 4) << 3) + (lane & 7);
    const int b_cb = ((lane >> 3) & 1) << 4;
    const int v_lr = (lane & 7) + (((lane >> 3) & 1) << 3);
    const int v_cB = ((lane >> 4) << 3) * 2;

    // ---- Q tile (128x64 hi only), once ----
    #pragma unroll
    for (int t = 0; t < 4; t++) {
        int idx = tid + t * 256;
        int r = idx >> 3, j = idx & 7;
        cp16(sb + SWZ(r * 128 + j * 16), g_qh + (bh + qt * 128 + r) * DH_ + j * 8);
    }
    asm volatile("cp.async.commit_group;" ::: "memory");

    auto prefetch = [&](int kt) {
        const uint32_t stg = sb + ATT_KV + (kt & 1) * ATT_STG;
        #pragma unroll
        for (int t = 0; t < 6; t++) {
            int idx = tid + t * 256;
            int p = idx >> 9, r = (idx >> 3) & 63, j = idx & 7;
            const __nv_bfloat16* src =
                ((p == 0) ? g_kh : (p == 1) ? g_vh : g_vl)
                + (bh + kt * 64 + r) * DH_ + j * 8;
            cp16(stg + p * 8192 + SWZ(r * 128 + j * 16), src);
        }
        asm volatile("cp.async.commit_group;" ::: "memory");
    };
    prefetch(0);

    float c_o[8][4];
    #pragma unroll
    for (int nj = 0; nj < 8; nj++)
        #pragma unroll
        for (int e = 0; e < 4; e++) c_o[nj][e] = 0.f;
    float m2[2] = {-1e30f, -1e30f}, l2[2] = {0.f, 0.f};

    for (int kt = 0; kt < L_ / 64; kt++) {
        if (kt + 1 < L_ / 64) {
            prefetch(kt + 1);
            asm volatile("cp.async.wait_group 1;" ::: "memory");
        } else {
            asm volatile("cp.async.wait_group 0;" ::: "memory");
        }
        __syncthreads();

        const uint32_t stg = sb + ATT_KV + (kt & 1) * ATT_STG;
        const uint32_t kH = stg, vH = stg + 8192, vL = stg + 16384;

        // ---- S = Qh Kh^T : warp 16x64 stripe, 1 MMA per fragment ----
        float c_s[8][4];
        #pragma unroll
        for (int nj = 0; nj < 8; nj++)
            #pragma unroll
            for (int e = 0; e < 4; e++) c_s[nj][e] = 0.f;

        #pragma unroll
        for (int ks = 0; ks < 4; ks++) {
            const int kb = ks * 32;
            uint32_t qa[4];
            ldmx4(qa, sb + SWZ((w * 16 + a_lr) * 128 + kb + a_cb));
            #pragma unroll
            for (int grp = 0; grp < 4; grp++) {
                uint32_t off = SWZ((grp * 16 + b_lr) * 128 + kb + b_cb);
                uint32_t r[4];
                ldmx4(r, kH + off);
                uint32_t f0[2] = {r[0], r[1]}, f1[2] = {r[2], r[3]};
                mma16816(c_s[grp * 2],     qa, f0);
                mma16816(c_s[grp * 2 + 1], qa, f1);
            }
        }

        // ---- warp-local online softmax ----
        float alpha[2];
        #pragma unroll
        for (int rh = 0; rh < 2; rh++) {
            float mx = -1e30f;
            #pragma unroll
            for (int nj = 0; nj < 8; nj++)
                mx = fmaxf(mx, fmaxf(c_s[nj][rh * 2], c_s[nj][rh * 2 + 1]));
            mx = fmaxf(mx, __shfl_xor_sync(0xffffffffu, mx, 1));
            mx = fmaxf(mx, __shfl_xor_sync(0xffffffffu, mx, 2));
            float mnew = fmaxf(m2[rh], mx);
            alpha[rh] = __expf(m2[rh] - mnew);
            m2[rh] = mnew;
        }

        uint32_t ph[4][4], pl[4][4];
        float rs0 = 0.f, rs1 = 0.f;
        #pragma unroll
        for (int nj = 0; nj < 8; nj++) {
            float p0 = __expf(c_s[nj][0] - m2[0]);
            float p1 = __expf(c_s[nj][1] - m2[0]);
            float p2 = __expf(c_s[nj][2] - m2[1]);
            float p3 = __expf(c_s[nj][3] - m2[1]);
            rs0 += p0 + p1;
            rs1 += p2 + p3;
            split2(p0, p1, ph[nj >> 1][(nj & 1) * 2 + 0], pl[nj >> 1][(nj & 1) * 2 + 0]);
            split2(p2, p3, ph[nj >> 1][(nj & 1) * 2 + 1], pl[nj >> 1][(nj & 1) * 2 + 1]);
        }
        rs0 += __shfl_xor_sync(0xffffffffu, rs0, 1);
        rs0 += __shfl_xor_sync(0xffffffffu, rs0, 2);
        rs1 += __shfl_xor_sync(0xffffffffu, rs1, 1);
        rs1 += __shfl_xor_sync(0xffffffffu, rs1, 2);
        l2[0] = l2[0] * alpha[0] + rs0;
        l2[1] = l2[1] * alpha[1] + rs1;
        #pragma unroll
        for (int nj = 0; nj < 8; nj++) {
            c_o[nj][0] *= alpha[0];
            c_o[nj][1] *= alpha[0];
            c_o[nj][2] *= alpha[1];
            c_o[nj][3] *= alpha[1];
        }

        // ---- O += P V  (register P split; V hi/lo via ldmatrix.trans) ----
        #pragma unroll
        for (int ks = 0; ks < 4; ks++) {
            uint32_t vb_h[8][2], vb_l[8][2];
            #pragma unroll
            for (int grp = 0; grp < 4; grp++) {
                uint32_t off = SWZ((ks * 16 + v_lr) * 128 + grp * 32 + v_cB);
                uint32_t r[4];
                ldmx4t(r, vH + off);
                vb_h[grp * 2][0] = r[0]; vb_h[grp * 2][1] = r[1];
                vb_h[grp * 2 + 1][0] = r[2]; vb_h[grp * 2 + 1][1] = r[3];
                ldmx4t(r, vL + off);
                vb_l[grp * 2][0] = r[0]; vb_l[grp * 2][1] = r[1];
                vb_l[grp * 2 + 1][0] = r[2]; vb_l[grp * 2 + 1][1] = r[3];
            }
            #pragma unroll
            for (int nj = 0; nj < 8; nj++) {
                mma16816(c_o[nj], ph[ks], vb_h[nj]);
                mma16816(c_o[nj], ph[ks], vb_l[nj]);
                mma16816(c_o[nj], pl[ks], vb_h[nj]);
            }
        }
        __syncthreads();
    }

    // ---- epilogue ----
    #pragma unroll
    for (int rh = 0; rh < 2; rh++) {
        int row = qt * 128 + w * 16 + r0 + rh * 8;
        float inv = 1.0f / l2[rh];
        size_t grow = ((size_t)b * L_ + row) * C_ + h * DH_;
        #pragma unroll
        for (int nj = 0; nj < 8; nj++) {
            float o0 = c_o[nj][rh * 2]     * inv;
            float o1 = c_o[nj][rh * 2 + 1] * inv;
            uint32_t hi, lo;
            split2(o0, o1, hi, lo);
            *reinterpret_cast<uint32_t*>(g_ath + grow + nj * 8 + cb) = hi;
            *reinterpret_cast<uint32_t*>(g_atl + grow + nj * 8 + cb) = lo;
        }
    }
}

// ---------------------------------------------------------------------------
extern "C" void kernel_launch(void* const* d_in, const int* in_sizes, int n_in,
                              void* d_out, int out_size) {
    const float* x     = (const float*)d_in[0];
    const float* w_qkv = (const float*)d_in[1];
    const float* w_out = (const float*)d_in[2];
    const float* b_out = (const float*)d_in[3];
    float* out = (float*)d_out;

    cudaFuncSetAttribute(hmma_gemm<0>, cudaFuncAttributeMaxDynamicSharedMemorySize, GSMEM);
    cudaFuncSetAttribute(hmma_gemm<1>, cudaFuncAttributeMaxDynamicSharedMemorySize, GSMEM);
    cudaFuncSetAttribute(attn_mma, cudaFuncAttributeMaxDynamicSharedMemorySize, ATT_SMEM);

    split_bf16<0><<<4096 * 1024 / 1024, 256>>>(x, 4096 * 1024);
    split_bf16<1><<<3072 * 1024 / 1024, 256>>>(w_qkv, 3072 * 1024);
    split_bf16<2><<<1024 * 1024 / 1024, 256>>>(w_out, 1024 * 1024);

    hmma_gemm<0><<<dim3(24, 32), 256, GSMEM>>>(nullptr, nullptr);

    attn_mma<<<dim3(L_ / 128, H_, B_), 256, ATT_SMEM>>>();

    hmma_gemm<1><<<dim3(8, 32), 256, GSMEM>>>(b_out, out);
}

// round 7
// speedup vs baseline: 5.2432x; 1.1296x over previous
#include <cuda_runtime.h>
#include <cuda_bf16.h>
#include <cuda_fp16.h>
#include <cstdint>

// ---------------------------------------------------------------------------
// MHA block. Round 7: QKV Q/K tiles 2-MMA; attention in fp16 (S 1 MMA,
// PV 2 MMAs with V fp16-split).
// ---------------------------------------------------------------------------

#define B_   2
#define L_   2048
#define C_   1024
#define H_   16
#define DH_  64
#define SCALE_ 0.03125f   // 1024^-0.5

// ---------------- scratch ----------------------------------------------------
__device__ __nv_bfloat16 g_xh[4096 * 1024], g_xl[4096 * 1024];
__device__ __nv_bfloat16 g_wqh[3072 * 1024], g_wql[3072 * 1024];
__device__ __nv_bfloat16 g_woh[1024 * 1024], g_wol[1024 * 1024];
__device__ __nv_bfloat16 g_ath[4096 * 1024], g_atl[4096 * 1024];
__device__ __half g_qh[B_*H_*L_*DH_];
__device__ __half g_kh[B_*H_*L_*DH_];
__device__ __half g_vh[B_*H_*L_*DH_], g_vl[B_*H_*L_*DH_];

// ---------------- helpers ----------------------------------------------------
static __device__ __forceinline__ uint32_t smem_u32(const void* p) {
    uint32_t a;
    asm("{ .reg .u64 t; cvta.to.shared.u64 t, %1; cvt.u32.u64 %0, t; }"
        : "=r"(a) : "l"(p));
    return a;
}
#define SWZ(o)   ((o) ^ (((o) >> 3) & 0x70))   // 128B-row swizzle
#define SWZ64(o) ((o) ^ (((o) >> 3) & 0x30))   // 64B-row swizzle

static __device__ __forceinline__ void cp16(uint32_t saddr, const void* gaddr) {
    asm volatile("cp.async.cg.shared.global [%0], [%1], 16;"
                 :: "r"(saddr), "l"(gaddr) : "memory");
}
static __device__ __forceinline__ void ldmx4(uint32_t* r, uint32_t addr) {
    asm volatile("ldmatrix.sync.aligned.m8n8.x4.shared.b16 {%0,%1,%2,%3}, [%4];"
                 : "=r"(r[0]), "=r"(r[1]), "=r"(r[2]), "=r"(r[3]) : "r"(addr));
}
static __device__ __forceinline__ void ldmx4t(uint32_t* r, uint32_t addr) {
    asm volatile("ldmatrix.sync.aligned.m8n8.x4.trans.shared.b16 {%0,%1,%2,%3}, [%4];"
                 : "=r"(r[0]), "=r"(r[1]), "=r"(r[2]), "=r"(r[3]) : "r"(addr));
}
static __device__ __forceinline__ void mma16816(float* c, const uint32_t* a,
                                                const uint32_t* b) {
    asm volatile(
        "mma.sync.aligned.m16n8k16.row.col.f32.bf16.bf16.f32 "
        "{%0,%1,%2,%3}, {%4,%5,%6,%7}, {%8,%9}, {%0,%1,%2,%3};"
        : "+f"(c[0]), "+f"(c[1]), "+f"(c[2]), "+f"(c[3])
        : "r"(a[0]), "r"(a[1]), "r"(a[2]), "r"(a[3]), "r"(b[0]), "r"(b[1]));
}
static __device__ __forceinline__ void mma16816h(float* c, const uint32_t* a,
                                                 const uint32_t* b) {
    asm volatile(
        "mma.sync.aligned.m16n8k16.row.col.f32.f16.f16.f32 "
        "{%0,%1,%2,%3}, {%4,%5,%6,%7}, {%8,%9}, {%0,%1,%2,%3};"
        : "+f"(c[0]), "+f"(c[1]), "+f"(c[2]), "+f"(c[3])
        : "r"(a[0]), "r"(a[1]), "r"(a[2]), "r"(a[3]), "r"(b[0]), "r"(b[1]));
}
static __device__ __forceinline__ uint32_t packbf(float a, float b) {
    __nv_bfloat162 t = __floats2bfloat162_rn(a, b);
    return *reinterpret_cast<uint32_t*>(&t);
}
static __device__ __forceinline__ uint32_t packh(float a, float b) {
    __half2 t = __floats2half2_rn(a, b);
    return *reinterpret_cast<uint32_t*>(&t);
}
static __device__ __forceinline__ void split2(float a, float b,
                                              uint32_t& hi, uint32_t& lo) {
    __nv_bfloat16 ha = __float2bfloat16(a), hb = __float2bfloat16(b);
    hi = ((uint32_t)*reinterpret_cast<uint16_t*>(&hb) << 16) |
         *reinterpret_cast<uint16_t*>(&ha);
    lo = packbf(a - __bfloat162float(ha), b - __bfloat162float(hb));
}
static __device__ __forceinline__ void split2h(float a, float b,
                                               uint32_t& hi, uint32_t& lo) {
    __half ha = __float2half_rn(a), hb = __float2half_rn(b);
    hi = ((uint32_t)*reinterpret_cast<uint16_t*>(&hb) << 16) |
         *reinterpret_cast<uint16_t*>(&ha);
    lo = packh(a - __half2float(ha), b - __half2float(hb));
}

// ---------------------------------------------------------------------------
// fp32 -> bf16 hi/lo split.  SEL: 0=x, 1=w_qkv, 2=w_out
// ---------------------------------------------------------------------------
template <int SEL>
__global__ __launch_bounds__(256) void split_bf16(const float* __restrict__ src, int n) {
    __nv_bfloat16 *h, *l;
    if (SEL == 0)      { h = g_xh;  l = g_xl;  }
    else if (SEL == 1) { h = g_wqh; l = g_wql; }
    else               { h = g_woh; l = g_wol; }

    int i = blockIdx.x * 256 + threadIdx.x;
    if (i * 4 < n) {
        float4 v = reinterpret_cast<const float4*>(src)[i];
        float vv[4] = {v.x, v.y, v.z, v.w};
        __nv_bfloat16 hh[4], ll[4];
        #pragma unroll
        for (int j = 0; j < 4; j++) {
            hh[j] = __float2bfloat16(vv[j]);
            ll[j] = __float2bfloat16(vv[j] - __bfloat162float(hh[j]));
        }
        *reinterpret_cast<uint2*>(h + i * 4) = *reinterpret_cast<uint2*>(hh);
        *reinterpret_cast<uint2*>(l + i * 4) = *reinterpret_cast<uint2*>(ll);
    }
}

// ---------------------------------------------------------------------------
// HMMA GEMM: 128x128 tile, K-chunk 32 (SW64), 2-stage, 2 CTAs/SM.
// OUTK 0: QKV. Q/K tiles (part 0,1): 2 MMAs, no B-lo. V tile (part 2): 3 MMAs.
// OUTK 1: out-proj, 3 MMAs, fp32 + bias.
// ---------------------------------------------------------------------------
static constexpr int GSMEM = 65536;   // 2 stages x 32KB

template <int OUTK>
__global__ __launch_bounds__(256, 2) void hmma_gemm(const float* __restrict__ bias,
                                                    float* __restrict__ outp) {
    extern __shared__ char smem[];
    const uint32_t sb = smem_u32(smem);
    const int tid = threadIdx.x;
    const int lane = tid & 31, wid = tid >> 5;
    const int wm = wid & 1, wn = wid >> 1;

    const __nv_bfloat16* Ah = (OUTK == 0) ? g_xh  : g_ath;
    const __nv_bfloat16* Al = (OUTK == 0) ? g_xl  : g_atl;
    const __nv_bfloat16* Bh = (OUTK == 0) ? g_wqh : g_woh;
    const __nv_bfloat16* Bl = (OUTK == 0) ? g_wql : g_wol;

    const int n0 = blockIdx.x * 128;
    const int m0 = blockIdx.y * 128;
    const int part = (OUTK == 0) ? (blockIdx.x >> 3) : 1;     // 0=Q 1=K 2=V
    const bool fullB = (OUTK == 1) || (part == 2);

    float c[4][4][4];
    #pragma unroll
    for (int i = 0; i < 4; i++)
        #pragma unroll
        for (int j = 0; j < 4; j++)
            #pragma unroll
            for (int e = 0; e < 4; e++) c[i][j][e] = 0.f;

    // stage = 32KB: Ah 8K | Al 8K | Bh 8K | Bl 8K ; rows are 64B (32 bf16)
    auto prefetch = [&](int ch, int s) {
        const int k0 = ch * 32;
        #pragma unroll
        for (int p = 0; p < 4; p++) {
            if (p == 3 && !fullB) continue;
            const __nv_bfloat16* src = (p == 0) ? Ah : (p == 1) ? Al : (p == 2) ? Bh : Bl;
            const int base = (p < 2) ? m0 : n0;
            #pragma unroll
            for (int t = 0; t < 2; t++) {
                int idx = tid + t * 256;
                int r = idx >> 2, j = idx & 3;
                uint32_t sa = sb + s * 32768 + p * 8192 + SWZ64(r * 64 + j * 16);
                cp16(sa, src + (size_t)(base + r) * 1024 + k0 + j * 8);
            }
        }
        asm volatile("cp.async.commit_group;" ::: "memory");
    };

    prefetch(0, 0);

    for (int ch = 0; ch < 32; ch++) {
        if (ch + 1 < 32) {
            prefetch(ch + 1, (ch + 1) & 1);
            asm volatile("cp.async.wait_group 1;" ::: "memory");
        } else {
            asm volatile("cp.async.wait_group 0;" ::: "memory");
        }
        __syncthreads();

        const uint32_t stg = sb + (ch & 1) * 32768;
        const uint32_t aH = stg, aL = stg + 8192, bH = stg + 16384, bL = stg + 24576;

        const int a_row = wm * 64 + (lane & 15);
        const int a_cb  = (lane >> 4) << 4;
        const int b_row = wn * 32 + ((lane >> 4) << 3) + (lane & 7);
        const int b_cb  = ((lane >> 3) & 1) << 4;

        #pragma unroll
        for (int ks = 0; ks < 2; ks++) {
            const int kb = ks * 32;
            uint32_t ahf[4][4], alf[4][4];
            #pragma unroll
            for (int mi = 0; mi < 4; mi++) {
                uint32_t off = SWZ64((a_row + mi * 16) * 64 + kb + a_cb);
                ldmx4(ahf[mi], aH + off);
                ldmx4(alf[mi], aL + off);
            }
            uint32_t bhf[4][2], blf[4][2];
            #pragma unroll
            for (int nj = 0; nj < 2; nj++) {
                uint32_t off = SWZ64((b_row + nj * 16) * 64 + kb + b_cb);
                uint32_t r[4];
                ldmx4(r, bH + off);
                bhf[nj * 2][0] = r[0]; bhf[nj * 2][1] = r[1];
                bhf[nj * 2 + 1][0] = r[2]; bhf[nj * 2 + 1][1] = r[3];
                if (fullB) {
                    ldmx4(r, bL + off);
                    blf[nj * 2][0] = r[0]; blf[nj * 2][1] = r[1];
                    blf[nj * 2 + 1][0] = r[2]; blf[nj * 2 + 1][1] = r[3];
                }
            }
            #pragma unroll
            for (int mi = 0; mi < 4; mi++)
                #pragma unroll
                for (int nj = 0; nj < 4; nj++) {
                    mma16816(c[mi][nj], ahf[mi], bhf[nj]);
                    mma16816(c[mi][nj], alf[mi], bhf[nj]);
                    if (fullB) mma16816(c[mi][nj], ahf[mi], blf[nj]);
                }
        }
        __syncthreads();
    }

    const int row_in = lane >> 2;
    const int col_in = (lane & 3) * 2;
    #pragma unroll
    for (int mi = 0; mi < 4; mi++) {
        #pragma unroll
        for (int nj = 0; nj < 4; nj++) {
            int o = n0 + wn * 32 + nj * 8 + col_in;
            #pragma unroll
            for (int half = 0; half < 2; half++) {
                int m = m0 + wm * 64 + mi * 16 + row_in + half * 8;
                float v0 = c[mi][nj][half * 2 + 0];
                float v1 = c[mi][nj][half * 2 + 1];
                if (OUTK == 0) {
                    int b = m >> 11, l = m & (L_ - 1);
                    int cc = o & (C_ - 1);
                    int hh = cc >> 6, d = cc & 63;
                    size_t base = (((size_t)(b << 4) + hh) * L_ + l) * DH_ + d;
                    if (part == 0) {
                        *reinterpret_cast<uint32_t*>(g_qh + base) =
                            packh(v0 * SCALE_, v1 * SCALE_);
                    } else if (part == 1) {
                        *reinterpret_cast<uint32_t*>(g_kh + base) = packh(v0, v1);
                    } else {
                        uint32_t hi, lo;
                        split2h(v0, v1, hi, lo);
                        *reinterpret_cast<uint32_t*>(g_vh + base) = hi;
                        *reinterpret_cast<uint32_t*>(g_vl + base) = lo;
                    }
                } else {
                    float2* pd = reinterpret_cast<float2*>(outp + (size_t)m * C_ + o);
                    *pd = make_float2(v0 + bias[o], v1 + bias[o + 1]);
                }
            }
        }
    }
}

// ---------------------------------------------------------------------------
// Flash attention, fp16: S = Qh Kh^T (1 MMA), PV = Ph * (Vh + Vl) (2 MMAs),
// register P, warp-local softmax. smem: Qh 16K | 2 x 24K (Kh|Vh|Vl) = 64 KB.
// ---------------------------------------------------------------------------
static constexpr int ATT_KV   = 16384;
static constexpr int ATT_STG  = 24576;
static constexpr int ATT_SMEM = 65536;

__global__ __launch_bounds__(256, 2) void attn_mma() {
    extern __shared__ char smem[];
    const uint32_t sb = smem_u32(smem);
    const int tid = threadIdx.x, lane = tid & 31, w = tid >> 5;
    const int qt = blockIdx.x, h = blockIdx.y, b = blockIdx.z;
    const size_t bh = (size_t)(b * H_ + h) * L_;

    const int r0   = lane >> 2;
    const int cb   = (lane & 3) * 2;
    const int a_lr = lane & 15;
    const int a_cb = (lane >> 4) << 4;
    const int b_lr = ((lane >> 4) << 3) + (lane & 7);
    const int b_cb = ((lane >> 3) & 1) << 4;
    const int v_lr = (lane & 7) + (((lane >> 3) & 1) << 3);
    const int v_cB = ((lane >> 4) << 3) * 2;

    // ---- Q tile (128x64 fp16), once ----
    #pragma unroll
    for (int t = 0; t < 4; t++) {
        int idx = tid + t * 256;
        int r = idx >> 3, j = idx & 7;
        cp16(sb + SWZ(r * 128 + j * 16), g_qh + (bh + qt * 128 + r) * DH_ + j * 8);
    }
    asm volatile("cp.async.commit_group;" ::: "memory");

    auto prefetch = [&](int kt) {
        const uint32_t stg = sb + ATT_KV + (kt & 1) * ATT_STG;
        #pragma unroll
        for (int t = 0; t < 6; t++) {
            int idx = tid + t * 256;
            int p = idx >> 9, r = (idx >> 3) & 63, j = idx & 7;
            const __half* src =
                ((p == 0) ? g_kh : (p == 1) ? g_vh : g_vl)
                + (bh + kt * 64 + r) * DH_ + j * 8;
            cp16(stg + p * 8192 + SWZ(r * 128 + j * 16), src);
        }
        asm volatile("cp.async.commit_group;" ::: "memory");
    };
    prefetch(0);

    float c_o[8][4];
    #pragma unroll
    for (int nj = 0; nj < 8; nj++)
        #pragma unroll
        for (int e = 0; e < 4; e++) c_o[nj][e] = 0.f;
    float m2[2] = {-1e30f, -1e30f}, l2[2] = {0.f, 0.f};

    for (int kt = 0; kt < L_ / 64; kt++) {
        if (kt + 1 < L_ / 64) {
            prefetch(kt + 1);
            asm volatile("cp.async.wait_group 1;" ::: "memory");
        } else {
            asm volatile("cp.async.wait_group 0;" ::: "memory");
        }
        __syncthreads();

        const uint32_t stg = sb + ATT_KV + (kt & 1) * ATT_STG;
        const uint32_t kH = stg, vH = stg + 8192, vL = stg + 16384;

        // ---- S = Q K^T : warp 16x64 stripe, fp16, 1 MMA / fragment ----
        float c_s[8][4];
        #pragma unroll
        for (int nj = 0; nj < 8; nj++)
            #pragma unroll
            for (int e = 0; e < 4; e++) c_s[nj][e] = 0.f;

        #pragma unroll
        for (int ks = 0; ks < 4; ks++) {
            const int kb = ks * 32;
            uint32_t qa[4];
            ldmx4(qa, sb + SWZ((w * 16 + a_lr) * 128 + kb + a_cb));
            #pragma unroll
            for (int grp = 0; grp < 4; grp++) {
                uint32_t off = SWZ((grp * 16 + b_lr) * 128 + kb + b_cb);
                uint32_t r[4];
                ldmx4(r, kH + off);
                uint32_t f0[2] = {r[0], r[1]}, f1[2] = {r[2], r[3]};
                mma16816h(c_s[grp * 2],     qa, f0);
                mma16816h(c_s[grp * 2 + 1], qa, f1);
            }
        }

        // ---- warp-local online softmax ----
        float alpha[2];
        #pragma unroll
        for (int rh = 0; rh < 2; rh++) {
            float mx = -1e30f;
            #pragma unroll
            for (int nj = 0; nj < 8; nj++)
                mx = fmaxf(mx, fmaxf(c_s[nj][rh * 2], c_s[nj][rh * 2 + 1]));
            mx = fmaxf(mx, __shfl_xor_sync(0xffffffffu, mx, 1));
            mx = fmaxf(mx, __shfl_xor_sync(0xffffffffu, mx, 2));
            float mnew = fmaxf(m2[rh], mx);
            alpha[rh] = __expf(m2[rh] - mnew);
            m2[rh] = mnew;
        }

        uint32_t ph[4][4];
        float rs0 = 0.f, rs1 = 0.f;
        #pragma unroll
        for (int nj = 0; nj < 8; nj++) {
            float p0 = __expf(c_s[nj][0] - m2[0]);
            float p1 = __expf(c_s[nj][1] - m2[0]);
            float p2 = __expf(c_s[nj][2] - m2[1]);
            float p3 = __expf(c_s[nj][3] - m2[1]);
            rs0 += p0 + p1;
            rs1 += p2 + p3;
            ph[nj >> 1][(nj & 1) * 2 + 0] = packh(p0, p1);
            ph[nj >> 1][(nj & 1) * 2 + 1] = packh(p2, p3);
        }
        rs0 += __shfl_xor_sync(0xffffffffu, rs0, 1);
        rs0 += __shfl_xor_sync(0xffffffffu, rs0, 2);
        rs1 += __shfl_xor_sync(0xffffffffu, rs1, 1);
        rs1 += __shfl_xor_sync(0xffffffffu, rs1, 2);
        l2[0] = l2[0] * alpha[0] + rs0;
        l2[1] = l2[1] * alpha[1] + rs1;
        #pragma unroll
        for (int nj = 0; nj < 8; nj++) {
            c_o[nj][0] *= alpha[0];
            c_o[nj][1] *= alpha[0];
            c_o[nj][2] *= alpha[1];
            c_o[nj][3] *= alpha[1];
        }

        // ---- O += P V  (P fp16 register; V fp16 hi/lo via ldmatrix.trans) ----
        #pragma unroll
        for (int ks = 0; ks < 4; ks++) {
            uint32_t vb_h[8][2], vb_l[8][2];
            #pragma unroll
            for (int grp = 0; grp < 4; grp++) {
                uint32_t off = SWZ((ks * 16 + v_lr) * 128 + grp * 32 + v_cB);
                uint32_t r[4];
                ldmx4t(r, vH + off);
                vb_h[grp * 2][0] = r[0]; vb_h[grp * 2][1] = r[1];
                vb_h[grp * 2 + 1][0] = r[2]; vb_h[grp * 2 + 1][1] = r[3];
                ldmx4t(r, vL + off);
                vb_l[grp * 2][0] = r[0]; vb_l[grp * 2][1] = r[1];
                vb_l[grp * 2 + 1][0] = r[2]; vb_l[grp * 2 + 1][1] = r[3];
            }
            #pragma unroll
            for (int nj = 0; nj < 8; nj++) {
                mma16816h(c_o[nj], ph[ks], vb_h[nj]);
                mma16816h(c_o[nj], ph[ks], vb_l[nj]);
            }
        }
        __syncthreads();
    }

    // ---- epilogue ----
    #pragma unroll
    for (int rh = 0; rh < 2; rh++) {
        int row = qt * 128 + w * 16 + r0 + rh * 8;
        float inv = 1.0f / l2[rh];
        size_t grow = ((size_t)b * L_ + row) * C_ + h * DH_;
        #pragma unroll
        for (int nj = 0; nj < 8; nj++) {
            float o0 = c_o[nj][rh * 2]     * inv;
            float o1 = c_o[nj][rh * 2 + 1] * inv;
            uint32_t hi, lo;
            split2(o0, o1, hi, lo);
            *reinterpret_cast<uint32_t*>(g_ath + grow + nj * 8 + cb) = hi;
            *reinterpret_cast<uint32_t*>(g_atl + grow + nj * 8 + cb) = lo;
        }
    }
}

// ---------------------------------------------------------------------------
extern "C" void kernel_launch(void* const* d_in, const int* in_sizes, int n_in,
                              void* d_out, int out_size) {
    const float* x     = (const float*)d_in[0];
    const float* w_qkv = (const float*)d_in[1];
    const float* w_out = (const float*)d_in[2];
    const float* b_out = (const float*)d_in[3];
    float* out = (float*)d_out;

    cudaFuncSetAttribute(hmma_gemm<0>, cudaFuncAttributeMaxDynamicSharedMemorySize, GSMEM);
    cudaFuncSetAttribute(hmma_gemm<1>, cudaFuncAttributeMaxDynamicSharedMemorySize, GSMEM);
    cudaFuncSetAttribute(attn_mma, cudaFuncAttributeMaxDynamicSharedMemorySize, ATT_SMEM);

    split_bf16<0><<<4096 * 1024 / 1024, 256>>>(x, 4096 * 1024);
    split_bf16<1><<<3072 * 1024 / 1024, 256>>>(w_qkv, 3072 * 1024);
    split_bf16<2><<<1024 * 1024 / 1024, 256>>>(w_out, 1024 * 1024);

    hmma_gemm<0><<<dim3(24, 32), 256, GSMEM>>>(nullptr, nullptr);

    attn_mma<<<dim3(L_ / 128, H_, B_), 256, ATT_SMEM>>>();

    hmma_gemm<1><<<dim3(8, 32), 256, GSMEM>>>(b_out, out);
}

// round 8
// speedup vs baseline: 5.7630x; 1.0991x over previous
#include <cuda_runtime.h>
#include <cuda_bf16.h>
#include <cuda_fp16.h>
#include <cstdint>

// ---------------------------------------------------------------------------
// MHA block. Round 8: Q/K 1-MMA in QKV, PV 1-MMA (fp16 V), 3-stage pipelines.
// ---------------------------------------------------------------------------

#define B_   2
#define L_   2048
#define C_   1024
#define H_   16
#define DH_  64
#define SCALE_ 0.03125f   // 1024^-0.5

// ---------------- scratch ----------------------------------------------------
__device__ __nv_bfloat16 g_xh[4096 * 1024], g_xl[4096 * 1024];
__device__ __nv_bfloat16 g_wqh[3072 * 1024], g_wql[3072 * 1024];
__device__ __nv_bfloat16 g_woh[1024 * 1024], g_wol[1024 * 1024];
__device__ __nv_bfloat16 g_ath[4096 * 1024], g_atl[4096 * 1024];
__device__ __half g_qh[B_*H_*L_*DH_];
__device__ __half g_kh[B_*H_*L_*DH_];
__device__ __half g_vh[B_*H_*L_*DH_];

// ---------------- helpers ----------------------------------------------------
static __device__ __forceinline__ uint32_t smem_u32(const void* p) {
    uint32_t a;
    asm("{ .reg .u64 t; cvta.to.shared.u64 t, %1; cvt.u32.u64 %0, t; }"
        : "=r"(a) : "l"(p));
    return a;
}
#define SWZ(o)   ((o) ^ (((o) >> 3) & 0x70))   // 128B-row swizzle
#define SWZ64(o) ((o) ^ (((o) >> 3) & 0x30))   // 64B-row swizzle

static __device__ __forceinline__ void cp16(uint32_t saddr, const void* gaddr) {
    asm volatile("cp.async.cg.shared.global [%0], [%1], 16;"
                 :: "r"(saddr), "l"(gaddr) : "memory");
}
static __device__ __forceinline__ void ldmx4(uint32_t* r, uint32_t addr) {
    asm volatile("ldmatrix.sync.aligned.m8n8.x4.shared.b16 {%0,%1,%2,%3}, [%4];"
                 : "=r"(r[0]), "=r"(r[1]), "=r"(r[2]), "=r"(r[3]) : "r"(addr));
}
static __device__ __forceinline__ void ldmx4t(uint32_t* r, uint32_t addr) {
    asm volatile("ldmatrix.sync.aligned.m8n8.x4.trans.shared.b16 {%0,%1,%2,%3}, [%4];"
                 : "=r"(r[0]), "=r"(r[1]), "=r"(r[2]), "=r"(r[3]) : "r"(addr));
}
static __device__ __forceinline__ void mma16816(float* c, const uint32_t* a,
                                                const uint32_t* b) {
    asm volatile(
        "mma.sync.aligned.m16n8k16.row.col.f32.bf16.bf16.f32 "
        "{%0,%1,%2,%3}, {%4,%5,%6,%7}, {%8,%9}, {%0,%1,%2,%3};"
        : "+f"(c[0]), "+f"(c[1]), "+f"(c[2]), "+f"(c[3])
        : "r"(a[0]), "r"(a[1]), "r"(a[2]), "r"(a[3]), "r"(b[0]), "r"(b[1]));
}
static __device__ __forceinline__ void mma16816h(float* c, const uint32_t* a,
                                                 const uint32_t* b) {
    asm volatile(
        "mma.sync.aligned.m16n8k16.row.col.f32.f16.f16.f32 "
        "{%0,%1,%2,%3}, {%4,%5,%6,%7}, {%8,%9}, {%0,%1,%2,%3};"
        : "+f"(c[0]), "+f"(c[1]), "+f"(c[2]), "+f"(c[3])
        : "r"(a[0]), "r"(a[1]), "r"(a[2]), "r"(a[3]), "r"(b[0]), "r"(b[1]));
}
static __device__ __forceinline__ uint32_t packbf(float a, float b) {
    __nv_bfloat162 t = __floats2bfloat162_rn(a, b);
    return *reinterpret_cast<uint32_t*>(&t);
}
static __device__ __forceinline__ uint32_t packh(float a, float b) {
    __half2 t = __floats2half2_rn(a, b);
    return *reinterpret_cast<uint32_t*>(&t);
}
static __device__ __forceinline__ void split2(float a, float b,
                                              uint32_t& hi, uint32_t& lo) {
    __nv_bfloat16 ha = __float2bfloat16(a), hb = __float2bfloat16(b);
    hi = ((uint32_t)*reinterpret_cast<uint16_t*>(&hb) << 16) |
         *reinterpret_cast<uint16_t*>(&ha);
    lo = packbf(a - __bfloat162float(ha), b - __bfloat162float(hb));
}

// ---------------------------------------------------------------------------
// fp32 -> bf16 hi/lo split.  SEL: 0=x, 1=w_qkv, 2=w_out
// ---------------------------------------------------------------------------
template <int SEL>
__global__ __launch_bounds__(256) void split_bf16(const float* __restrict__ src, int n) {
    __nv_bfloat16 *h, *l;
    if (SEL == 0)      { h = g_xh;  l = g_xl;  }
    else if (SEL == 1) { h = g_wqh; l = g_wql; }
    else               { h = g_woh; l = g_wol; }

    int i = blockIdx.x * 256 + threadIdx.x;
    if (i * 4 < n) {
        float4 v = reinterpret_cast<const float4*>(src)[i];
        float vv[4] = {v.x, v.y, v.z, v.w};
        __nv_bfloat16 hh[4], ll[4];
        #pragma unroll
        for (int j = 0; j < 4; j++) {
            hh[j] = __float2bfloat16(vv[j]);
            ll[j] = __float2bfloat16(vv[j] - __bfloat162float(hh[j]));
        }
        *reinterpret_cast<uint2*>(h + i * 4) = *reinterpret_cast<uint2*>(hh);
        *reinterpret_cast<uint2*>(l + i * 4) = *reinterpret_cast<uint2*>(ll);
    }
}

// ---------------------------------------------------------------------------
// HMMA GEMM: 128x128 tile, K-chunk 32 (SW64), 3-stage, 2 CTAs/SM.
// OUTK 0: QKV. Q/K tiles: 1 MMA (hi*hi). V tile: 3 MMAs (hi/lo).
// OUTK 1: out-proj, 3 MMAs, fp32 + bias.
// ---------------------------------------------------------------------------
static constexpr int GSMEM = 98304;   // 3 stages x 32KB

template <int OUTK>
__global__ __launch_bounds__(256, 2) void hmma_gemm(const float* __restrict__ bias,
                                                    float* __restrict__ outp) {
    extern __shared__ char smem[];
    const uint32_t sb = smem_u32(smem);
    const int tid = threadIdx.x;
    const int lane = tid & 31, wid = tid >> 5;
    const int wm = wid & 1, wn = wid >> 1;

    const __nv_bfloat16* Ah = (OUTK == 0) ? g_xh  : g_ath;
    const __nv_bfloat16* Al = (OUTK == 0) ? g_xl  : g_atl;
    const __nv_bfloat16* Bh = (OUTK == 0) ? g_wqh : g_woh;
    const __nv_bfloat16* Bl = (OUTK == 0) ? g_wql : g_wol;

    const int n0 = blockIdx.x * 128;
    const int m0 = blockIdx.y * 128;
    const int part = (OUTK == 0) ? (blockIdx.x >> 3) : 1;     // 0=Q 1=K 2=V
    const bool full = (OUTK == 1) || (part == 2);             // 3-term vs 1-term

    float c[4][4][4];
    #pragma unroll
    for (int i = 0; i < 4; i++)
        #pragma unroll
        for (int j = 0; j < 4; j++)
            #pragma unroll
            for (int e = 0; e < 4; e++) c[i][j][e] = 0.f;

    // stage = 32KB: Ah 8K | Al 8K | Bh 8K | Bl 8K ; rows are 64B (32 bf16)
    auto prefetch = [&](int ch, int s) {
        const int k0 = ch * 32;
        #pragma unroll
        for (int p = 0; p < 4; p++) {
            if ((p == 1 || p == 3) && !full) continue;
            const __nv_bfloat16* src = (p == 0) ? Ah : (p == 1) ? Al : (p == 2) ? Bh : Bl;
            const int base = (p < 2) ? m0 : n0;
            #pragma unroll
            for (int t = 0; t < 2; t++) {
                int idx = tid + t * 256;
                int r = idx >> 2, j = idx & 3;
                uint32_t sa = sb + s * 32768 + p * 8192 + SWZ64(r * 64 + j * 16);
                cp16(sa, src + (size_t)(base + r) * 1024 + k0 + j * 8);
            }
        }
        asm volatile("cp.async.commit_group;" ::: "memory");
    };

    prefetch(0, 0);
    prefetch(1, 1);

    int stage = 0;
    for (int ch = 0; ch < 32; ch++) {
        if (ch + 2 < 32) {
            prefetch(ch + 2, (ch + 2) % 3);
            asm volatile("cp.async.wait_group 2;" ::: "memory");
        } else if (ch + 1 < 32) {
            asm volatile("cp.async.wait_group 1;" ::: "memory");
        } else {
            asm volatile("cp.async.wait_group 0;" ::: "memory");
        }
        __syncthreads();

        const uint32_t stg = sb + stage * 32768;
        stage = (stage + 1 == 3) ? 0 : stage + 1;
        const uint32_t aH = stg, aL = stg + 8192, bH = stg + 16384, bL = stg + 24576;

        const int a_row = wm * 64 + (lane & 15);
        const int a_cb  = (lane >> 4) << 4;
        const int b_row = wn * 32 + ((lane >> 4) << 3) + (lane & 7);
        const int b_cb  = ((lane >> 3) & 1) << 4;

        #pragma unroll
        for (int ks = 0; ks < 2; ks++) {
            const int kb = ks * 32;
            uint32_t ahf[4][4], alf[4][4];
            #pragma unroll
            for (int mi = 0; mi < 4; mi++) {
                uint32_t off = SWZ64((a_row + mi * 16) * 64 + kb + a_cb);
                ldmx4(ahf[mi], aH + off);
                if (full) ldmx4(alf[mi], aL + off);
            }
            uint32_t bhf[4][2], blf[4][2];
            #pragma unroll
            for (int nj = 0; nj < 2; nj++) {
                uint32_t off = SWZ64((b_row + nj * 16) * 64 + kb + b_cb);
                uint32_t r[4];
                ldmx4(r, bH + off);
                bhf[nj * 2][0] = r[0]; bhf[nj * 2][1] = r[1];
                bhf[nj * 2 + 1][0] = r[2]; bhf[nj * 2 + 1][1] = r[3];
                if (full) {
                    ldmx4(r, bL + off);
                    blf[nj * 2][0] = r[0]; blf[nj * 2][1] = r[1];
                    blf[nj * 2 + 1][0] = r[2]; blf[nj * 2 + 1][1] = r[3];
                }
            }
            #pragma unroll
            for (int mi = 0; mi < 4; mi++)
                #pragma unroll
                for (int nj = 0; nj < 4; nj++) {
                    mma16816(c[mi][nj], ahf[mi], bhf[nj]);
                    if (full) {
                        mma16816(c[mi][nj], alf[mi], bhf[nj]);
                        mma16816(c[mi][nj], ahf[mi], blf[nj]);
                    }
                }
        }
        __syncthreads();
    }

    const int row_in = lane >> 2;
    const int col_in = (lane & 3) * 2;
    #pragma unroll
    for (int mi = 0; mi < 4; mi++) {
        #pragma unroll
        for (int nj = 0; nj < 4; nj++) {
            int o = n0 + wn * 32 + nj * 8 + col_in;
            #pragma unroll
            for (int half = 0; half < 2; half++) {
                int m = m0 + wm * 64 + mi * 16 + row_in + half * 8;
                float v0 = c[mi][nj][half * 2 + 0];
                float v1 = c[mi][nj][half * 2 + 1];
                if (OUTK == 0) {
                    int b = m >> 11, l = m & (L_ - 1);
                    int cc = o & (C_ - 1);
                    int hh = cc >> 6, d = cc & 63;
                    size_t base = (((size_t)(b << 4) + hh) * L_ + l) * DH_ + d;
                    if (part == 0) {
                        *reinterpret_cast<uint32_t*>(g_qh + base) =
                            packh(v0 * SCALE_, v1 * SCALE_);
                    } else if (part == 1) {
                        *reinterpret_cast<uint32_t*>(g_kh + base) = packh(v0, v1);
                    } else {
                        *reinterpret_cast<uint32_t*>(g_vh + base) = packh(v0, v1);
                    }
                } else {
                    float2* pd = reinterpret_cast<float2*>(outp + (size_t)m * C_ + o);
                    *pd = make_float2(v0 + bias[o], v1 + bias[o + 1]);
                }
            }
        }
    }
}

// ---------------------------------------------------------------------------
// Flash attention, fp16: S = Q K^T (1 MMA), PV = P V (1 MMA), register P,
// warp-local softmax. smem: Qh 16K | 3 stages x 16K (Kh|Vh) = 64 KB.
// ---------------------------------------------------------------------------
static constexpr int ATT_KV   = 16384;
static constexpr int ATT_STG  = 16384;
static constexpr int ATT_SMEM = 65536;

__global__ __launch_bounds__(256, 2) void attn_mma() {
    extern __shared__ char smem[];
    const uint32_t sb = smem_u32(smem);
    const int tid = threadIdx.x, lane = tid & 31, w = tid >> 5;
    const int qt = blockIdx.x, h = blockIdx.y, b = blockIdx.z;
    const size_t bh = (size_t)(b * H_ + h) * L_;

    const int r0   = lane >> 2;
    const int cb   = (lane & 3) * 2;
    const int a_lr = lane & 15;
    const int a_cb = (lane >> 4) << 4;
    const int b_lr = ((lane >> 4) << 3) + (lane & 7);
    const int b_cb = ((lane >> 3) & 1) << 4;
    const int v_lr = (lane & 7) + (((lane >> 3) & 1) << 3);
    const int v_cB = ((lane >> 4) << 3) * 2;

    // ---- Q tile (128x64 fp16), once ----
    #pragma unroll
    for (int t = 0; t < 4; t++) {
        int idx = tid + t * 256;
        int r = idx >> 3, j = idx & 7;
        cp16(sb + SWZ(r * 128 + j * 16), g_qh + (bh + qt * 128 + r) * DH_ + j * 8);
    }
    asm volatile("cp.async.commit_group;" ::: "memory");

    auto prefetch = [&](int kt) {
        const uint32_t stg = sb + ATT_KV + (kt % 3) * ATT_STG;
        #pragma unroll
        for (int t = 0; t < 4; t++) {
            int idx = tid + t * 256;
            int p = idx >> 9, r = (idx >> 3) & 63, j = idx & 7;
            const __half* src = ((p == 0) ? g_kh : g_vh) + (bh + kt * 64 + r) * DH_ + j * 8;
            cp16(stg + p * 8192 + SWZ(r * 128 + j * 16), src);
        }
        asm volatile("cp.async.commit_group;" ::: "memory");
    };
    prefetch(0);
    prefetch(1);

    float c_o[8][4];
    #pragma unroll
    for (int nj = 0; nj < 8; nj++)
        #pragma unroll
        for (int e = 0; e < 4; e++) c_o[nj][e] = 0.f;
    float m2[2] = {-1e30f, -1e30f}, l2[2] = {0.f, 0.f};

    const int NKT = L_ / 64;
    for (int kt = 0; kt < NKT; kt++) {
        if (kt + 2 < NKT) {
            prefetch(kt + 2);
            asm volatile("cp.async.wait_group 2;" ::: "memory");
        } else if (kt + 1 < NKT) {
            asm volatile("cp.async.wait_group 1;" ::: "memory");
        } else {
            asm volatile("cp.async.wait_group 0;" ::: "memory");
        }
        __syncthreads();

        const uint32_t stg = sb + ATT_KV + (kt % 3) * ATT_STG;
        const uint32_t kH = stg, vH = stg + 8192;

        // ---- S = Q K^T : warp 16x64 stripe, 1 MMA / fragment ----
        float c_s[8][4];
        #pragma unroll
        for (int nj = 0; nj < 8; nj++)
            #pragma unroll
            for (int e = 0; e < 4; e++) c_s[nj][e] = 0.f;

        #pragma unroll
        for (int ks = 0; ks < 4; ks++) {
            const int kb = ks * 32;
            uint32_t qa[4];
            ldmx4(qa, sb + SWZ((w * 16 + a_lr) * 128 + kb + a_cb));
            #pragma unroll
            for (int grp = 0; grp < 4; grp++) {
                uint32_t off = SWZ((grp * 16 + b_lr) * 128 + kb + b_cb);
                uint32_t r[4];
                ldmx4(r, kH + off);
                uint32_t f0[2] = {r[0], r[1]}, f1[2] = {r[2], r[3]};
                mma16816h(c_s[grp * 2],     qa, f0);
                mma16816h(c_s[grp * 2 + 1], qa, f1);
            }
        }

        // ---- warp-local online softmax ----
        float alpha[2];
        #pragma unroll
        for (int rh = 0; rh < 2; rh++) {
            float mx = -1e30f;
            #pragma unroll
            for (int nj = 0; nj < 8; nj++)
                mx = fmaxf(mx, fmaxf(c_s[nj][rh * 2], c_s[nj][rh * 2 + 1]));
            mx = fmaxf(mx, __shfl_xor_sync(0xffffffffu, mx, 1));
            mx = fmaxf(mx, __shfl_xor_sync(0xffffffffu, mx, 2));
            float mnew = fmaxf(m2[rh], mx);
            alpha[rh] = __expf(m2[rh] - mnew);
            m2[rh] = mnew;
        }

        uint32_t ph[4][4];
        float rs0 = 0.f, rs1 = 0.f;
        #pragma unroll
        for (int nj = 0; nj < 8; nj++) {
            float p0 = __expf(c_s[nj][0] - m2[0]);
            float p1 = __expf(c_s[nj][1] - m2[0]);
            float p2 = __expf(c_s[nj][2] - m2[1]);
            float p3 = __expf(c_s[nj][3] - m2[1]);
            rs0 += p0 + p1;
            rs1 += p2 + p3;
            ph[nj >> 1][(nj & 1) * 2 + 0] = packh(p0, p1);
            ph[nj >> 1][(nj & 1) * 2 + 1] = packh(p2, p3);
        }
        rs0 += __shfl_xor_sync(0xffffffffu, rs0, 1);
        rs0 += __shfl_xor_sync(0xffffffffu, rs0, 2);
        rs1 += __shfl_xor_sync(0xffffffffu, rs1, 1);
        rs1 += __shfl_xor_sync(0xffffffffu, rs1, 2);
        l2[0] = l2[0] * alpha[0] + rs0;
        l2[1] = l2[1] * alpha[1] + rs1;
        #pragma unroll
        for (int nj = 0; nj < 8; nj++) {
            c_o[nj][0] *= alpha[0];
            c_o[nj][1] *= alpha[0];
            c_o[nj][2] *= alpha[1];
            c_o[nj][3] *= alpha[1];
        }

        // ---- O += P V  (P fp16 register; V via ldmatrix.trans) ----
        #pragma unroll
        for (int ks = 0; ks < 4; ks++) {
            uint32_t vb[8][2];
            #pragma unroll
            for (int grp = 0; grp < 4; grp++) {
                uint32_t off = SWZ((ks * 16 + v_lr) * 128 + grp * 32 + v_cB);
                uint32_t r[4];
                ldmx4t(r, vH + off);
                vb[grp * 2][0] = r[0]; vb[grp * 2][1] = r[1];
                vb[grp * 2 + 1][0] = r[2]; vb[grp * 2 + 1][1] = r[3];
            }
            #pragma unroll
            for (int nj = 0; nj < 8; nj++)
                mma16816h(c_o[nj], ph[ks], vb[nj]);
        }
        __syncthreads();
    }

    // ---- epilogue: O/l -> bf16 hi/lo att ----
    #pragma unroll
    for (int rh = 0; rh < 2; rh++) {
        int row = qt * 128 + w * 16 + r0 + rh * 8;
        float inv = 1.0f / l2[rh];
        size_t grow = ((size_t)b * L_ + row) * C_ + h * DH_;
        #pragma unroll
        for (int nj = 0; nj < 8; nj++) {
            float o0 = c_o[nj][rh * 2]     * inv;
            float o1 = c_o[nj][rh * 2 + 1] * inv;
            uint32_t hi, lo;
            split2(o0, o1, hi, lo);
            *reinterpret_cast<uint32_t*>(g_ath + grow + nj * 8 + cb) = hi;
            *reinterpret_cast<uint32_t*>(g_atl + grow + nj * 8 + cb) = lo;
        }
    }
}

// ---------------------------------------------------------------------------
extern "C" void kernel_launch(void* const* d_in, const int* in_sizes, int n_in,
                              void* d_out, int out_size) {
    const float* x     = (const float*)d_in[0];
    const float* w_qkv = (const float*)d_in[1];
    const float* w_out = (const float*)d_in[2];
    const float* b_out = (const float*)d_in[3];
    float* out = (float*)d_out;

    cudaFuncSetAttribute(hmma_gemm<0>, cudaFuncAttributeMaxDynamicSharedMemorySize, GSMEM);
    cudaFuncSetAttribute(hmma_gemm<1>, cudaFuncAttributeMaxDynamicSharedMemorySize, GSMEM);
    cudaFuncSetAttribute(attn_mma, cudaFuncAttributeMaxDynamicSharedMemorySize, ATT_SMEM);

    split_bf16<0><<<4096 * 1024 / 1024, 256>>>(x, 4096 * 1024);
    split_bf16<1><<<3072 * 1024 / 1024, 256>>>(w_qkv, 3072 * 1024);
    split_bf16<2><<<1024 * 1024 / 1024, 256>>>(w_out, 1024 * 1024);

    hmma_gemm<0><<<dim3(24, 32), 256, GSMEM>>>(nullptr, nullptr);

    attn_mma<<<dim3(L_ / 128, H_, B_), 256, ATT_SMEM>>>();

    hmma_gemm<1><<<dim3(8, 32), 256, GSMEM>>>(b_out, out);
}

// round 9
// speedup vs baseline: 9.1220x; 1.5828x over previous
#include <cuda_runtime.h>
#include <cuda_fp16.h>
#include <cstdint>

// ---------------------------------------------------------------------------
// MHA block. Round 9: all-fp16 operands, 1 MMA per k16 everywhere.
// ---------------------------------------------------------------------------

#define B_   2
#define L_   2048
#define C_   1024
#define H_   16
#define DH_  64
#define SCALE_ 0.03125f   // 1024^-0.5

// ---------------- scratch ----------------------------------------------------
__device__ __half g_x16[4096 * 1024];
__device__ __half g_wq16[3072 * 1024];
__device__ __half g_wo16[1024 * 1024];
__device__ __half g_at16[4096 * 1024];
__device__ __half g_qh[B_*H_*L_*DH_];
__device__ __half g_kh[B_*H_*L_*DH_];
__device__ __half g_vh[B_*H_*L_*DH_];

// ---------------- helpers ----------------------------------------------------
static __device__ __forceinline__ uint32_t smem_u32(const void* p) {
    uint32_t a;
    asm("{ .reg .u64 t; cvta.to.shared.u64 t, %1; cvt.u32.u64 %0, t; }"
        : "=r"(a) : "l"(p));
    return a;
}
#define SWZ(o)   ((o) ^ (((o) >> 3) & 0x70))   // 128B-row swizzle
#define SWZ64(o) ((o) ^ (((o) >> 3) & 0x30))   // 64B-row swizzle

static __device__ __forceinline__ void cp16(uint32_t saddr, const void* gaddr) {
    asm volatile("cp.async.cg.shared.global [%0], [%1], 16;"
                 :: "r"(saddr), "l"(gaddr) : "memory");
}
static __device__ __forceinline__ void ldmx4(uint32_t* r, uint32_t addr) {
    asm volatile("ldmatrix.sync.aligned.m8n8.x4.shared.b16 {%0,%1,%2,%3}, [%4];"
                 : "=r"(r[0]), "=r"(r[1]), "=r"(r[2]), "=r"(r[3]) : "r"(addr));
}
static __device__ __forceinline__ void ldmx4t(uint32_t* r, uint32_t addr) {
    asm volatile("ldmatrix.sync.aligned.m8n8.x4.trans.shared.b16 {%0,%1,%2,%3}, [%4];"
                 : "=r"(r[0]), "=r"(r[1]), "=r"(r[2]), "=r"(r[3]) : "r"(addr));
}
static __device__ __forceinline__ void mma16816h(float* c, const uint32_t* a,
                                                 const uint32_t* b) {
    asm volatile(
        "mma.sync.aligned.m16n8k16.row.col.f32.f16.f16.f32 "
        "{%0,%1,%2,%3}, {%4,%5,%6,%7}, {%8,%9}, {%0,%1,%2,%3};"
        : "+f"(c[0]), "+f"(c[1]), "+f"(c[2]), "+f"(c[3])
        : "r"(a[0]), "r"(a[1]), "r"(a[2]), "r"(a[3]), "r"(b[0]), "r"(b[1]));
}
static __device__ __forceinline__ uint32_t packh(float a, float b) {
    __half2 t = __floats2half2_rn(a, b);
    return *reinterpret_cast<uint32_t*>(&t);
}

// ---------------------------------------------------------------------------
// fp32 -> fp16 convert.  SEL: 0=x, 1=w_qkv, 2=w_out
// ---------------------------------------------------------------------------
template <int SEL>
__global__ __launch_bounds__(256) void conv_h(const float* __restrict__ src, int n) {
    __half* dst = (SEL == 0) ? g_x16 : (SEL == 1) ? g_wq16 : g_wo16;
    int i = blockIdx.x * 256 + threadIdx.x;
    if (i * 4 < n) {
        float4 v = reinterpret_cast<const float4*>(src)[i];
        uint2 o;
        o.x = packh(v.x, v.y);
        o.y = packh(v.z, v.w);
        *reinterpret_cast<uint2*>(dst + i * 4) = o;
    }
}

// ---------------------------------------------------------------------------
// fp16 HMMA GEMM: D[M,N] = A[M,K] * B[N,K]^T, 1 MMA per k16 fragment.
// 128x128 tile, K-chunk 32 (SW64), 3-stage cp.async, 2 CTAs/SM.
// OUTK 0: QKV -> q(scaled)/k/v fp16.  OUTK 1: out-proj -> fp32 + bias.
// ---------------------------------------------------------------------------
static constexpr int GSMEM = 49152;   // 3 stages x 16KB (A 8K | B 8K)

template <int OUTK>
__global__ __launch_bounds__(256, 2) void hmma_gemm(const float* __restrict__ bias,
                                                    float* __restrict__ outp) {
    extern __shared__ char smem[];
    const uint32_t sb = smem_u32(smem);
    const int tid = threadIdx.x;
    const int lane = tid & 31, wid = tid >> 5;
    const int wm = wid & 1, wn = wid >> 1;

    const __half* A = (OUTK == 0) ? g_x16  : g_at16;
    const __half* Bm = (OUTK == 0) ? g_wq16 : g_wo16;

    const int n0 = blockIdx.x * 128;
    const int m0 = blockIdx.y * 128;
    const int part = (OUTK == 0) ? (blockIdx.x >> 3) : 0;     // 0=Q 1=K 2=V

    float c[4][4][4];
    #pragma unroll
    for (int i = 0; i < 4; i++)
        #pragma unroll
        for (int j = 0; j < 4; j++)
            #pragma unroll
            for (int e = 0; e < 4; e++) c[i][j][e] = 0.f;

    // stage = 16KB: A 8K | B 8K ; rows are 64B (32 fp16)
    auto prefetch = [&](int ch) {
        const int s = ch % 3;
        const int k0 = ch * 32;
        #pragma unroll
        for (int p = 0; p < 2; p++) {
            const __half* src = p ? Bm : A;
            const int base = p ? n0 : m0;
            #pragma unroll
            for (int t = 0; t < 2; t++) {
                int idx = tid + t * 256;
                int r = idx >> 2, j = idx & 3;
                uint32_t sa = sb + s * 16384 + p * 8192 + SWZ64(r * 64 + j * 16);
                cp16(sa, src + (size_t)(base + r) * 1024 + k0 + j * 8);
            }
        }
        asm volatile("cp.async.commit_group;" ::: "memory");
    };

    prefetch(0);
    prefetch(1);

    const int a_row = wm * 64 + (lane & 15);
    const int a_cb  = (lane >> 4) << 4;
    const int b_row = wn * 32 + ((lane >> 4) << 3) + (lane & 7);
    const int b_cb  = ((lane >> 3) & 1) << 4;

    for (int ch = 0; ch < 32; ch++) {
        if (ch + 1 < 32) {
            asm volatile("cp.async.wait_group 1;" ::: "memory");
        } else {
            asm volatile("cp.async.wait_group 0;" ::: "memory");
        }
        __syncthreads();
        if (ch + 2 < 32) prefetch(ch + 2);

        const uint32_t stg = sb + (ch % 3) * 16384;
        const uint32_t aS = stg, bS = stg + 8192;

        #pragma unroll
        for (int ks = 0; ks < 2; ks++) {
            const int kb = ks * 32;
            uint32_t af[4][4];
            #pragma unroll
            for (int mi = 0; mi < 4; mi++)
                ldmx4(af[mi], aS + SWZ64((a_row + mi * 16) * 64 + kb + a_cb));
            uint32_t bf[4][2];
            #pragma unroll
            for (int nj = 0; nj < 2; nj++) {
                uint32_t r[4];
                ldmx4(r, bS + SWZ64((b_row + nj * 16) * 64 + kb + b_cb));
                bf[nj * 2][0] = r[0]; bf[nj * 2][1] = r[1];
                bf[nj * 2 + 1][0] = r[2]; bf[nj * 2 + 1][1] = r[3];
            }
            #pragma unroll
            for (int mi = 0; mi < 4; mi++)
                #pragma unroll
                for (int nj = 0; nj < 4; nj++)
                    mma16816h(c[mi][nj], af[mi], bf[nj]);
        }
        __syncthreads();
    }

    const int row_in = lane >> 2;
    const int col_in = (lane & 3) * 2;
    #pragma unroll
    for (int mi = 0; mi < 4; mi++) {
        #pragma unroll
        for (int nj = 0; nj < 4; nj++) {
            int o = n0 + wn * 32 + nj * 8 + col_in;
            #pragma unroll
            for (int half = 0; half < 2; half++) {
                int m = m0 + wm * 64 + mi * 16 + row_in + half * 8;
                float v0 = c[mi][nj][half * 2 + 0];
                float v1 = c[mi][nj][half * 2 + 1];
                if (OUTK == 0) {
                    int b = m >> 11, l = m & (L_ - 1);
                    int cc = o & (C_ - 1);
                    int hh = cc >> 6, d = cc & 63;
                    size_t base = (((size_t)(b << 4) + hh) * L_ + l) * DH_ + d;
                    if (part == 0) {
                        *reinterpret_cast<uint32_t*>(g_qh + base) =
                            packh(v0 * SCALE_, v1 * SCALE_);
                    } else if (part == 1) {
                        *reinterpret_cast<uint32_t*>(g_kh + base) = packh(v0, v1);
                    } else {
                        *reinterpret_cast<uint32_t*>(g_vh + base) = packh(v0, v1);
                    }
                } else {
                    float2* pd = reinterpret_cast<float2*>(outp + (size_t)m * C_ + o);
                    *pd = make_float2(v0 + bias[o], v1 + bias[o + 1]);
                }
            }
        }
    }
}

// ---------------------------------------------------------------------------
// Flash attention, fp16: S = Q K^T (1 MMA), PV (1 MMA), register P,
// warp-local softmax. smem: Q 16K | 3 stages x 16K (K|V) = 64 KB.
// ---------------------------------------------------------------------------
static constexpr int ATT_KV   = 16384;
static constexpr int ATT_STG  = 16384;
static constexpr int ATT_SMEM = 65536;

__global__ __launch_bounds__(256, 2) void attn_mma() {
    extern __shared__ char smem[];
    const uint32_t sb = smem_u32(smem);
    const int tid = threadIdx.x, lane = tid & 31, w = tid >> 5;
    const int qt = blockIdx.x, h = blockIdx.y, b = blockIdx.z;
    const size_t bh = (size_t)(b * H_ + h) * L_;

    const int r0   = lane >> 2;
    const int cb   = (lane & 3) * 2;
    const int a_lr = lane & 15;
    const int a_cb = (lane >> 4) << 4;
    const int b_lr = ((lane >> 4) << 3) + (lane & 7);
    const int b_cb = ((lane >> 3) & 1) << 4;
    const int v_lr = (lane & 7) + (((lane >> 3) & 1) << 3);
    const int v_cB = ((lane >> 4) << 3) * 2;

    // ---- Q tile (128x64 fp16), once ----
    #pragma unroll
    for (int t = 0; t < 4; t++) {
        int idx = tid + t * 256;
        int r = idx >> 3, j = idx & 7;
        cp16(sb + SWZ(r * 128 + j * 16), g_qh + (bh + qt * 128 + r) * DH_ + j * 8);
    }
    asm volatile("cp.async.commit_group;" ::: "memory");

    auto prefetch = [&](int kt) {
        const uint32_t stg = sb + ATT_KV + (kt % 3) * ATT_STG;
        #pragma unroll
        for (int t = 0; t < 4; t++) {
            int idx = tid + t * 256;
            int p = idx >> 9, r = (idx >> 3) & 63, j = idx & 7;
            const __half* src = ((p == 0) ? g_kh : g_vh) + (bh + kt * 64 + r) * DH_ + j * 8;
            cp16(stg + p * 8192 + SWZ(r * 128 + j * 16), src);
        }
        asm volatile("cp.async.commit_group;" ::: "memory");
    };
    prefetch(0);
    prefetch(1);

    float c_o[8][4];
    #pragma unroll
    for (int nj = 0; nj < 8; nj++)
        #pragma unroll
        for (int e = 0; e < 4; e++) c_o[nj][e] = 0.f;
    float m2[2] = {-1e30f, -1e30f}, l2[2] = {0.f, 0.f};

    const int NKT = L_ / 64;
    for (int kt = 0; kt < NKT; kt++) {
        if (kt + 1 < NKT) {
            asm volatile("cp.async.wait_group 1;" ::: "memory");
        } else {
            asm volatile("cp.async.wait_group 0;" ::: "memory");
        }
        __syncthreads();
        if (kt + 2 < NKT) prefetch(kt + 2);

        const uint32_t stg = sb + ATT_KV + (kt % 3) * ATT_STG;
        const uint32_t kH = stg, vH = stg + 8192;

        // ---- S = Q K^T : warp 16x64 stripe, 1 MMA / fragment ----
        float c_s[8][4];
        #pragma unroll
        for (int nj = 0; nj < 8; nj++)
            #pragma unroll
            for (int e = 0; e < 4; e++) c_s[nj][e] = 0.f;

        #pragma unroll
        for (int ks = 0; ks < 4; ks++) {
            const int kb = ks * 32;
            uint32_t qa[4];
            ldmx4(qa, sb + SWZ((w * 16 + a_lr) * 128 + kb + a_cb));
            #pragma unroll
            for (int grp = 0; grp < 4; grp++) {
                uint32_t off = SWZ((grp * 16 + b_lr) * 128 + kb + b_cb);
                uint32_t r[4];
                ldmx4(r, kH + off);
                uint32_t f0[2] = {r[0], r[1]}, f1[2] = {r[2], r[3]};
                mma16816h(c_s[grp * 2],     qa, f0);
                mma16816h(c_s[grp * 2 + 1], qa, f1);
            }
        }

        // ---- warp-local online softmax ----
        float alpha[2];
        #pragma unroll
        for (int rh = 0; rh < 2; rh++) {
            float mx = -1e30f;
            #pragma unroll
            for (int nj = 0; nj < 8; nj++)
                mx = fmaxf(mx, fmaxf(c_s[nj][rh * 2], c_s[nj][rh * 2 + 1]));
            mx = fmaxf(mx, __shfl_xor_sync(0xffffffffu, mx, 1));
            mx = fmaxf(mx, __shfl_xor_sync(0xffffffffu, mx, 2));
            float mnew = fmaxf(m2[rh], mx);
            alpha[rh] = __expf(m2[rh] - mnew);
            m2[rh] = mnew;
        }

        uint32_t ph[4][4];
        float rs0 = 0.f, rs1 = 0.f;
        #pragma unroll
        for (int nj = 0; nj < 8; nj++) {
            float p0 = __expf(c_s[nj][0] - m2[0]);
            float p1 = __expf(c_s[nj][1] - m2[0]);
            float p2 = __expf(c_s[nj][2] - m2[1]);
            float p3 = __expf(c_s[nj][3] - m2[1]);
            rs0 += p0 + p1;
            rs1 += p2 + p3;
            ph[nj >> 1][(nj & 1) * 2 + 0] = packh(p0, p1);
            ph[nj >> 1][(nj & 1) * 2 + 1] = packh(p2, p3);
        }
        rs0 += __shfl_xor_sync(0xffffffffu, rs0, 1);
        rs0 += __shfl_xor_sync(0xffffffffu, rs0, 2);
        rs1 += __shfl_xor_sync(0xffffffffu, rs1, 1);
        rs1 += __shfl_xor_sync(0xffffffffu, rs1, 2);
        l2[0] = l2[0] * alpha[0] + rs0;
        l2[1] = l2[1] * alpha[1] + rs1;
        #pragma unroll
        for (int nj = 0; nj < 8; nj++) {
            c_o[nj][0] *= alpha[0];
            c_o[nj][1] *= alpha[0];
            c_o[nj][2] *= alpha[1];
            c_o[nj][3] *= alpha[1];
        }

        // ---- O += P V  (P fp16 register; V via ldmatrix.trans) ----
        #pragma unroll
        for (int ks = 0; ks < 4; ks++) {
            uint32_t vb[8][2];
            #pragma unroll
            for (int grp = 0; grp < 4; grp++) {
                uint32_t off = SWZ((ks * 16 + v_lr) * 128 + grp * 32 + v_cB);
                uint32_t r[4];
                ldmx4t(r, vH + off);
                vb[grp * 2][0] = r[0]; vb[grp * 2][1] = r[1];
                vb[grp * 2 + 1][0] = r[2]; vb[grp * 2 + 1][1] = r[3];
            }
            #pragma unroll
            for (int nj = 0; nj < 8; nj++)
                mma16816h(c_o[nj], ph[ks], vb[nj]);
        }
        __syncthreads();
    }

    // ---- epilogue: O/l -> fp16 att ----
    #pragma unroll
    for (int rh = 0; rh < 2; rh++) {
        int row = qt * 128 + w * 16 + r0 + rh * 8;
        float inv = 1.0f / l2[rh];
        size_t grow = ((size_t)b * L_ + row) * C_ + h * DH_;
        #pragma unroll
        for (int nj = 0; nj < 8; nj++) {
            float o0 = c_o[nj][rh * 2]     * inv;
            float o1 = c_o[nj][rh * 2 + 1] * inv;
            *reinterpret_cast<uint32_t*>(g_at16 + grow + nj * 8 + cb) = packh(o0, o1);
        }
    }
}

// ---------------------------------------------------------------------------
extern "C" void kernel_launch(void* const* d_in, const int* in_sizes, int n_in,
                              void* d_out, int out_size) {
    const float* x     = (const float*)d_in[0];
    const float* w_qkv = (const float*)d_in[1];
    const float* w_out = (const float*)d_in[2];
    const float* b_out = (const float*)d_in[3];
    float* out = (float*)d_out;

    cudaFuncSetAttribute(hmma_gemm<0>, cudaFuncAttributeMaxDynamicSharedMemorySize, GSMEM);
    cudaFuncSetAttribute(hmma_gemm<1>, cudaFuncAttributeMaxDynamicSharedMemorySize, GSMEM);
    cudaFuncSetAttribute(attn_mma, cudaFuncAttributeMaxDynamicSharedMemorySize, ATT_SMEM);

    conv_h<0><<<4096 * 1024 / 1024, 256>>>(x, 4096 * 1024);
    conv_h<1><<<3072 * 1024 / 1024, 256>>>(w_qkv, 3072 * 1024);
    conv_h<2><<<1024 * 1024 / 1024, 256>>>(w_out, 1024 * 1024);

    hmma_gemm<0><<<dim3(24, 32), 256, GSMEM>>>(nullptr, nullptr);

    attn_mma<<<dim3(L_ / 128, H_, B_), 256, ATT_SMEM>>>();

    hmma_gemm<1><<<dim3(8, 32), 256, GSMEM>>>(b_out, out);
}

// round 10
// speedup vs baseline: 10.0663x; 1.1035x over previous
#include <cuda_runtime.h>
#include <cuda_fp16.h>
#include <cstdint>

// ---------------------------------------------------------------------------
// MHA block. Round 10: all-fp16 1-MMA; GEMM K-chunk 64; base-2 softmax with
// ex2.approx.f16x2 (log2e folded into Q scale).
// ---------------------------------------------------------------------------

#define B_   2
#define L_   2048
#define C_   1024
#define H_   16
#define DH_  64
#define QSCALE_ 0.045084439f   // 1024^-0.5 * log2(e)

// ---------------- scratch ----------------------------------------------------
__device__ __half g_x16[4096 * 1024];
__device__ __half g_wq16[3072 * 1024];
__device__ __half g_wo16[1024 * 1024];
__device__ __half g_at16[4096 * 1024];
__device__ __half g_qh[B_*H_*L_*DH_];
__device__ __half g_kh[B_*H_*L_*DH_];
__device__ __half g_vh[B_*H_*L_*DH_];

// ---------------- helpers ----------------------------------------------------
static __device__ __forceinline__ uint32_t smem_u32(const void* p) {
    uint32_t a;
    asm("{ .reg .u64 t; cvta.to.shared.u64 t, %1; cvt.u32.u64 %0, t; }"
        : "=r"(a) : "l"(p));
    return a;
}
#define SWZ(o)   ((o) ^ (((o) >> 3) & 0x70))   // 128B-row swizzle

static __device__ __forceinline__ void cp16(uint32_t saddr, const void* gaddr) {
    asm volatile("cp.async.cg.shared.global [%0], [%1], 16;"
                 :: "r"(saddr), "l"(gaddr) : "memory");
}
static __device__ __forceinline__ void ldmx4(uint32_t* r, uint32_t addr) {
    asm volatile("ldmatrix.sync.aligned.m8n8.x4.shared.b16 {%0,%1,%2,%3}, [%4];"
                 : "=r"(r[0]), "=r"(r[1]), "=r"(r[2]), "=r"(r[3]) : "r"(addr));
}
static __device__ __forceinline__ void ldmx4t(uint32_t* r, uint32_t addr) {
    asm volatile("ldmatrix.sync.aligned.m8n8.x4.trans.shared.b16 {%0,%1,%2,%3}, [%4];"
                 : "=r"(r[0]), "=r"(r[1]), "=r"(r[2]), "=r"(r[3]) : "r"(addr));
}
static __device__ __forceinline__ void mma16816h(float* c, const uint32_t* a,
                                                 const uint32_t* b) {
    asm volatile(
        "mma.sync.aligned.m16n8k16.row.col.f32.f16.f16.f32 "
        "{%0,%1,%2,%3}, {%4,%5,%6,%7}, {%8,%9}, {%0,%1,%2,%3};"
        : "+f"(c[0]), "+f"(c[1]), "+f"(c[2]), "+f"(c[3])
        : "r"(a[0]), "r"(a[1]), "r"(a[2]), "r"(a[3]), "r"(b[0]), "r"(b[1]));
}
static __device__ __forceinline__ uint32_t packh(float a, float b) {
    __half2 t = __floats2half2_rn(a, b);
    return *reinterpret_cast<uint32_t*>(&t);
}
// exp2 of two floats -> packed fp16x2 (single MUFU op on the f16x2 path)
static __device__ __forceinline__ uint32_t ex2h2(float a, float b) {
    uint32_t p = packh(a, b);
    uint32_t r;
    asm("ex2.approx.f16x2 %0, %1;" : "=r"(r) : "r"(p));
    return r;
}

// ---------------------------------------------------------------------------
// fp32 -> fp16 convert.  SEL: 0=x, 1=w_qkv, 2=w_out
// ---------------------------------------------------------------------------
template <int SEL>
__global__ __launch_bounds__(256) void conv_h(const float* __restrict__ src, int n) {
    __half* dst = (SEL == 0) ? g_x16 : (SEL == 1) ? g_wq16 : g_wo16;
    int i = blockIdx.x * 256 + threadIdx.x;
    if (i * 4 < n) {
        float4 v = reinterpret_cast<const float4*>(src)[i];
        uint2 o;
        o.x = packh(v.x, v.y);
        o.y = packh(v.z, v.w);
        *reinterpret_cast<uint2*>(dst + i * 4) = o;
    }
}

// ---------------------------------------------------------------------------
// fp16 HMMA GEMM: 128x128 tile, K-chunk 64 (SW128), 3-stage, 2 CTAs/SM.
// OUTK 0: QKV -> q(scaled by QSCALE_)/k/v fp16.  OUTK 1: out-proj fp32+bias.
// ---------------------------------------------------------------------------
static constexpr int GSMEM = 98304;   // 3 stages x 32KB (A 16K | B 16K)

template <int OUTK>
__global__ __launch_bounds__(256, 2) void hmma_gemm(const float* __restrict__ bias,
                                                    float* __restrict__ outp) {
    extern __shared__ char smem[];
    const uint32_t sb = smem_u32(smem);
    const int tid = threadIdx.x;
    const int lane = tid & 31, wid = tid >> 5;
    const int wm = wid & 1, wn = wid >> 1;

    const __half* A  = (OUTK == 0) ? g_x16  : g_at16;
    const __half* Bm = (OUTK == 0) ? g_wq16 : g_wo16;

    const int n0 = blockIdx.x * 128;
    const int m0 = blockIdx.y * 128;
    const int part = (OUTK == 0) ? (blockIdx.x >> 3) : 0;     // 0=Q 1=K 2=V

    float c[4][4][4];
    #pragma unroll
    for (int i = 0; i < 4; i++)
        #pragma unroll
        for (int j = 0; j < 4; j++)
            #pragma unroll
            for (int e = 0; e < 4; e++) c[i][j][e] = 0.f;

    // stage = 32KB: A 16K | B 16K ; rows are 128B (64 fp16)
    auto prefetch = [&](int ch) {
        const int s = ch % 3;
        const int k0 = ch * 64;
        #pragma unroll
        for (int p = 0; p < 2; p++) {
            const __half* src = p ? Bm : A;
            const int base = p ? n0 : m0;
            #pragma unroll
            for (int t = 0; t < 4; t++) {
                int idx = tid + t * 256;
                int r = idx >> 3, j = idx & 7;
                uint32_t sa = sb + s * 32768 + p * 16384 + SWZ(r * 128 + j * 16);
                cp16(sa, src + (size_t)(base + r) * 1024 + k0 + j * 8);
            }
        }
        asm volatile("cp.async.commit_group;" ::: "memory");
    };

    prefetch(0);
    prefetch(1);

    const int a_row = wm * 64 + (lane & 15);
    const int a_cb  = (lane >> 4) << 4;
    const int b_row = wn * 32 + ((lane >> 4) << 3) + (lane & 7);
    const int b_cb  = ((lane >> 3) & 1) << 4;

    for (int ch = 0; ch < 16; ch++) {
        if (ch + 1 < 16) {
            asm volatile("cp.async.wait_group 1;" ::: "memory");
        } else {
            asm volatile("cp.async.wait_group 0;" ::: "memory");
        }
        __syncthreads();
        if (ch + 2 < 16) prefetch(ch + 2);

        const uint32_t stg = sb + (ch % 3) * 32768;
        const uint32_t aS = stg, bS = stg + 16384;

        #pragma unroll
        for (int ks = 0; ks < 4; ks++) {
            const int kb = ks * 32;
            uint32_t af[4][4];
            #pragma unroll
            for (int mi = 0; mi < 4; mi++)
                ldmx4(af[mi], aS + SWZ((a_row + mi * 16) * 128 + kb + a_cb));
            uint32_t bf[4][2];
            #pragma unroll
            for (int nj = 0; nj < 2; nj++) {
                uint32_t r[4];
                ldmx4(r, bS + SWZ((b_row + nj * 16) * 128 + kb + b_cb));
                bf[nj * 2][0] = r[0]; bf[nj * 2][1] = r[1];
                bf[nj * 2 + 1][0] = r[2]; bf[nj * 2 + 1][1] = r[3];
            }
            #pragma unroll
            for (int mi = 0; mi < 4; mi++)
                #pragma unroll
                for (int nj = 0; nj < 4; nj++)
                    mma16816h(c[mi][nj], af[mi], bf[nj]);
        }
        __syncthreads();
    }

    const int row_in = lane >> 2;
    const int col_in = (lane & 3) * 2;
    #pragma unroll
    for (int mi = 0; mi < 4; mi++) {
        #pragma unroll
        for (int nj = 0; nj < 4; nj++) {
            int o = n0 + wn * 32 + nj * 8 + col_in;
            #pragma unroll
            for (int half = 0; half < 2; half++) {
                int m = m0 + wm * 64 + mi * 16 + row_in + half * 8;
                float v0 = c[mi][nj][half * 2 + 0];
                float v1 = c[mi][nj][half * 2 + 1];
                if (OUTK == 0) {
                    int b = m >> 11, l = m & (L_ - 1);
                    int cc = o & (C_ - 1);
                    int hh = cc >> 6, d = cc & 63;
                    size_t base = (((size_t)(b << 4) + hh) * L_ + l) * DH_ + d;
                    if (part == 0) {
                        *reinterpret_cast<uint32_t*>(g_qh + base) =
                            packh(v0 * QSCALE_, v1 * QSCALE_);
                    } else if (part == 1) {
                        *reinterpret_cast<uint32_t*>(g_kh + base) = packh(v0, v1);
                    } else {
                        *reinterpret_cast<uint32_t*>(g_vh + base) = packh(v0, v1);
                    }
                } else {
                    float2* pd = reinterpret_cast<float2*>(outp + (size_t)m * C_ + o);
                    *pd = make_float2(v0 + bias[o], v1 + bias[o + 1]);
                }
            }
        }
    }
}

// ---------------------------------------------------------------------------
// Flash attention, fp16, base-2 softmax (S already in log2 domain via QSCALE_).
// S = Q K^T (1 MMA), PV (1 MMA), register P, warp-local softmax.
// smem: Q 16K | 3 stages x 16K (K|V) = 64 KB, 2 CTAs/SM.
// ---------------------------------------------------------------------------
static constexpr int ATT_KV   = 16384;
static constexpr int ATT_STG  = 16384;
static constexpr int ATT_SMEM = 65536;

__global__ __launch_bounds__(256, 2) void attn_mma() {
    extern __shared__ char smem[];
    const uint32_t sb = smem_u32(smem);
    const int tid = threadIdx.x, lane = tid & 31, w = tid >> 5;
    const int qt = blockIdx.x, h = blockIdx.y, b = blockIdx.z;
    const size_t bh = (size_t)(b * H_ + h) * L_;

    const int r0   = lane >> 2;
    const int cb   = (lane & 3) * 2;
    const int a_lr = lane & 15;
    const int a_cb = (lane >> 4) << 4;
    const int b_lr = ((lane >> 4) << 3) + (lane & 7);
    const int b_cb = ((lane >> 3) & 1) << 4;
    const int v_lr = (lane & 7) + (((lane >> 3) & 1) << 3);
    const int v_cB = ((lane >> 4) << 3) * 2;

    // ---- Q tile (128x64 fp16), once ----
    #pragma unroll
    for (int t = 0; t < 4; t++) {
        int idx = tid + t * 256;
        int r = idx >> 3, j = idx & 7;
        cp16(sb + SWZ(r * 128 + j * 16), g_qh + (bh + qt * 128 + r) * DH_ + j * 8);
    }
    asm volatile("cp.async.commit_group;" ::: "memory");

    auto prefetch = [&](int kt) {
        const uint32_t stg = sb + ATT_KV + (kt % 3) * ATT_STG;
        #pragma unroll
        for (int t = 0; t < 4; t++) {
            int idx = tid + t * 256;
            int p = idx >> 9, r = (idx >> 3) & 63, j = idx & 7;
            const __half* src = ((p == 0) ? g_kh : g_vh) + (bh + kt * 64 + r) * DH_ + j * 8;
            cp16(stg + p * 8192 + SWZ(r * 128 + j * 16), src);
        }
        asm volatile("cp.async.commit_group;" ::: "memory");
    };
    prefetch(0);
    prefetch(1);

    float c_o[8][4];
    #pragma unroll
    for (int nj = 0; nj < 8; nj++)
        #pragma unroll
        for (int e = 0; e < 4; e++) c_o[nj][e] = 0.f;
    float m2[2] = {-1e30f, -1e30f}, l2[2] = {0.f, 0.f};

    const int NKT = L_ / 64;
    for (int kt = 0; kt < NKT; kt++) {
        if (kt + 1 < NKT) {
            asm volatile("cp.async.wait_group 1;" ::: "memory");
        } else {
            asm volatile("cp.async.wait_group 0;" ::: "memory");
        }
        __syncthreads();
        if (kt + 2 < NKT) prefetch(kt + 2);

        const uint32_t stg = sb + ATT_KV + (kt % 3) * ATT_STG;
        const uint32_t kH = stg, vH = stg + 8192;

        // ---- S = Q K^T : warp 16x64 stripe (log2 domain) ----
        float c_s[8][4];
        #pragma unroll
        for (int nj = 0; nj < 8; nj++)
            #pragma unroll
            for (int e = 0; e < 4; e++) c_s[nj][e] = 0.f;

        #pragma unroll
        for (int ks = 0; ks < 4; ks++) {
            const int kb = ks * 32;
            uint32_t qa[4];
            ldmx4(qa, sb + SWZ((w * 16 + a_lr) * 128 + kb + a_cb));
            #pragma unroll
            for (int grp = 0; grp < 4; grp++) {
                uint32_t off = SWZ((grp * 16 + b_lr) * 128 + kb + b_cb);
                uint32_t r[4];
                ldmx4(r, kH + off);
                uint32_t f0[2] = {r[0], r[1]}, f1[2] = {r[2], r[3]};
                mma16816h(c_s[grp * 2],     qa, f0);
                mma16816h(c_s[grp * 2 + 1], qa, f1);
            }
        }

        // ---- warp-local online softmax (base 2) ----
        float alpha[2];
        #pragma unroll
        for (int rh = 0; rh < 2; rh++) {
            float mx = -1e30f;
            #pragma unroll
            for (int nj = 0; nj < 8; nj++)
                mx = fmaxf(mx, fmaxf(c_s[nj][rh * 2], c_s[nj][rh * 2 + 1]));
            mx = fmaxf(mx, __shfl_xor_sync(0xffffffffu, mx, 1));
            mx = fmaxf(mx, __shfl_xor_sync(0xffffffffu, mx, 2));
            float mnew = fmaxf(m2[rh], mx);
            alpha[rh] = exp2f(m2[rh] - mnew);
            m2[rh] = mnew;
        }

        uint32_t ph[4][4];
        float rs0 = 0.f, rs1 = 0.f;
        #pragma unroll
        for (int nj = 0; nj < 8; nj++) {
            uint32_t h01 = ex2h2(c_s[nj][0] - m2[0], c_s[nj][1] - m2[0]);
            uint32_t h23 = ex2h2(c_s[nj][2] - m2[1], c_s[nj][3] - m2[1]);
            ph[nj >> 1][(nj & 1) * 2 + 0] = h01;
            ph[nj >> 1][(nj & 1) * 2 + 1] = h23;
            float2 f01 = __half22float2(*reinterpret_cast<__half2*>(&h01));
            float2 f23 = __half22float2(*reinterpret_cast<__half2*>(&h23));
            rs0 += f01.x + f01.y;
            rs1 += f23.x + f23.y;
        }
        rs0 += __shfl_xor_sync(0xffffffffu, rs0, 1);
        rs0 += __shfl_xor_sync(0xffffffffu, rs0, 2);
        rs1 += __shfl_xor_sync(0xffffffffu, rs1, 1);
        rs1 += __shfl_xor_sync(0xffffffffu, rs1, 2);
        l2[0] = l2[0] * alpha[0] + rs0;
        l2[1] = l2[1] * alpha[1] + rs1;
        #pragma unroll
        for (int nj = 0; nj < 8; nj++) {
            c_o[nj][0] *= alpha[0];
            c_o[nj][1] *= alpha[0];
            c_o[nj][2] *= alpha[1];
            c_o[nj][3] *= alpha[1];
        }

        // ---- O += P V  (P fp16 register; V via ldmatrix.trans) ----
        #pragma unroll
        for (int ks = 0; ks < 4; ks++) {
            uint32_t vb[8][2];
            #pragma unroll
            for (int grp = 0; grp < 4; grp++) {
                uint32_t off = SWZ((ks * 16 + v_lr) * 128 + grp * 32 + v_cB);
                uint32_t r[4];
                ldmx4t(r, vH + off);
                vb[grp * 2][0] = r[0]; vb[grp * 2][1] = r[1];
                vb[grp * 2 + 1][0] = r[2]; vb[grp * 2 + 1][1] = r[3];
            }
            #pragma unroll
            for (int nj = 0; nj < 8; nj++)
                mma16816h(c_o[nj], ph[ks], vb[nj]);
        }
        __syncthreads();
    }

    // ---- epilogue: O/l -> fp16 att ----
    #pragma unroll
    for (int rh = 0; rh < 2; rh++) {
        int row = qt * 128 + w * 16 + r0 + rh * 8;
        float inv = 1.0f / l2[rh];
        size_t grow = ((size_t)b * L_ + row) * C_ + h * DH_;
        #pragma unroll
        for (int nj = 0; nj < 8; nj++) {
            float o0 = c_o[nj][rh * 2]     * inv;
            float o1 = c_o[nj][rh * 2 + 1] * inv;
            *reinterpret_cast<uint32_t*>(g_at16 + grow + nj * 8 + cb) = packh(o0, o1);
        }
    }
}

// ---------------------------------------------------------------------------
extern "C" void kernel_launch(void* const* d_in, const int* in_sizes, int n_in,
                              void* d_out, int out_size) {
    const float* x     = (const float*)d_in[0];
    const float* w_qkv = (const float*)d_in[1];
    const float* w_out = (const float*)d_in[2];
    const float* b_out = (const float*)d_in[3];
    float* out = (float*)d_out;

    cudaFuncSetAttribute(hmma_gemm<0>, cudaFuncAttributeMaxDynamicSharedMemorySize, GSMEM);
    cudaFuncSetAttribute(hmma_gemm<1>, cudaFuncAttributeMaxDynamicSharedMemorySize, GSMEM);
    cudaFuncSetAttribute(attn_mma, cudaFuncAttributeMaxDynamicSharedMemorySize, ATT_SMEM);

    conv_h<0><<<4096 * 1024 / 1024, 256>>>(x, 4096 * 1024);
    conv_h<1><<<3072 * 1024 / 1024, 256>>>(w_qkv, 3072 * 1024);
    conv_h<2><<<1024 * 1024 / 1024, 256>>>(w_out, 1024 * 1024);

    hmma_gemm<0><<<dim3(24, 32), 256, GSMEM>>>(nullptr, nullptr);

    attn_mma<<<dim3(L_ / 128, H_, B_), 256, ATT_SMEM>>>();

    hmma_gemm<1><<<dim3(8, 32), 256, GSMEM>>>(b_out, out);
}

// round 11
// speedup vs baseline: 10.5144x; 1.0445x over previous
#include <cuda_runtime.h>
#include <cuda_fp16.h>
#include <cstdint>

// ---------------------------------------------------------------------------
// MHA block. Round 11: single-sync chunk loops, 4-stage attention pipeline,
// fused fp32->fp16 conversion kernel.
// ---------------------------------------------------------------------------

#define B_   2
#define L_   2048
#define C_   1024
#define H_   16
#define DH_  64
#define QSCALE_ 0.045084439f   // 1024^-0.5 * log2(e)

// ---------------- scratch ----------------------------------------------------
__device__ __half g_x16[4096 * 1024];
__device__ __half g_wq16[3072 * 1024];
__device__ __half g_wo16[1024 * 1024];
__device__ __half g_at16[4096 * 1024];
__device__ __half g_qh[B_*H_*L_*DH_];
__device__ __half g_kh[B_*H_*L_*DH_];
__device__ __half g_vh[B_*H_*L_*DH_];

// ---------------- helpers ----------------------------------------------------
static __device__ __forceinline__ uint32_t smem_u32(const void* p) {
    uint32_t a;
    asm("{ .reg .u64 t; cvta.to.shared.u64 t, %1; cvt.u32.u64 %0, t; }"
        : "=r"(a) : "l"(p));
    return a;
}
#define SWZ(o)   ((o) ^ (((o) >> 3) & 0x70))   // 128B-row swizzle

static __device__ __forceinline__ void cp16(uint32_t saddr, const void* gaddr) {
    asm volatile("cp.async.cg.shared.global [%0], [%1], 16;"
                 :: "r"(saddr), "l"(gaddr) : "memory");
}
static __device__ __forceinline__ void ldmx4(uint32_t* r, uint32_t addr) {
    asm volatile("ldmatrix.sync.aligned.m8n8.x4.shared.b16 {%0,%1,%2,%3}, [%4];"
                 : "=r"(r[0]), "=r"(r[1]), "=r"(r[2]), "=r"(r[3]) : "r"(addr));
}
static __device__ __forceinline__ void ldmx4t(uint32_t* r, uint32_t addr) {
    asm volatile("ldmatrix.sync.aligned.m8n8.x4.trans.shared.b16 {%0,%1,%2,%3}, [%4];"
                 : "=r"(r[0]), "=r"(r[1]), "=r"(r[2]), "=r"(r[3]) : "r"(addr));
}
static __device__ __forceinline__ void mma16816h(float* c, const uint32_t* a,
                                                 const uint32_t* b) {
    asm volatile(
        "mma.sync.aligned.m16n8k16.row.col.f32.f16.f16.f32 "
        "{%0,%1,%2,%3}, {%4,%5,%6,%7}, {%8,%9}, {%0,%1,%2,%3};"
        : "+f"(c[0]), "+f"(c[1]), "+f"(c[2]), "+f"(c[3])
        : "r"(a[0]), "r"(a[1]), "r"(a[2]), "r"(a[3]), "r"(b[0]), "r"(b[1]));
}
static __device__ __forceinline__ uint32_t packh(float a, float b) {
    __half2 t = __floats2half2_rn(a, b);
    return *reinterpret_cast<uint32_t*>(&t);
}
static __device__ __forceinline__ uint32_t ex2h2(float a, float b) {
    uint32_t p = packh(a, b);
    uint32_t r;
    asm("ex2.approx.f16x2 %0, %1;" : "=r"(r) : "r"(p));
    return r;
}

// ---------------------------------------------------------------------------
// Fused fp32 -> fp16 convert: x (4M), w_qkv (3M), w_out (1M) in one launch.
// Index space is float4 units: x 1M | wq 768K | wo 256K = 2M total.
// ---------------------------------------------------------------------------
__global__ __launch_bounds__(256) void conv_all(const float* __restrict__ x,
                                                const float* __restrict__ wq,
                                                const float* __restrict__ wo) {
    int i = blockIdx.x * 256 + threadIdx.x;
    const float* src;
    __half* dst;
    int off;
    if (i < 1048576)       { src = x;  dst = g_x16;  off = i; }
    else if (i < 1835008)  { src = wq; dst = g_wq16; off = i - 1048576; }
    else                   { src = wo; dst = g_wo16; off = i - 1835008; }
    float4 v = reinterpret_cast<const float4*>(src)[off];
    uint2 o;
    o.x = packh(v.x, v.y);
    o.y = packh(v.z, v.w);
    *reinterpret_cast<uint2*>(dst + (size_t)off * 4) = o;
}

// ---------------------------------------------------------------------------
// fp16 HMMA GEMM: 128x128 tile, K-chunk 64 (SW128), 3-stage, 2 CTAs/SM,
// ONE sync per chunk.
// OUTK 0: QKV -> q(scaled by QSCALE_)/k/v fp16.  OUTK 1: out-proj fp32+bias.
// ---------------------------------------------------------------------------
static constexpr int GSMEM = 98304;   // 3 stages x 32KB (A 16K | B 16K)

template <int OUTK>
__global__ __launch_bounds__(256, 2) void hmma_gemm(const float* __restrict__ bias,
                                                    float* __restrict__ outp) {
    extern __shared__ char smem[];
    const uint32_t sb = smem_u32(smem);
    const int tid = threadIdx.x;
    const int lane = tid & 31, wid = tid >> 5;
    const int wm = wid & 1, wn = wid >> 1;

    const __half* A  = (OUTK == 0) ? g_x16  : g_at16;
    const __half* Bm = (OUTK == 0) ? g_wq16 : g_wo16;

    const int n0 = blockIdx.x * 128;
    const int m0 = blockIdx.y * 128;
    const int part = (OUTK == 0) ? (blockIdx.x >> 3) : 0;     // 0=Q 1=K 2=V

    float c[4][4][4];
    #pragma unroll
    for (int i = 0; i < 4; i++)
        #pragma unroll
        for (int j = 0; j < 4; j++)
            #pragma unroll
            for (int e = 0; e < 4; e++) c[i][j][e] = 0.f;

    auto prefetch = [&](int ch) {
        const int s = ch % 3;
        const int k0 = ch * 64;
        #pragma unroll
        for (int p = 0; p < 2; p++) {
            const __half* src = p ? Bm : A;
            const int base = p ? n0 : m0;
            #pragma unroll
            for (int t = 0; t < 4; t++) {
                int idx = tid + t * 256;
                int r = idx >> 3, j = idx & 7;
                uint32_t sa = sb + s * 32768 + p * 16384 + SWZ(r * 128 + j * 16);
                cp16(sa, src + (size_t)(base + r) * 1024 + k0 + j * 8);
            }
        }
        asm volatile("cp.async.commit_group;" ::: "memory");
    };

    prefetch(0);
    prefetch(1);

    const int a_row = wm * 64 + (lane & 15);
    const int a_cb  = (lane >> 4) << 4;
    const int b_row = wn * 32 + ((lane >> 4) << 3) + (lane & 7);
    const int b_cb  = ((lane >> 3) & 1) << 4;

    for (int ch = 0; ch < 16; ch++) {
        if (ch + 1 < 16) {
            asm volatile("cp.async.wait_group 1;" ::: "memory");
        } else {
            asm volatile("cp.async.wait_group 0;" ::: "memory");
        }
        __syncthreads();     // single barrier: also fences previous-stage readers
        if (ch + 2 < 16) prefetch(ch + 2);

        const uint32_t stg = sb + (ch % 3) * 32768;
        const uint32_t aS = stg, bS = stg + 16384;

        #pragma unroll
        for (int ks = 0; ks < 4; ks++) {
            const int kb = ks * 32;
            uint32_t af[4][4];
            #pragma unroll
            for (int mi = 0; mi < 4; mi++)
                ldmx4(af[mi], aS + SWZ((a_row + mi * 16) * 128 + kb + a_cb));
            uint32_t bf[4][2];
            #pragma unroll
            for (int nj = 0; nj < 2; nj++) {
                uint32_t r[4];
                ldmx4(r, bS + SWZ((b_row + nj * 16) * 128 + kb + b_cb));
                bf[nj * 2][0] = r[0]; bf[nj * 2][1] = r[1];
                bf[nj * 2 + 1][0] = r[2]; bf[nj * 2 + 1][1] = r[3];
            }
            #pragma unroll
            for (int mi = 0; mi < 4; mi++)
                #pragma unroll
                for (int nj = 0; nj < 4; nj++)
                    mma16816h(c[mi][nj], af[mi], bf[nj]);
        }
    }

    const int row_in = lane >> 2;
    const int col_in = (lane & 3) * 2;
    #pragma unroll
    for (int mi = 0; mi < 4; mi++) {
        #pragma unroll
        for (int nj = 0; nj < 4; nj++) {
            int o = n0 + wn * 32 + nj * 8 + col_in;
            #pragma unroll
            for (int half = 0; half < 2; half++) {
                int m = m0 + wm * 64 + mi * 16 + row_in + half * 8;
                float v0 = c[mi][nj][half * 2 + 0];
                float v1 = c[mi][nj][half * 2 + 1];
                if (OUTK == 0) {
                    int b = m >> 11, l = m & (L_ - 1);
                    int cc = o & (C_ - 1);
                    int hh = cc >> 6, d = cc & 63;
                    size_t base = (((size_t)(b << 4) + hh) * L_ + l) * DH_ + d;
                    if (part == 0) {
                        *reinterpret_cast<uint32_t*>(g_qh + base) =
                            packh(v0 * QSCALE_, v1 * QSCALE_);
                    } else if (part == 1) {
                        *reinterpret_cast<uint32_t*>(g_kh + base) = packh(v0, v1);
                    } else {
                        *reinterpret_cast<uint32_t*>(g_vh + base) = packh(v0, v1);
                    }
                } else {
                    float2* pd = reinterpret_cast<float2*>(outp + (size_t)m * C_ + o);
                    *pd = make_float2(v0 + bias[o], v1 + bias[o + 1]);
                }
            }
        }
    }
}

// ---------------------------------------------------------------------------
// Flash attention, fp16, base-2 softmax. S (1 MMA), PV (1 MMA), register P,
// warp-local softmax. 4-stage KV pipeline, ONE sync per chunk.
// smem: Q 16K | 4 stages x 16K (K|V) = 80 KB, 2 CTAs/SM.
// ---------------------------------------------------------------------------
static constexpr int ATT_KV   = 16384;
static constexpr int ATT_STG  = 16384;
static constexpr int ATT_SMEM = 81920;

__global__ __launch_bounds__(256, 2) void attn_mma() {
    extern __shared__ char smem[];
    const uint32_t sb = smem_u32(smem);
    const int tid = threadIdx.x, lane = tid & 31, w = tid >> 5;
    const int qt = blockIdx.x, h = blockIdx.y, b = blockIdx.z;
    const size_t bh = (size_t)(b * H_ + h) * L_;

    const int r0   = lane >> 2;
    const int cb   = (lane & 3) * 2;
    const int a_lr = lane & 15;
    const int a_cb = (lane >> 4) << 4;
    const int b_lr = ((lane >> 4) << 3) + (lane & 7);
    const int b_cb = ((lane >> 3) & 1) << 4;
    const int v_lr = (lane & 7) + (((lane >> 3) & 1) << 3);
    const int v_cB = ((lane >> 4) << 3) * 2;

    // ---- Q tile (128x64 fp16), once ----
    #pragma unroll
    for (int t = 0; t < 4; t++) {
        int idx = tid + t * 256;
        int r = idx >> 3, j = idx & 7;
        cp16(sb + SWZ(r * 128 + j * 16), g_qh + (bh + qt * 128 + r) * DH_ + j * 8);
    }
    asm volatile("cp.async.commit_group;" ::: "memory");

    auto prefetch = [&](int kt) {
        const uint32_t stg = sb + ATT_KV + (kt & 3) * ATT_STG;
        #pragma unroll
        for (int t = 0; t < 4; t++) {
            int idx = tid + t * 256;
            int p = idx >> 9, r = (idx >> 3) & 63, j = idx & 7;
            const __half* src = ((p == 0) ? g_kh : g_vh) + (bh + kt * 64 + r) * DH_ + j * 8;
            cp16(stg + p * 8192 + SWZ(r * 128 + j * 16), src);
        }
        asm volatile("cp.async.commit_group;" ::: "memory");
    };
    prefetch(0);
    prefetch(1);
    prefetch(2);

    float c_o[8][4];
    #pragma unroll
    for (int nj = 0; nj < 8; nj++)
        #pragma unroll
        for (int e = 0; e < 4; e++) c_o[nj][e] = 0.f;
    float m2[2] = {-1e30f, -1e30f}, l2[2] = {0.f, 0.f};

    const int NKT = L_ / 64;
    for (int kt = 0; kt < NKT; kt++) {
        int inflight = (NKT - 1 - kt < 2) ? (NKT - 1 - kt) : 2;
        if (inflight == 2) {
            asm volatile("cp.async.wait_group 2;" ::: "memory");
        } else if (inflight == 1) {
            asm volatile("cp.async.wait_group 1;" ::: "memory");
        } else {
            asm volatile("cp.async.wait_group 0;" ::: "memory");
        }
        __syncthreads();
        if (kt + 3 < NKT) prefetch(kt + 3);

        const uint32_t stg = sb + ATT_KV + (kt & 3) * ATT_STG;
        const uint32_t kH = stg, vH = stg + 8192;

        // ---- S = Q K^T : warp 16x64 stripe (log2 domain) ----
        float c_s[8][4];
        #pragma unroll
        for (int nj = 0; nj < 8; nj++)
            #pragma unroll
            for (int e = 0; e < 4; e++) c_s[nj][e] = 0.f;

        #pragma unroll
        for (int ks = 0; ks < 4; ks++) {
            const int kb = ks * 32;
            uint32_t qa[4];
            ldmx4(qa, sb + SWZ((w * 16 + a_lr) * 128 + kb + a_cb));
            #pragma unroll
            for (int grp = 0; grp < 4; grp++) {
                uint32_t off = SWZ((grp * 16 + b_lr) * 128 + kb + b_cb);
                uint32_t r[4];
                ldmx4(r, kH + off);
                uint32_t f0[2] = {r[0], r[1]}, f1[2] = {r[2], r[3]};
                mma16816h(c_s[grp * 2],     qa, f0);
                mma16816h(c_s[grp * 2 + 1], qa, f1);
            }
        }

        // ---- warp-local online softmax (base 2) ----
        float alpha[2];
        #pragma unroll
        for (int rh = 0; rh < 2; rh++) {
            float mx = -1e30f;
            #pragma unroll
            for (int nj = 0; nj < 8; nj++)
                mx = fmaxf(mx, fmaxf(c_s[nj][rh * 2], c_s[nj][rh * 2 + 1]));
            mx = fmaxf(mx, __shfl_xor_sync(0xffffffffu, mx, 1));
            mx = fmaxf(mx, __shfl_xor_sync(0xffffffffu, mx, 2));
            float mnew = fmaxf(m2[rh], mx);
            alpha[rh] = exp2f(m2[rh] - mnew);
            m2[rh] = mnew;
        }

        uint32_t ph[4][4];
        float rs0 = 0.f, rs1 = 0.f;
        #pragma unroll
        for (int nj = 0; nj < 8; nj++) {
            uint32_t h01 = ex2h2(c_s[nj][0] - m2[0], c_s[nj][1] - m2[0]);
            uint32_t h23 = ex2h2(c_s[nj][2] - m2[1], c_s[nj][3] - m2[1]);
            ph[nj >> 1][(nj & 1) * 2 + 0] = h01;
            ph[nj >> 1][(nj & 1) * 2 + 1] = h23;
            float2 f01 = __half22float2(*reinterpret_cast<__half2*>(&h01));
            float2 f23 = __half22float2(*reinterpret_cast<__half2*>(&h23));
            rs0 += f01.x + f01.y;
            rs1 += f23.x + f23.y;
        }
        rs0 += __shfl_xor_sync(0xffffffffu, rs0, 1);
        rs0 += __shfl_xor_sync(0xffffffffu, rs0, 2);
        rs1 += __shfl_xor_sync(0xffffffffu, rs1, 1);
        rs1 += __shfl_xor_sync(0xffffffffu, rs1, 2);
        l2[0] = l2[0] * alpha[0] + rs0;
        l2[1] = l2[1] * alpha[1] + rs1;
        #pragma unroll
        for (int nj = 0; nj < 8; nj++) {
            c_o[nj][0] *= alpha[0];
            c_o[nj][1] *= alpha[0];
            c_o[nj][2] *= alpha[1];
            c_o[nj][3] *= alpha[1];
        }

        // ---- O += P V ----
        #pragma unroll
        for (int ks = 0; ks < 4; ks++) {
            uint32_t vb[8][2];
            #pragma unroll
            for (int grp = 0; grp < 4; grp++) {
                uint32_t off = SWZ((ks * 16 + v_lr) * 128 + grp * 32 + v_cB);
                uint32_t r[4];
                ldmx4t(r, vH + off);
                vb[grp * 2][0] = r[0]; vb[grp * 2][1] = r[1];
                vb[grp * 2 + 1][0] = r[2]; vb[grp * 2 + 1][1] = r[3];
            }
            #pragma unroll
            for (int nj = 0; nj < 8; nj++)
                mma16816h(c_o[nj], ph[ks], vb[nj]);
        }
    }

    // ---- epilogue: O/l -> fp16 att ----
    #pragma unroll
    for (int rh = 0; rh < 2; rh++) {
        int row = qt * 128 + w * 16 + r0 + rh * 8;
        float inv = 1.0f / l2[rh];
        size_t grow = ((size_t)b * L_ + row) * C_ + h * DH_;
        #pragma unroll
        for (int nj = 0; nj < 8; nj++) {
            float o0 = c_o[nj][rh * 2]     * inv;
            float o1 = c_o[nj][rh * 2 + 1] * inv;
            *reinterpret_cast<uint32_t*>(g_at16 + grow + nj * 8 + cb) = packh(o0, o1);
        }
    }
}

// ---------------------------------------------------------------------------
extern "C" void kernel_launch(void* const* d_in, const int* in_sizes, int n_in,
                              void* d_out, int out_size) {
    const float* x     = (const float*)d_in[0];
    const float* w_qkv = (const float*)d_in[1];
    const float* w_out = (const float*)d_in[2];
    const float* b_out = (const float*)d_in[3];
    float* out = (float*)d_out;

    cudaFuncSetAttribute(hmma_gemm<0>, cudaFuncAttributeMaxDynamicSharedMemorySize, GSMEM);
    cudaFuncSetAttribute(hmma_gemm<1>, cudaFuncAttributeMaxDynamicSharedMemorySize, GSMEM);
    cudaFuncSetAttribute(attn_mma, cudaFuncAttributeMaxDynamicSharedMemorySize, ATT_SMEM);

    // fused conversions: 2M float4 units
    conv_all<<<2097152 / 256, 256>>>(x, w_qkv, w_out);

    hmma_gemm<0><<<dim3(24, 32), 256, GSMEM>>>(nullptr, nullptr);

    attn_mma<<<dim3(L_ / 128, H_, B_), 256, ATT_SMEM>>>();

    hmma_gemm<1><<<dim3(8, 32), 256, GSMEM>>>(b_out, out);
}

// round 12
// speedup vs baseline: 10.6293x; 1.0109x over previous
#include <cuda_runtime.h>
#include <cuda_fp16.h>
#include <cstdint>

// ---------------------------------------------------------------------------
// MHA block. Round 12: attention warp M-tile 32 (K/V ldmatrix reuse x2,
// 4-warp CTAs); proj GEMM 64x128 tiles for wave balance.
// ---------------------------------------------------------------------------

#define B_   2
#define L_   2048
#define C_   1024
#define H_   16
#define DH_  64
#define QSCALE_ 0.045084439f   // 1024^-0.5 * log2(e)

// ---------------- scratch ----------------------------------------------------
__device__ __half g_x16[4096 * 1024];
__device__ __half g_wq16[3072 * 1024];
__device__ __half g_wo16[1024 * 1024];
__device__ __half g_at16[4096 * 1024];
__device__ __half g_qh[B_*H_*L_*DH_];
__device__ __half g_kh[B_*H_*L_*DH_];
__device__ __half g_vh[B_*H_*L_*DH_];

// ---------------- helpers ----------------------------------------------------
static __device__ __forceinline__ uint32_t smem_u32(const void* p) {
    uint32_t a;
    asm("{ .reg .u64 t; cvta.to.shared.u64 t, %1; cvt.u32.u64 %0, t; }"
        : "=r"(a) : "l"(p));
    return a;
}
#define SWZ(o)   ((o) ^ (((o) >> 3) & 0x70))   // 128B-row swizzle

static __device__ __forceinline__ void cp16(uint32_t saddr, const void* gaddr) {
    asm volatile("cp.async.cg.shared.global [%0], [%1], 16;"
                 :: "r"(saddr), "l"(gaddr) : "memory");
}
static __device__ __forceinline__ void ldmx4(uint32_t* r, uint32_t addr) {
    asm volatile("ldmatrix.sync.aligned.m8n8.x4.shared.b16 {%0,%1,%2,%3}, [%4];"
                 : "=r"(r[0]), "=r"(r[1]), "=r"(r[2]), "=r"(r[3]) : "r"(addr));
}
static __device__ __forceinline__ void ldmx4t(uint32_t* r, uint32_t addr) {
    asm volatile("ldmatrix.sync.aligned.m8n8.x4.trans.shared.b16 {%0,%1,%2,%3}, [%4];"
                 : "=r"(r[0]), "=r"(r[1]), "=r"(r[2]), "=r"(r[3]) : "r"(addr));
}
static __device__ __forceinline__ void mma16816h(float* c, const uint32_t* a,
                                                 const uint32_t* b) {
    asm volatile(
        "mma.sync.aligned.m16n8k16.row.col.f32.f16.f16.f32 "
        "{%0,%1,%2,%3}, {%4,%5,%6,%7}, {%8,%9}, {%0,%1,%2,%3};"
        : "+f"(c[0]), "+f"(c[1]), "+f"(c[2]), "+f"(c[3])
        : "r"(a[0]), "r"(a[1]), "r"(a[2]), "r"(a[3]), "r"(b[0]), "r"(b[1]));
}
static __device__ __forceinline__ uint32_t packh(float a, float b) {
    __half2 t = __floats2half2_rn(a, b);
    return *reinterpret_cast<uint32_t*>(&t);
}
static __device__ __forceinline__ uint32_t ex2h2(float a, float b) {
    uint32_t p = packh(a, b);
    uint32_t r;
    asm("ex2.approx.f16x2 %0, %1;" : "=r"(r) : "r"(p));
    return r;
}

// ---------------------------------------------------------------------------
// Fused fp32 -> fp16 convert: x | w_qkv | w_out, one launch (float4 units).
// ---------------------------------------------------------------------------
__global__ __launch_bounds__(256) void conv_all(const float* __restrict__ x,
                                                const float* __restrict__ wq,
                                                const float* __restrict__ wo) {
    int i = blockIdx.x * 256 + threadIdx.x;
    const float* src;
    __half* dst;
    int off;
    if (i < 1048576)       { src = x;  dst = g_x16;  off = i; }
    else if (i < 1835008)  { src = wq; dst = g_wq16; off = i - 1048576; }
    else                   { src = wo; dst = g_wo16; off = i - 1835008; }
    float4 v = reinterpret_cast<const float4*>(src)[off];
    uint2 o;
    o.x = packh(v.x, v.y);
    o.y = packh(v.z, v.w);
    *reinterpret_cast<uint2*>(dst + (size_t)off * 4) = o;
}

// ---------------------------------------------------------------------------
// fp16 HMMA GEMM. OUTK 0: 128x128 tile (QKV). OUTK 1: 64x128 tile (proj).
// K-chunk 64 (SW128), 3-stage, 2 CTAs/SM, one sync per chunk.
// ---------------------------------------------------------------------------
template <int OUTK>
__global__ __launch_bounds__(256, 2) void hmma_gemm(const float* __restrict__ bias,
                                                    float* __restrict__ outp) {
    constexpr int MT = (OUTK == 0) ? 128 : 64;      // M tile
    constexpr int MI = MT / 32;                     // m frags per warp (4 or 2)
    constexpr int ASTG = MT * 128;                  // A stage bytes
    constexpr int STG = ASTG + 16384;               // stage bytes

    extern __shared__ char smem[];
    const uint32_t sb = smem_u32(smem);
    const int tid = threadIdx.x;
    const int lane = tid & 31, wid = tid >> 5;
    const int wm = wid & 1, wn = wid >> 1;

    const __half* A  = (OUTK == 0) ? g_x16  : g_at16;
    const __half* Bm = (OUTK == 0) ? g_wq16 : g_wo16;

    const int n0 = blockIdx.x * 128;
    const int m0 = blockIdx.y * MT;
    const int part = (OUTK == 0) ? (blockIdx.x >> 3) : 0;     // 0=Q 1=K 2=V

    float c[MI][4][4];
    #pragma unroll
    for (int i = 0; i < MI; i++)
        #pragma unroll
        for (int j = 0; j < 4; j++)
            #pragma unroll
            for (int e = 0; e < 4; e++) c[i][j][e] = 0.f;

    auto prefetch = [&](int ch) {
        const int s = ch % 3;
        const int k0 = ch * 64;
        // A tile: MT rows x 64 cols -> MT*8 float4
        #pragma unroll
        for (int t = 0; t < MT / 32; t++) {
            int idx = tid + t * 256;
            int r = idx >> 3, j = idx & 7;
            cp16(sb + s * STG + SWZ(r * 128 + j * 16),
                 A + (size_t)(m0 + r) * 1024 + k0 + j * 8);
        }
        // B tile: 128 rows x 64 cols -> 1024 float4
        #pragma unroll
        for (int t = 0; t < 4; t++) {
            int idx = tid + t * 256;
            int r = idx >> 3, j = idx & 7;
            cp16(sb + s * STG + ASTG + SWZ(r * 128 + j * 16),
                 Bm + (size_t)(n0 + r) * 1024 + k0 + j * 8);
        }
        asm volatile("cp.async.commit_group;" ::: "memory");
    };

    prefetch(0);
    prefetch(1);

    const int a_row = wm * (MI * 16) + (lane & 15);
    const int a_cb  = (lane >> 4) << 4;
    const int b_row = wn * 32 + ((lane >> 4) << 3) + (lane & 7);
    const int b_cb  = ((lane >> 3) & 1) << 4;

    for (int ch = 0; ch < 16; ch++) {
        if (ch + 1 < 16) {
            asm volatile("cp.async.wait_group 1;" ::: "memory");
        } else {
            asm volatile("cp.async.wait_group 0;" ::: "memory");
        }
        __syncthreads();
        if (ch + 2 < 16) prefetch(ch + 2);

        const uint32_t aS = sb + (ch % 3) * STG;
        const uint32_t bS = aS + ASTG;

        #pragma unroll
        for (int ks = 0; ks < 4; ks++) {
            const int kb = ks * 32;
            uint32_t af[MI][4];
            #pragma unroll
            for (int mi = 0; mi < MI; mi++)
                ldmx4(af[mi], aS + SWZ((a_row + mi * 16) * 128 + kb + a_cb));
            uint32_t bf[4][2];
            #pragma unroll
            for (int nj = 0; nj < 2; nj++) {
                uint32_t r[4];
                ldmx4(r, bS + SWZ((b_row + nj * 16) * 128 + kb + b_cb));
                bf[nj * 2][0] = r[0]; bf[nj * 2][1] = r[1];
                bf[nj * 2 + 1][0] = r[2]; bf[nj * 2 + 1][1] = r[3];
            }
            #pragma unroll
            for (int mi = 0; mi < MI; mi++)
                #pragma unroll
                for (int nj = 0; nj < 4; nj++)
                    mma16816h(c[mi][nj], af[mi], bf[nj]);
        }
    }

    const int row_in = lane >> 2;
    const int col_in = (lane & 3) * 2;
    #pragma unroll
    for (int mi = 0; mi < MI; mi++) {
        #pragma unroll
        for (int nj = 0; nj < 4; nj++) {
            int o = n0 + wn * 32 + nj * 8 + col_in;
            #pragma unroll
            for (int half = 0; half < 2; half++) {
                int m = m0 + wm * (MI * 16) + mi * 16 + row_in + half * 8;
                float v0 = c[mi][nj][half * 2 + 0];
                float v1 = c[mi][nj][half * 2 + 1];
                if (OUTK == 0) {
                    int b = m >> 11, l = m & (L_ - 1);
                    int cc = o & (C_ - 1);
                    int hh = cc >> 6, d = cc & 63;
                    size_t base = (((size_t)(b << 4) + hh) * L_ + l) * DH_ + d;
                    if (part == 0) {
                        *reinterpret_cast<uint32_t*>(g_qh + base) =
                            packh(v0 * QSCALE_, v1 * QSCALE_);
                    } else if (part == 1) {
                        *reinterpret_cast<uint32_t*>(g_kh + base) = packh(v0, v1);
                    } else {
                        *reinterpret_cast<uint32_t*>(g_vh + base) = packh(v0, v1);
                    }
                } else {
                    float2* pd = reinterpret_cast<float2*>(outp + (size_t)m * C_ + o);
                    *pd = make_float2(v0 + bias[o], v1 + bias[o + 1]);
                }
            }
        }
    }
}

static constexpr int GSMEM0 = 3 * (128 * 128 + 16384);   // 98304
static constexpr int GSMEM1 = 3 * (64 * 128 + 16384);    // 73728

// ---------------------------------------------------------------------------
// Flash attention: 4 warps x 32 q-rows (K/V fragment reuse x2), fp16,
// base-2 softmax, 4-stage KV pipeline, one sync per chunk.
// smem: Q 16K | 4 stages x 16K (K|V) = 80 KB, 2 CTAs/SM (128 threads).
// ---------------------------------------------------------------------------
static constexpr int ATT_KV   = 16384;
static constexpr int ATT_STG  = 16384;
static constexpr int ATT_SMEM = 81920;

__global__ __launch_bounds__(128, 2) void attn_mma() {
    extern __shared__ char smem[];
    const uint32_t sb = smem_u32(smem);
    const int tid = threadIdx.x, lane = tid & 31, w = tid >> 5;   // w: 0..3
    const int qt = blockIdx.x, h = blockIdx.y, b = blockIdx.z;
    const size_t bh = (size_t)(b * H_ + h) * L_;

    const int r0   = lane >> 2;
    const int cb   = (lane & 3) * 2;
    const int a_lr = lane & 15;
    const int a_cb = (lane >> 4) << 4;
    const int b_lr = ((lane >> 4) << 3) + (lane & 7);
    const int b_cb = ((lane >> 3) & 1) << 4;
    const int v_lr = (lane & 7) + (((lane >> 3) & 1) << 3);
    const int v_cB = ((lane >> 4) << 3) * 2;

    // ---- Q tile (128x64 fp16), once: 1024 float4 / 128 threads ----
    #pragma unroll
    for (int t = 0; t < 8; t++) {
        int idx = tid + t * 128;
        int r = idx >> 3, j = idx & 7;
        cp16(sb + SWZ(r * 128 + j * 16), g_qh + (bh + qt * 128 + r) * DH_ + j * 8);
    }
    asm volatile("cp.async.commit_group;" ::: "memory");

    auto prefetch = [&](int kt) {
        const uint32_t stg = sb + ATT_KV + (kt & 3) * ATT_STG;
        #pragma unroll
        for (int t = 0; t < 8; t++) {
            int idx = tid + t * 128;
            int p = idx >> 9, r = (idx >> 3) & 63, j = idx & 7;
            const __half* src = ((p == 0) ? g_kh : g_vh) + (bh + kt * 64 + r) * DH_ + j * 8;
            cp16(stg + p * 8192 + SWZ(r * 128 + j * 16), src);
        }
        asm volatile("cp.async.commit_group;" ::: "memory");
    };
    prefetch(0);
    prefetch(1);
    prefetch(2);

    float c_o[2][8][4];
    #pragma unroll
    for (int mi = 0; mi < 2; mi++)
        #pragma unroll
        for (int nj = 0; nj < 8; nj++)
            #pragma unroll
            for (int e = 0; e < 4; e++) c_o[mi][nj][e] = 0.f;
    float m2[2][2] = {{-1e30f, -1e30f}, {-1e30f, -1e30f}};
    float l2[2][2] = {{0.f, 0.f}, {0.f, 0.f}};

    const int NKT = L_ / 64;
    for (int kt = 0; kt < NKT; kt++) {
        int inflight = (NKT - 1 - kt < 2) ? (NKT - 1 - kt) : 2;
        if (inflight == 2) {
            asm volatile("cp.async.wait_group 2;" ::: "memory");
        } else if (inflight == 1) {
            asm volatile("cp.async.wait_group 1;" ::: "memory");
        } else {
            asm volatile("cp.async.wait_group 0;" ::: "memory");
        }
        __syncthreads();
        if (kt + 3 < NKT) prefetch(kt + 3);

        const uint32_t stg = sb + ATT_KV + (kt & 3) * ATT_STG;
        const uint32_t kH = stg, vH = stg + 8192;

        // ---- S = Q K^T : warp 32x64 stripe, K frags shared across mi ----
        float c_s[2][8][4];
        #pragma unroll
        for (int mi = 0; mi < 2; mi++)
            #pragma unroll
            for (int nj = 0; nj < 8; nj++)
                #pragma unroll
                for (int e = 0; e < 4; e++) c_s[mi][nj][e] = 0.f;

        #pragma unroll
        for (int ks = 0; ks < 4; ks++) {
            const int kb = ks * 32;
            uint32_t qa[2][4];
            #pragma unroll
            for (int mi = 0; mi < 2; mi++)
                ldmx4(qa[mi], sb + SWZ((w * 32 + mi * 16 + a_lr) * 128 + kb + a_cb));
            #pragma unroll
            for (int grp = 0; grp < 4; grp++) {
                uint32_t off = SWZ((grp * 16 + b_lr) * 128 + kb + b_cb);
                uint32_t r[4];
                ldmx4(r, kH + off);
                uint32_t f0[2] = {r[0], r[1]}, f1[2] = {r[2], r[3]};
                #pragma unroll
                for (int mi = 0; mi < 2; mi++) {
                    mma16816h(c_s[mi][grp * 2],     qa[mi], f0);
                    mma16816h(c_s[mi][grp * 2 + 1], qa[mi], f1);
                }
            }
        }

        // ---- warp-local online softmax (base 2), per mi ----
        uint32_t ph[2][4][4];
        #pragma unroll
        for (int mi = 0; mi < 2; mi++) {
            float alpha[2];
            #pragma unroll
            for (int rh = 0; rh < 2; rh++) {
                float mx = -1e30f;
                #pragma unroll
                for (int nj = 0; nj < 8; nj++)
                    mx = fmaxf(mx, fmaxf(c_s[mi][nj][rh * 2], c_s[mi][nj][rh * 2 + 1]));
                mx = fmaxf(mx, __shfl_xor_sync(0xffffffffu, mx, 1));
                mx = fmaxf(mx, __shfl_xor_sync(0xffffffffu, mx, 2));
                float mnew = fmaxf(m2[mi][rh], mx);
                alpha[rh] = exp2f(m2[mi][rh] - mnew);
                m2[mi][rh] = mnew;
            }
            float rs0 = 0.f, rs1 = 0.f;
            #pragma unroll
            for (int nj = 0; nj < 8; nj++) {
                uint32_t h01 = ex2h2(c_s[mi][nj][0] - m2[mi][0], c_s[mi][nj][1] - m2[mi][0]);
                uint32_t h23 = ex2h2(c_s[mi][nj][2] - m2[mi][1], c_s[mi][nj][3] - m2[mi][1]);
                ph[mi][nj >> 1][(nj & 1) * 2 + 0] = h01;
                ph[mi][nj >> 1][(nj & 1) * 2 + 1] = h23;
                float2 f01 = __half22float2(*reinterpret_cast<__half2*>(&h01));
                float2 f23 = __half22float2(*reinterpret_cast<__half2*>(&h23));
                rs0 += f01.x + f01.y;
                rs1 += f23.x + f23.y;
            }
            rs0 += __shfl_xor_sync(0xffffffffu, rs0, 1);
            rs0 += __shfl_xor_sync(0xffffffffu, rs0, 2);
            rs1 += __shfl_xor_sync(0xffffffffu, rs1, 1);
            rs1 += __shfl_xor_sync(0xffffffffu, rs1, 2);
            l2[mi][0] = l2[mi][0] * alpha[0] + rs0;
            l2[mi][1] = l2[mi][1] * alpha[1] + rs1;
            #pragma unroll
            for (int nj = 0; nj < 8; nj++) {
                c_o[mi][nj][0] *= alpha[0];
                c_o[mi][nj][1] *= alpha[0];
                c_o[mi][nj][2] *= alpha[1];
                c_o[mi][nj][3] *= alpha[1];
            }
        }

        // ---- O += P V : V frags shared across mi ----
        #pragma unroll
        for (int ks = 0; ks < 4; ks++) {
            uint32_t vb[8][2];
            #pragma unroll
            for (int grp = 0; grp < 4; grp++) {
                uint32_t off = SWZ((ks * 16 + v_lr) * 128 + grp * 32 + v_cB);
                uint32_t r[4];
                ldmx4t(r, vH + off);
                vb[grp * 2][0] = r[0]; vb[grp * 2][1] = r[1];
                vb[grp * 2 + 1][0] = r[2]; vb[grp * 2 + 1][1] = r[3];
            }
            #pragma unroll
            for (int mi = 0; mi < 2; mi++)
                #pragma unroll
                for (int nj = 0; nj < 8; nj++)
                    mma16816h(c_o[mi][nj], ph[mi][ks], vb[nj]);
        }
    }

    // ---- epilogue: O/l -> fp16 att ----
    #pragma unroll
    for (int mi = 0; mi < 2; mi++)
        #pragma unroll
        for (int rh = 0; rh < 2; rh++) {
            int row = qt * 128 + w * 32 + mi * 16 + r0 + rh * 8;
            float inv = 1.0f / l2[mi][rh];
            size_t grow = ((size_t)b * L_ + row) * C_ + h * DH_;
            #pragma unroll
            for (int nj = 0; nj < 8; nj++) {
                float o0 = c_o[mi][nj][rh * 2]     * inv;
                float o1 = c_o[mi][nj][rh * 2 + 1] * inv;
                *reinterpret_cast<uint32_t*>(g_at16 + grow + nj * 8 + cb) = packh(o0, o1);
            }
        }
}

// ---------------------------------------------------------------------------
extern "C" void kernel_launch(void* const* d_in, const int* in_sizes, int n_in,
                              void* d_out, int out_size) {
    const float* x     = (const float*)d_in[0];
    const float* w_qkv = (const float*)d_in[1];
    const float* w_out = (const float*)d_in[2];
    const float* b_out = (const float*)d_in[3];
    float* out = (float*)d_out;

    cudaFuncSetAttribute(hmma_gemm<0>, cudaFuncAttributeMaxDynamicSharedMemorySize, GSMEM0);
    cudaFuncSetAttribute(hmma_gemm<1>, cudaFuncAttributeMaxDynamicSharedMemorySize, GSMEM1);
    cudaFuncSetAttribute(attn_mma, cudaFuncAttributeMaxDynamicSharedMemorySize, ATT_SMEM);

    conv_all<<<2097152 / 256, 256>>>(x, w_qkv, w_out);

    // QKV: 24 n-tiles x 32 m-tiles (128x128)
    hmma_gemm<0><<<dim3(24, 32), 256, GSMEM0>>>(nullptr, nullptr);

    // attention: 128-row q-tiles, 128 threads
    attn_mma<<<dim3(L_ / 128, H_, B_), 128, ATT_SMEM>>>();

    // proj: 8 n-tiles x 64 m-tiles (64x128)
    hmma_gemm<1><<<dim3(8, 64), 256, GSMEM1>>>(b_out, out);
}